// round 1
// baseline (speedup 1.0000x reference)
#include <cuda_runtime.h>
#include <math.h>

#define CH    64
#define DDIM  48
#define WDIM  128
#define HDIM  128
#define S_TOT (DDIM*WDIM*HDIM)   /* 786432 spatial positions */
#define SLAB  (WDIM*HDIM)        /* 16384 per (c,d) slab     */
#define NSLAB (CH*DDIM)          /* 3072 attention problems  */

#define QSCALE 0.594603557501360533f   /* 8^(-1/4) */

/* Scratch (device globals are the sanctioned scratch mechanism) */
__device__ float g_q[CH * S_TOT];
__device__ float g_k[CH * S_TOT];
__device__ float g_v[CH * S_TOT];
__device__ float g_o[CH * S_TOT];

/* ------------------------------------------------------------------ */
/* Phase 1: fused QKV projection.                                      */
/* out_p[c][s] = (sum_k w_p[c][k] * x[k][s] + b_p[c]) * (p==q ? QSCALE : 1) */
/* Block: 128 spatial positions, 256 threads. Thread tile: 4c x 8s.    */
/* ------------------------------------------------------------------ */
#define P1_SMEM ((3*64*65 + 3*64 + 64*128) * 4)

__global__ void __launch_bounds__(256) qkv_kernel(
    const float* __restrict__ x,
    const float* __restrict__ wq, const float* __restrict__ bq,
    const float* __restrict__ wk, const float* __restrict__ bk,
    const float* __restrict__ wv, const float* __restrict__ bv)
{
    extern __shared__ float sm[];
    float* ws = sm;               /* [3][64][65] padded */
    float* bs = ws + 3*64*65;     /* [3][64]            */
    float* xs = bs + 3*64;        /* [64][128]          */

    const int t  = threadIdx.x;
    const int s0 = blockIdx.x * 128;

    for (int i = t; i < 64*64; i += 256) {
        int r = i >> 6, c = i & 63;
        ws[(0*64 + r)*65 + c] = wq[i];
        ws[(1*64 + r)*65 + c] = wk[i];
        ws[(2*64 + r)*65 + c] = wv[i];
    }
    if (t < 64) { bs[t] = bq[t]; bs[64 + t] = bk[t]; bs[128 + t] = bv[t]; }
    for (int i = t; i < 64*32; i += 256) {
        int r = i >> 5, c4 = (i & 31) * 4;
        *(float4*)&xs[r*128 + c4] =
            *(const float4*)&x[(size_t)r * S_TOT + s0 + c4];
    }
    __syncthreads();

    const int tx = t & 15;   /* s-group: s = tx*4 + {0..3} and +64 */
    const int ty = t >> 4;   /* c-group: c = ty*4 + {0..3}          */

    #pragma unroll 1
    for (int p = 0; p < 3; p++) {
        float acc[4][8];
        #pragma unroll
        for (int i = 0; i < 4; i++) {
            float b = bs[p*64 + ty*4 + i];
            #pragma unroll
            for (int j = 0; j < 8; j++) acc[i][j] = b;
        }

        #pragma unroll 4
        for (int k = 0; k < 64; k++) {
            float4 x0 = *(float4*)&xs[k*128 + tx*4];
            float4 x1 = *(float4*)&xs[k*128 + tx*4 + 64];
            #pragma unroll
            for (int i = 0; i < 4; i++) {
                float wf = ws[(p*64 + ty*4 + i)*65 + k];
                acc[i][0] += wf * x0.x;  acc[i][1] += wf * x0.y;
                acc[i][2] += wf * x0.z;  acc[i][3] += wf * x0.w;
                acc[i][4] += wf * x1.x;  acc[i][5] += wf * x1.y;
                acc[i][6] += wf * x1.z;  acc[i][7] += wf * x1.w;
            }
        }

        const float scale = (p == 0) ? QSCALE : 1.0f;
        float* g = (p == 0) ? g_q : (p == 1) ? g_k : g_v;
        #pragma unroll
        for (int i = 0; i < 4; i++) {
            size_t row = (size_t)(ty*4 + i) * S_TOT + s0 + tx*4;
            float4 v0 = make_float4(acc[i][0]*scale, acc[i][1]*scale,
                                    acc[i][2]*scale, acc[i][3]*scale);
            float4 v1 = make_float4(acc[i][4]*scale, acc[i][5]*scale,
                                    acc[i][6]*scale, acc[i][7]*scale);
            *(float4*)&g[row]      = v0;
            *(float4*)&g[row + 64] = v1;
        }
    }
}

/* ------------------------------------------------------------------ */
/* Phase 2: per-(c,d) attention. One block per slab (3072 blocks).     */
/* smem rows padded to 132 floats for conflict-free strided-row loads. */
/* 8 warps; warp w owns output rows [16w, 16w+16).                     */
/* ------------------------------------------------------------------ */
#define P2_PAD  132
#define P2_SMEM (3 * 128 * P2_PAD * 4)   /* 202752 bytes */

__global__ void __launch_bounds__(256) attn_kernel()
{
    extern __shared__ float sm[];
    float* Ksh = sm;                    /* [128][132] */
    float* Vsh = Ksh + 128*P2_PAD;      /* [128][132] */
    float* QA  = Vsh + 128*P2_PAD;      /* Q, then overwritten per-warp by A */

    const int t    = threadIdx.x;
    const int lane = t & 31;
    const int wrp  = t >> 5;
    const size_t base = (size_t)blockIdx.x * SLAB;

    for (int i = t; i < 128*32; i += 256) {
        int r = i >> 5, c4 = (i & 31) * 4;
        *(float4*)&Ksh[r*P2_PAD + c4] = *(const float4*)&g_k[base + r*128 + c4];
        *(float4*)&Vsh[r*P2_PAD + c4] = *(const float4*)&g_v[base + r*128 + c4];
        *(float4*)&QA [r*P2_PAD + c4] = *(const float4*)&g_q[base + r*128 + c4];
    }
    __syncthreads();

    const int r0 = wrp * 16;

    /* ---- S = Q K^T : warp computes rows r0..r0+15, lane owns cols lane+32j */
    float s[16][4];
    #pragma unroll
    for (int i = 0; i < 16; i++)
        #pragma unroll
        for (int j = 0; j < 4; j++) s[i][j] = 0.0f;

    #pragma unroll 1
    for (int k4 = 0; k4 < 32; k4++) {
        float4 kf[4];
        #pragma unroll
        for (int j = 0; j < 4; j++)
            kf[j] = *(float4*)&Ksh[(lane + 32*j)*P2_PAD + k4*4];
        #pragma unroll
        for (int i = 0; i < 16; i++) {
            float4 qf = *(float4*)&QA[(r0 + i)*P2_PAD + k4*4];
            #pragma unroll
            for (int j = 0; j < 4; j++)
                s[i][j] += qf.x*kf[j].x + qf.y*kf[j].y
                         + qf.z*kf[j].z + qf.w*kf[j].w;
        }
    }

    /* ---- row softmax (cols spread across warp), write A into QA rows ---- */
    #pragma unroll 1
    for (int i = 0; i < 16; i++) {
        float m = fmaxf(fmaxf(s[i][0], s[i][1]), fmaxf(s[i][2], s[i][3]));
        #pragma unroll
        for (int off = 16; off; off >>= 1)
            m = fmaxf(m, __shfl_xor_sync(0xffffffffu, m, off));
        float e0 = __expf(s[i][0] - m);
        float e1 = __expf(s[i][1] - m);
        float e2 = __expf(s[i][2] - m);
        float e3 = __expf(s[i][3] - m);
        float sum = e0 + e1 + e2 + e3;
        #pragma unroll
        for (int off = 16; off; off >>= 1)
            sum += __shfl_xor_sync(0xffffffffu, sum, off);
        float inv = 1.0f / sum;
        float* row = &QA[(r0 + i)*P2_PAD];
        row[lane      ] = e0 * inv;
        row[lane + 32 ] = e1 * inv;
        row[lane + 64 ] = e2 * inv;
        row[lane + 96 ] = e3 * inv;
    }
    __syncwarp();

    /* ---- O = A V : lane owns h = lane*4..lane*4+3 ---- */
    float o[16][4];
    #pragma unroll
    for (int i = 0; i < 16; i++)
        #pragma unroll
        for (int j = 0; j < 4; j++) o[i][j] = 0.0f;

    #pragma unroll 1
    for (int v4 = 0; v4 < 32; v4++) {
        float4 vf[4];
        #pragma unroll
        for (int u = 0; u < 4; u++)
            vf[u] = *(float4*)&Vsh[(v4*4 + u)*P2_PAD + lane*4];
        #pragma unroll
        for (int i = 0; i < 16; i++) {
            float4 af = *(float4*)&QA[(r0 + i)*P2_PAD + v4*4];
            o[i][0] += af.x*vf[0].x + af.y*vf[1].x + af.z*vf[2].x + af.w*vf[3].x;
            o[i][1] += af.x*vf[0].y + af.y*vf[1].y + af.z*vf[2].y + af.w*vf[3].y;
            o[i][2] += af.x*vf[0].z + af.y*vf[1].z + af.z*vf[2].z + af.w*vf[3].z;
            o[i][3] += af.x*vf[0].w + af.y*vf[1].w + af.z*vf[2].w + af.w*vf[3].w;
        }
    }

    #pragma unroll
    for (int i = 0; i < 16; i++)
        *(float4*)&g_o[base + (size_t)(r0 + i)*128 + lane*4] =
            make_float4(o[i][0], o[i][1], o[i][2], o[i][3]);
}

/* ------------------------------------------------------------------ */
/* Phase 3: output projection. out[c][s] = sum_k wo[c][k]*o[k][s]+bo[c] */
/* ------------------------------------------------------------------ */
#define P3_SMEM ((64*65 + 64 + 64*128) * 4)

__global__ void __launch_bounds__(256) proj_o_kernel(
    float* __restrict__ out,
    const float* __restrict__ wo, const float* __restrict__ bo)
{
    extern __shared__ float sm[];
    float* ws = sm;              /* [64][65] */
    float* bs = ws + 64*65;      /* [64]     */
    float* xs = bs + 64;         /* [64][128]*/

    const int t  = threadIdx.x;
    const int s0 = blockIdx.x * 128;

    for (int i = t; i < 64*64; i += 256) {
        int r = i >> 6, c = i & 63;
        ws[r*65 + c] = wo[i];
    }
    if (t < 64) bs[t] = bo[t];
    for (int i = t; i < 64*32; i += 256) {
        int r = i >> 5, c4 = (i & 31) * 4;
        *(float4*)&xs[r*128 + c4] =
            *(const float4*)&g_o[(size_t)r * S_TOT + s0 + c4];
    }
    __syncthreads();

    const int tx = t & 15;
    const int ty = t >> 4;

    float acc[4][8];
    #pragma unroll
    for (int i = 0; i < 4; i++) {
        float b = bs[ty*4 + i];
        #pragma unroll
        for (int j = 0; j < 8; j++) acc[i][j] = b;
    }

    #pragma unroll 4
    for (int k = 0; k < 64; k++) {
        float4 x0 = *(float4*)&xs[k*128 + tx*4];
        float4 x1 = *(float4*)&xs[k*128 + tx*4 + 64];
        #pragma unroll
        for (int i = 0; i < 4; i++) {
            float wf = ws[(ty*4 + i)*65 + k];
            acc[i][0] += wf * x0.x;  acc[i][1] += wf * x0.y;
            acc[i][2] += wf * x0.z;  acc[i][3] += wf * x0.w;
            acc[i][4] += wf * x1.x;  acc[i][5] += wf * x1.y;
            acc[i][6] += wf * x1.z;  acc[i][7] += wf * x1.w;
        }
    }

    #pragma unroll
    for (int i = 0; i < 4; i++) {
        size_t row = (size_t)(ty*4 + i) * S_TOT + s0 + tx*4;
        *(float4*)&out[row]      = make_float4(acc[i][0], acc[i][1], acc[i][2], acc[i][3]);
        *(float4*)&out[row + 64] = make_float4(acc[i][4], acc[i][5], acc[i][6], acc[i][7]);
    }
}

/* ------------------------------------------------------------------ */
extern "C" void kernel_launch(void* const* d_in, const int* in_sizes, int n_in,
                              void* d_out, int out_size)
{
    const float* x  = (const float*)d_in[0];
    const float* wq = (const float*)d_in[1];
    const float* bq = (const float*)d_in[2];
    const float* wk = (const float*)d_in[3];
    const float* bk = (const float*)d_in[4];
    const float* wv = (const float*)d_in[5];
    const float* bv = (const float*)d_in[6];
    const float* wo = (const float*)d_in[7];
    const float* bo = (const float*)d_in[8];

    cudaFuncSetAttribute(qkv_kernel,    cudaFuncAttributeMaxDynamicSharedMemorySize, P1_SMEM);
    cudaFuncSetAttribute(attn_kernel,   cudaFuncAttributeMaxDynamicSharedMemorySize, P2_SMEM);
    cudaFuncSetAttribute(proj_o_kernel, cudaFuncAttributeMaxDynamicSharedMemorySize, P3_SMEM);

    qkv_kernel<<<S_TOT/128, 256, P1_SMEM>>>(x, wq, bq, wk, bk, wv, bv);
    attn_kernel<<<NSLAB, 256, P2_SMEM>>>();
    proj_o_kernel<<<S_TOT/128, 256, P3_SMEM>>>((float*)d_out, wo, bo);
}

// round 4
// speedup vs baseline: 1.3512x; 1.3512x over previous
#include <cuda_runtime.h>
#include <math.h>
#include <stdint.h>

#define CH    64
#define DDIM  48
#define WDIM  128
#define HDIM  128
#define S_TOT (DDIM*WDIM*HDIM)   /* 786432 spatial positions */
#define SLAB  (WDIM*HDIM)        /* 16384 per (c,d) slab     */
#define NSLAB (CH*DDIM)          /* 3072 attention problems  */

#define QSCALE 0.594603557501360533f   /* 8^(-1/4) */

__device__ float g_q[CH * S_TOT];
__device__ float g_k[CH * S_TOT];
__device__ float g_v[CH * S_TOT];
__device__ float g_o[CH * S_TOT];

/* ---------------- mma.sync tf32 helpers (legal in compute_103 PTX) ----- */
__device__ __forceinline__ void mma_tf32(float c[4],
                                         uint32_t a0, uint32_t a1, uint32_t a2, uint32_t a3,
                                         uint32_t b0, uint32_t b1) {
    asm volatile(
        "mma.sync.aligned.m16n8k8.row.col.f32.tf32.tf32.f32 "
        "{%0,%1,%2,%3}, {%4,%5,%6,%7}, {%8,%9}, {%0,%1,%2,%3};"
        : "+f"(c[0]), "+f"(c[1]), "+f"(c[2]), "+f"(c[3])
        : "r"(a0), "r"(a1), "r"(a2), "r"(a3), "r"(b0), "r"(b1));
}
__device__ __forceinline__ uint32_t f2tf32_rna(float f) {
    uint32_t u;
    asm("cvt.rna.tf32.f32 %0, %1;" : "=r"(u) : "f"(f));
    return u;
}
/* Dekker split: hi = tf32-truncation (what HMMA does to raw fp32 bits),
   lo = x - hi (exact in fp32). */
__device__ __forceinline__ void tf32_split(float x, uint32_t& hi, uint32_t& lo) {
    uint32_t h = __float_as_uint(x) & 0xFFFFE000u;
    hi = h;
    lo = __float_as_uint(x - __uint_as_float(h));
}

/* ------------------------------------------------------------------ */
/* Phase 1: fused QKV projection (fp32 FFMA).                          */
/* ------------------------------------------------------------------ */
#define P1_SMEM ((3*64*65 + 3*64 + 64*128) * 4)

__global__ void __launch_bounds__(256) qkv_kernel(
    const float* __restrict__ x,
    const float* __restrict__ wq, const float* __restrict__ bq,
    const float* __restrict__ wk, const float* __restrict__ bk,
    const float* __restrict__ wv, const float* __restrict__ bv)
{
    extern __shared__ float sm[];
    float* ws = sm;
    float* bs = ws + 3*64*65;
    float* xs = bs + 3*64;

    const int t  = threadIdx.x;
    const int s0 = blockIdx.x * 128;

    for (int i = t; i < 64*64; i += 256) {
        int r = i >> 6, c = i & 63;
        ws[(0*64 + r)*65 + c] = wq[i];
        ws[(1*64 + r)*65 + c] = wk[i];
        ws[(2*64 + r)*65 + c] = wv[i];
    }
    if (t < 64) { bs[t] = bq[t]; bs[64 + t] = bk[t]; bs[128 + t] = bv[t]; }
    for (int i = t; i < 64*32; i += 256) {
        int r = i >> 5, c4 = (i & 31) * 4;
        *(float4*)&xs[r*128 + c4] =
            *(const float4*)&x[(size_t)r * S_TOT + s0 + c4];
    }
    __syncthreads();

    const int tx = t & 15;
    const int ty = t >> 4;

    #pragma unroll 1
    for (int p = 0; p < 3; p++) {
        float acc[4][8];
        #pragma unroll
        for (int i = 0; i < 4; i++) {
            float b = bs[p*64 + ty*4 + i];
            #pragma unroll
            for (int j = 0; j < 8; j++) acc[i][j] = b;
        }

        #pragma unroll 4
        for (int k = 0; k < 64; k++) {
            float4 x0 = *(float4*)&xs[k*128 + tx*4];
            float4 x1 = *(float4*)&xs[k*128 + tx*4 + 64];
            #pragma unroll
            for (int i = 0; i < 4; i++) {
                float wf = ws[(p*64 + ty*4 + i)*65 + k];
                acc[i][0] += wf * x0.x;  acc[i][1] += wf * x0.y;
                acc[i][2] += wf * x0.z;  acc[i][3] += wf * x0.w;
                acc[i][4] += wf * x1.x;  acc[i][5] += wf * x1.y;
                acc[i][6] += wf * x1.z;  acc[i][7] += wf * x1.w;
            }
        }

        const float scale = (p == 0) ? QSCALE : 1.0f;
        float* g = (p == 0) ? g_q : (p == 1) ? g_k : g_v;
        #pragma unroll
        for (int i = 0; i < 4; i++) {
            size_t row = (size_t)(ty*4 + i) * S_TOT + s0 + tx*4;
            *(float4*)&g[row] = make_float4(acc[i][0]*scale, acc[i][1]*scale,
                                            acc[i][2]*scale, acc[i][3]*scale);
            *(float4*)&g[row + 64] = make_float4(acc[i][4]*scale, acc[i][5]*scale,
                                                 acc[i][6]*scale, acc[i][7]*scale);
        }
    }
}

/* ------------------------------------------------------------------ */
/* Phase 2: per-(c,d) attention via mma.sync tf32 (legacy HMMA path).  */
/*  S = QK^T with 3-term tf32 split; softmax; O = A*V single-pass tf32.*/
/*  8 warps, warp w owns output rows [16w, 16w+16).                    */
/* ------------------------------------------------------------------ */
#define QP 132          /* Q/A smem row pitch (floats) */
#define KP 132          /* K/O smem row pitch          */
#define VP 136          /* V smem row pitch            */
#define AT_SMEM ((128*QP + 128*KP + 128*VP) * 4)   /* 204800 bytes */

__global__ void __launch_bounds__(256) attn_kernel()
{
    extern __shared__ float sm[];
    float* Qs = sm;                 /* Q, later A (per-warp rows)   */
    float* Ks = Qs + 128*QP;        /* K, later O staging           */
    float* Vs = Ks + 128*KP;        /* V pre-rounded to tf32        */

    const int tid  = threadIdx.x;
    const int lane = tid & 31;
    const int wrp  = tid >> 5;
    const size_t base = (size_t)blockIdx.x * SLAB;

    /* ---- stage Q, K (raw fp32) and V (rna tf32) ---- */
    for (int i = tid; i < 128*32; i += 256) {
        int r = i >> 5, c4 = (i & 31) << 2;
        *(float4*)&Qs[r*QP + c4] = *(const float4*)&g_q[base + r*128 + c4];
        *(float4*)&Ks[r*KP + c4] = *(const float4*)&g_k[base + r*128 + c4];
        float4 v = *(const float4*)&g_v[base + r*128 + c4];
        uint4 vt;
        vt.x = f2tf32_rna(v.x); vt.y = f2tf32_rna(v.y);
        vt.z = f2tf32_rna(v.z); vt.w = f2tf32_rna(v.w);
        *(uint4*)&Vs[r*VP + c4] = vt;
    }
    __syncthreads();

    const int r0 = wrp * 16;
    const int lg = lane >> 2;       /* 0..7 */
    const int la = lane & 3;        /* 0..3 */

    /* ================= S = Q K^T (3-term tf32 split) ================= */
    float s[16][4];
    #pragma unroll
    for (int n = 0; n < 16; n++) {
        s[n][0] = 0.f; s[n][1] = 0.f; s[n][2] = 0.f; s[n][3] = 0.f;
    }

    #pragma unroll 1
    for (int kt = 0; kt < 16; kt++) {
        const int k0 = kt * 8;
        uint32_t ah[4], al[4];
        tf32_split(Qs[(r0 + lg    )*QP + k0 + la    ], ah[0], al[0]);
        tf32_split(Qs[(r0 + lg + 8)*QP + k0 + la    ], ah[1], al[1]);
        tf32_split(Qs[(r0 + lg    )*QP + k0 + la + 4], ah[2], al[2]);
        tf32_split(Qs[(r0 + lg + 8)*QP + k0 + la + 4], ah[3], al[3]);

        #pragma unroll
        for (int n = 0; n < 16; n++) {
            const int n0 = n * 8;
            uint32_t bh0, bl0, bh1, bl1;
            tf32_split(Ks[(n0 + lg)*KP + k0 + la    ], bh0, bl0);
            tf32_split(Ks[(n0 + lg)*KP + k0 + la + 4], bh1, bl1);
            mma_tf32(s[n], ah[0], ah[1], ah[2], ah[3], bh0, bh1);
            mma_tf32(s[n], ah[0], ah[1], ah[2], ah[3], bl0, bl1);
            mma_tf32(s[n], al[0], al[1], al[2], al[3], bh0, bh1);
        }
    }
    __syncwarp();

    /* ================= row softmax (rows ra and rb per thread) ======= */
    {
        float ma = -1e30f, mb = -1e30f;
        #pragma unroll
        for (int n = 0; n < 16; n++) {
            ma = fmaxf(ma, fmaxf(s[n][0], s[n][1]));
            mb = fmaxf(mb, fmaxf(s[n][2], s[n][3]));
        }
        ma = fmaxf(ma, __shfl_xor_sync(0xffffffffu, ma, 1));
        ma = fmaxf(ma, __shfl_xor_sync(0xffffffffu, ma, 2));
        mb = fmaxf(mb, __shfl_xor_sync(0xffffffffu, mb, 1));
        mb = fmaxf(mb, __shfl_xor_sync(0xffffffffu, mb, 2));

        float sa = 0.f, sb = 0.f;
        #pragma unroll
        for (int n = 0; n < 16; n++) {
            s[n][0] = __expf(s[n][0] - ma);  sa += s[n][0];
            s[n][1] = __expf(s[n][1] - ma);  sa += s[n][1];
            s[n][2] = __expf(s[n][2] - mb);  sb += s[n][2];
            s[n][3] = __expf(s[n][3] - mb);  sb += s[n][3];
        }
        sa += __shfl_xor_sync(0xffffffffu, sa, 1);
        sa += __shfl_xor_sync(0xffffffffu, sa, 2);
        sb += __shfl_xor_sync(0xffffffffu, sb, 1);
        sb += __shfl_xor_sync(0xffffffffu, sb, 2);
        const float ia = 1.0f / sa, ib = 1.0f / sb;

        /* write A (rna tf32) into Qs — warp-local rows, C-frag layout */
        const int ra = r0 + lg, rb = ra + 8, cc = 2 * la;
        #pragma unroll
        for (int n = 0; n < 16; n++) {
            float2 pa, pb;
            pa.x = __uint_as_float(f2tf32_rna(s[n][0] * ia));
            pa.y = __uint_as_float(f2tf32_rna(s[n][1] * ia));
            pb.x = __uint_as_float(f2tf32_rna(s[n][2] * ib));
            pb.y = __uint_as_float(f2tf32_rna(s[n][3] * ib));
            *(float2*)&Qs[ra*QP + n*8 + cc] = pa;
            *(float2*)&Qs[rb*QP + n*8 + cc] = pb;
        }
    }
    __syncwarp();

    /* ================= O = A * V (single-pass tf32) ================== */
    float o[16][4];
    #pragma unroll
    for (int n = 0; n < 16; n++) {
        o[n][0] = 0.f; o[n][1] = 0.f; o[n][2] = 0.f; o[n][3] = 0.f;
    }

    #pragma unroll 1
    for (int kt = 0; kt < 16; kt++) {
        const int k0 = kt * 8;
        uint32_t a0 = __float_as_uint(Qs[(r0 + lg    )*QP + k0 + la    ]);
        uint32_t a1 = __float_as_uint(Qs[(r0 + lg + 8)*QP + k0 + la    ]);
        uint32_t a2 = __float_as_uint(Qs[(r0 + lg    )*QP + k0 + la + 4]);
        uint32_t a3 = __float_as_uint(Qs[(r0 + lg + 8)*QP + k0 + la + 4]);

        #pragma unroll
        for (int n = 0; n < 16; n++) {
            const int n0 = n * 8;
            uint32_t b0 = __float_as_uint(Vs[(k0 + la    )*VP + n0 + lg]);
            uint32_t b1 = __float_as_uint(Vs[(k0 + la + 4)*VP + n0 + lg]);
            mma_tf32(o[n], a0, a1, a2, a3, b0, b1);
        }
    }

    /* ---- stage O through Ks (dead) for coalesced writes ---- */
    __syncthreads();
    {
        const int ra = r0 + lg, rb = ra + 8, cc = 2 * la;
        #pragma unroll
        for (int n = 0; n < 16; n++) {
            *(float2*)&Ks[ra*KP + n*8 + cc] = make_float2(o[n][0], o[n][1]);
            *(float2*)&Ks[rb*KP + n*8 + cc] = make_float2(o[n][2], o[n][3]);
        }
    }
    __syncthreads();
    for (int i = tid; i < 128*32; i += 256) {
        int r = i >> 5, c4 = (i & 31) << 2;
        *(float4*)&g_o[base + r*128 + c4] = *(float4*)&Ks[r*KP + c4];
    }
}

/* ------------------------------------------------------------------ */
/* Phase 3: output projection (fp32 FFMA).                             */
/* ------------------------------------------------------------------ */
#define P3_SMEM ((64*65 + 64 + 64*128) * 4)

__global__ void __launch_bounds__(256) proj_o_kernel(
    float* __restrict__ out,
    const float* __restrict__ wo, const float* __restrict__ bo)
{
    extern __shared__ float sm[];
    float* ws = sm;
    float* bs = ws + 64*65;
    float* xs = bs + 64;

    const int t  = threadIdx.x;
    const int s0 = blockIdx.x * 128;

    for (int i = t; i < 64*64; i += 256) {
        int r = i >> 6, c = i & 63;
        ws[r*65 + c] = wo[i];
    }
    if (t < 64) bs[t] = bo[t];
    for (int i = t; i < 64*32; i += 256) {
        int r = i >> 5, c4 = (i & 31) * 4;
        *(float4*)&xs[r*128 + c4] =
            *(const float4*)&g_o[(size_t)r * S_TOT + s0 + c4];
    }
    __syncthreads();

    const int tx = t & 15;
    const int ty = t >> 4;

    float acc[4][8];
    #pragma unroll
    for (int i = 0; i < 4; i++) {
        float b = bs[ty*4 + i];
        #pragma unroll
        for (int j = 0; j < 8; j++) acc[i][j] = b;
    }

    #pragma unroll 4
    for (int k = 0; k < 64; k++) {
        float4 x0 = *(float4*)&xs[k*128 + tx*4];
        float4 x1 = *(float4*)&xs[k*128 + tx*4 + 64];
        #pragma unroll
        for (int i = 0; i < 4; i++) {
            float wf = ws[(ty*4 + i)*65 + k];
            acc[i][0] += wf * x0.x;  acc[i][1] += wf * x0.y;
            acc[i][2] += wf * x0.z;  acc[i][3] += wf * x0.w;
            acc[i][4] += wf * x1.x;  acc[i][5] += wf * x1.y;
            acc[i][6] += wf * x1.z;  acc[i][7] += wf * x1.w;
        }
    }

    #pragma unroll
    for (int i = 0; i < 4; i++) {
        size_t row = (size_t)(ty*4 + i) * S_TOT + s0 + tx*4;
        *(float4*)&out[row]      = make_float4(acc[i][0], acc[i][1], acc[i][2], acc[i][3]);
        *(float4*)&out[row + 64] = make_float4(acc[i][4], acc[i][5], acc[i][6], acc[i][7]);
    }
}

/* ------------------------------------------------------------------ */
extern "C" void kernel_launch(void* const* d_in, const int* in_sizes, int n_in,
                              void* d_out, int out_size)
{
    const float* x  = (const float*)d_in[0];
    const float* wq = (const float*)d_in[1];
    const float* bq = (const float*)d_in[2];
    const float* wk = (const float*)d_in[3];
    const float* bk = (const float*)d_in[4];
    const float* wv = (const float*)d_in[5];
    const float* bv = (const float*)d_in[6];
    const float* wo = (const float*)d_in[7];
    const float* bo = (const float*)d_in[8];

    cudaFuncSetAttribute(qkv_kernel,    cudaFuncAttributeMaxDynamicSharedMemorySize, P1_SMEM);
    cudaFuncSetAttribute(attn_kernel,   cudaFuncAttributeMaxDynamicSharedMemorySize, AT_SMEM);
    cudaFuncSetAttribute(proj_o_kernel, cudaFuncAttributeMaxDynamicSharedMemorySize, P3_SMEM);

    qkv_kernel<<<S_TOT/128, 256, P1_SMEM>>>(x, wq, bq, wk, bk, wv, bv);
    attn_kernel<<<NSLAB, 256, AT_SMEM>>>();
    proj_o_kernel<<<S_TOT/128, 256, P3_SMEM>>>((float*)d_out, wo, bo);
}

// round 5
// speedup vs baseline: 1.4570x; 1.0784x over previous
#include <cuda_runtime.h>
#include <math.h>
#include <stdint.h>

#define CH    64
#define DDIM  48
#define WDIM  128
#define HDIM  128
#define S_TOT (DDIM*WDIM*HDIM)   /* 786432 spatial positions */
#define SLAB  (WDIM*HDIM)        /* 16384 per (c,d) slab     */
#define NSLAB (CH*DDIM)          /* 3072 attention problems  */

#define QSCALE 0.594603557501360533f   /* 8^(-1/4) */

__device__ float g_q[CH * S_TOT];
__device__ float g_k[CH * S_TOT];
__device__ float g_v[CH * S_TOT];
__device__ float g_o[CH * S_TOT];

/* ---------------- mma.sync tf32 helpers (legal in compute_103 PTX) ----- */
__device__ __forceinline__ void mma_tf32(float c[4],
                                         uint32_t a0, uint32_t a1, uint32_t a2, uint32_t a3,
                                         uint32_t b0, uint32_t b1) {
    asm volatile(
        "mma.sync.aligned.m16n8k8.row.col.f32.tf32.tf32.f32 "
        "{%0,%1,%2,%3}, {%4,%5,%6,%7}, {%8,%9}, {%0,%1,%2,%3};"
        : "+f"(c[0]), "+f"(c[1]), "+f"(c[2]), "+f"(c[3])
        : "r"(a0), "r"(a1), "r"(a2), "r"(a3), "r"(b0), "r"(b1));
}
__device__ __forceinline__ uint32_t f2tf32_rna(float f) {
    uint32_t u;
    asm("cvt.rna.tf32.f32 %0, %1;" : "=r"(u) : "f"(f));
    return u;
}
/* hi = tf32-truncation (what HMMA does to raw fp32 bits), lo = x - hi. */
__device__ __forceinline__ void tf32_split(float x, uint32_t& hi, uint32_t& lo) {
    uint32_t h = __float_as_uint(x) & 0xFFFFE000u;
    hi = h;
    lo = __float_as_uint(x - __uint_as_float(h));
}
__device__ __forceinline__ float tf32_lo(float x) {
    return x - __uint_as_float(__float_as_uint(x) & 0xFFFFE000u);
}

/* ------------------------------------------------------------------ */
/* Phase 1: fused QKV projection via split-tf32 mma.sync.              */
/* 384 thr = 12 warps. Warp w: tensor p=w>>2 (q/k/v), M-tile mt=w&3.   */
/* A = W rows [16mt,16mt+16) (in regs, pre-split), B = x cols in smem. */
/* ------------------------------------------------------------------ */
#define XP 136                         /* x smem pitch (floats) */
#define P1_SMEM (2 * 64 * XP * 4)      /* xhi + xlo = 69632 B   */

__global__ void __launch_bounds__(384) qkv_kernel(
    const float* __restrict__ x,
    const float* __restrict__ wq, const float* __restrict__ bq,
    const float* __restrict__ wk, const float* __restrict__ bk,
    const float* __restrict__ wv, const float* __restrict__ bv)
{
    extern __shared__ float sm[];
    float* xhi = sm;             /* [64][136] raw fp32 (HW truncates) */
    float* xlo = sm + 64*XP;     /* [64][136] exact residual          */

    const int tid  = threadIdx.x;
    const int lane = tid & 31;
    const int wrp  = tid >> 5;
    const int lg   = lane >> 2;        /* 0..7 */
    const int la   = lane & 3;         /* 0..3 */
    const int s0   = blockIdx.x * 128;

    /* ---- stage x slab: hi = raw, lo = residual ---- */
    for (int i = tid; i < 64*32; i += 384) {
        int r = i >> 5, c4 = (i & 31) << 2;
        float4 v = *(const float4*)&x[(size_t)r * S_TOT + s0 + c4];
        *(float4*)&xhi[r*XP + c4] = v;
        *(float4*)&xlo[r*XP + c4] =
            make_float4(tf32_lo(v.x), tf32_lo(v.y), tf32_lo(v.z), tf32_lo(v.w));
    }

    /* ---- per-warp: load + split W fragments into registers ---- */
    const int p  = wrp >> 2;                 /* 0=q 1=k 2=v */
    const int c0 = (wrp & 3) * 16;
    const float* W = (p == 0) ? wq : (p == 1) ? wk : wv;
    const float* B = (p == 0) ? bq : (p == 1) ? bk : bv;

    uint32_t ah[32], al[32];
    #pragma unroll
    for (int ks = 0; ks < 8; ks++) {
        int k1 = ks*8 + la;
        tf32_split(W[(c0 + lg    )*64 + k1    ], ah[ks*4+0], al[ks*4+0]);
        tf32_split(W[(c0 + lg + 8)*64 + k1    ], ah[ks*4+1], al[ks*4+1]);
        tf32_split(W[(c0 + lg    )*64 + k1 + 4], ah[ks*4+2], al[ks*4+2]);
        tf32_split(W[(c0 + lg + 8)*64 + k1 + 4], ah[ks*4+3], al[ks*4+3]);
    }
    const float b1 = B[c0 + lg];
    const float b2 = B[c0 + lg + 8];
    const float scale = (p == 0) ? QSCALE : 1.0f;
    float* g = (p == 0) ? g_q : (p == 1) ? g_k : g_v;

    __syncthreads();

    /* ---- two N-halves of 8 n-tiles each ---- */
    #pragma unroll 1
    for (int hf = 0; hf < 2; hf++) {
        float c[8][4];
        #pragma unroll
        for (int n = 0; n < 8; n++) {
            c[n][0] = b1; c[n][1] = b1; c[n][2] = b2; c[n][3] = b2;
        }

        #pragma unroll 1
        for (int ks = 0; ks < 8; ks++) {
            const int kr0 = (ks*8 + la) * XP + hf*64 + lg;
            const int kr1 = kr0 + 4*XP;
            #pragma unroll
            for (int n = 0; n < 8; n++) {
                uint32_t bh0 = __float_as_uint(xhi[kr0 + n*8]);
                uint32_t bh1 = __float_as_uint(xhi[kr1 + n*8]);
                uint32_t bl0 = __float_as_uint(xlo[kr0 + n*8]);
                uint32_t bl1 = __float_as_uint(xlo[kr1 + n*8]);
                mma_tf32(c[n], ah[ks*4+0], ah[ks*4+1], ah[ks*4+2], ah[ks*4+3], bh0, bh1);
                mma_tf32(c[n], ah[ks*4+0], ah[ks*4+1], ah[ks*4+2], ah[ks*4+3], bl0, bl1);
                mma_tf32(c[n], al[ks*4+0], al[ks*4+1], al[ks*4+2], al[ks*4+3], bh0, bh1);
            }
        }

        #pragma unroll
        for (int n = 0; n < 8; n++) {
            size_t col = (size_t)(s0 + hf*64 + n*8 + 2*la);
            *(float2*)&g[(size_t)(c0 + lg    )*S_TOT + col] =
                make_float2(c[n][0]*scale, c[n][1]*scale);
            *(float2*)&g[(size_t)(c0 + lg + 8)*S_TOT + col] =
                make_float2(c[n][2]*scale, c[n][3]*scale);
        }
    }
}

/* ------------------------------------------------------------------ */
/* Phase 2: per-(c,d) attention via mma.sync tf32 (unchanged, passing).*/
/* ------------------------------------------------------------------ */
#define QP 132
#define KP 132
#define VP 136
#define AT_SMEM ((128*QP + 128*KP + 128*VP) * 4)   /* 204800 bytes */

__global__ void __launch_bounds__(256) attn_kernel()
{
    extern __shared__ float sm[];
    float* Qs = sm;
    float* Ks = Qs + 128*QP;
    float* Vs = Ks + 128*KP;

    const int tid  = threadIdx.x;
    const int lane = tid & 31;
    const int wrp  = tid >> 5;
    const size_t base = (size_t)blockIdx.x * SLAB;

    for (int i = tid; i < 128*32; i += 256) {
        int r = i >> 5, c4 = (i & 31) << 2;
        *(float4*)&Qs[r*QP + c4] = *(const float4*)&g_q[base + r*128 + c4];
        *(float4*)&Ks[r*KP + c4] = *(const float4*)&g_k[base + r*128 + c4];
        float4 v = *(const float4*)&g_v[base + r*128 + c4];
        uint4 vt;
        vt.x = f2tf32_rna(v.x); vt.y = f2tf32_rna(v.y);
        vt.z = f2tf32_rna(v.z); vt.w = f2tf32_rna(v.w);
        *(uint4*)&Vs[r*VP + c4] = vt;
    }
    __syncthreads();

    const int r0 = wrp * 16;
    const int lg = lane >> 2;
    const int la = lane & 3;

    float s[16][4];
    #pragma unroll
    for (int n = 0; n < 16; n++) {
        s[n][0] = 0.f; s[n][1] = 0.f; s[n][2] = 0.f; s[n][3] = 0.f;
    }

    #pragma unroll 1
    for (int kt = 0; kt < 16; kt++) {
        const int k0 = kt * 8;
        uint32_t ah[4], al[4];
        tf32_split(Qs[(r0 + lg    )*QP + k0 + la    ], ah[0], al[0]);
        tf32_split(Qs[(r0 + lg + 8)*QP + k0 + la    ], ah[1], al[1]);
        tf32_split(Qs[(r0 + lg    )*QP + k0 + la + 4], ah[2], al[2]);
        tf32_split(Qs[(r0 + lg + 8)*QP + k0 + la + 4], ah[3], al[3]);

        #pragma unroll
        for (int n = 0; n < 16; n++) {
            const int n0 = n * 8;
            uint32_t bh0, bl0, bh1, bl1;
            tf32_split(Ks[(n0 + lg)*KP + k0 + la    ], bh0, bl0);
            tf32_split(Ks[(n0 + lg)*KP + k0 + la + 4], bh1, bl1);
            mma_tf32(s[n], ah[0], ah[1], ah[2], ah[3], bh0, bh1);
            mma_tf32(s[n], ah[0], ah[1], ah[2], ah[3], bl0, bl1);
            mma_tf32(s[n], al[0], al[1], al[2], al[3], bh0, bh1);
        }
    }
    __syncwarp();

    {
        float ma = -1e30f, mb = -1e30f;
        #pragma unroll
        for (int n = 0; n < 16; n++) {
            ma = fmaxf(ma, fmaxf(s[n][0], s[n][1]));
            mb = fmaxf(mb, fmaxf(s[n][2], s[n][3]));
        }
        ma = fmaxf(ma, __shfl_xor_sync(0xffffffffu, ma, 1));
        ma = fmaxf(ma, __shfl_xor_sync(0xffffffffu, ma, 2));
        mb = fmaxf(mb, __shfl_xor_sync(0xffffffffu, mb, 1));
        mb = fmaxf(mb, __shfl_xor_sync(0xffffffffu, mb, 2));

        float sa = 0.f, sb = 0.f;
        #pragma unroll
        for (int n = 0; n < 16; n++) {
            s[n][0] = __expf(s[n][0] - ma);  sa += s[n][0];
            s[n][1] = __expf(s[n][1] - ma);  sa += s[n][1];
            s[n][2] = __expf(s[n][2] - mb);  sb += s[n][2];
            s[n][3] = __expf(s[n][3] - mb);  sb += s[n][3];
        }
        sa += __shfl_xor_sync(0xffffffffu, sa, 1);
        sa += __shfl_xor_sync(0xffffffffu, sa, 2);
        sb += __shfl_xor_sync(0xffffffffu, sb, 1);
        sb += __shfl_xor_sync(0xffffffffu, sb, 2);
        const float ia = 1.0f / sa, ib = 1.0f / sb;

        const int ra = r0 + lg, rb = ra + 8, cc = 2 * la;
        #pragma unroll
        for (int n = 0; n < 16; n++) {
            float2 pa, pb;
            pa.x = __uint_as_float(f2tf32_rna(s[n][0] * ia));
            pa.y = __uint_as_float(f2tf32_rna(s[n][1] * ia));
            pb.x = __uint_as_float(f2tf32_rna(s[n][2] * ib));
            pb.y = __uint_as_float(f2tf32_rna(s[n][3] * ib));
            *(float2*)&Qs[ra*QP + n*8 + cc] = pa;
            *(float2*)&Qs[rb*QP + n*8 + cc] = pb;
        }
    }
    __syncwarp();

    float o[16][4];
    #pragma unroll
    for (int n = 0; n < 16; n++) {
        o[n][0] = 0.f; o[n][1] = 0.f; o[n][2] = 0.f; o[n][3] = 0.f;
    }

    #pragma unroll 1
    for (int kt = 0; kt < 16; kt++) {
        const int k0 = kt * 8;
        uint32_t a0 = __float_as_uint(Qs[(r0 + lg    )*QP + k0 + la    ]);
        uint32_t a1 = __float_as_uint(Qs[(r0 + lg + 8)*QP + k0 + la    ]);
        uint32_t a2 = __float_as_uint(Qs[(r0 + lg    )*QP + k0 + la + 4]);
        uint32_t a3 = __float_as_uint(Qs[(r0 + lg + 8)*QP + k0 + la + 4]);

        #pragma unroll
        for (int n = 0; n < 16; n++) {
            const int n0 = n * 8;
            uint32_t b0 = __float_as_uint(Vs[(k0 + la    )*VP + n0 + lg]);
            uint32_t b1 = __float_as_uint(Vs[(k0 + la + 4)*VP + n0 + lg]);
            mma_tf32(o[n], a0, a1, a2, a3, b0, b1);
        }
    }

    __syncthreads();
    {
        const int ra = r0 + lg, rb = ra + 8, cc = 2 * la;
        #pragma unroll
        for (int n = 0; n < 16; n++) {
            *(float2*)&Ks[ra*KP + n*8 + cc] = make_float2(o[n][0], o[n][1]);
            *(float2*)&Ks[rb*KP + n*8 + cc] = make_float2(o[n][2], o[n][3]);
        }
    }
    __syncthreads();
    for (int i = tid; i < 128*32; i += 256) {
        int r = i >> 5, c4 = (i & 31) << 2;
        *(float4*)&g_o[base + r*128 + c4] = *(float4*)&Ks[r*KP + c4];
    }
}

/* ------------------------------------------------------------------ */
/* Phase 3: output projection via split-tf32 mma.sync.                 */
/* 256 thr = 8 warps. Warp w: M-tile mt=w&3, N-half nh=w>>2.           */
/* ------------------------------------------------------------------ */
#define P3_SMEM (2 * 64 * XP * 4)

__global__ void __launch_bounds__(256) proj_o_kernel(
    float* __restrict__ out,
    const float* __restrict__ wo, const float* __restrict__ bo)
{
    extern __shared__ float sm[];
    float* ohi = sm;
    float* olo = sm + 64*XP;

    const int tid  = threadIdx.x;
    const int lane = tid & 31;
    const int wrp  = tid >> 5;
    const int lg   = lane >> 2;
    const int la   = lane & 3;
    const int s0   = blockIdx.x * 128;

    for (int i = tid; i < 64*32; i += 256) {
        int r = i >> 5, c4 = (i & 31) << 2;
        float4 v = *(const float4*)&g_o[(size_t)r * S_TOT + s0 + c4];
        *(float4*)&ohi[r*XP + c4] = v;
        *(float4*)&olo[r*XP + c4] =
            make_float4(tf32_lo(v.x), tf32_lo(v.y), tf32_lo(v.z), tf32_lo(v.w));
    }

    const int c0 = (wrp & 3) * 16;
    const int hf = wrp >> 2;

    uint32_t ah[32], al[32];
    #pragma unroll
    for (int ks = 0; ks < 8; ks++) {
        int k1 = ks*8 + la;
        tf32_split(wo[(c0 + lg    )*64 + k1    ], ah[ks*4+0], al[ks*4+0]);
        tf32_split(wo[(c0 + lg + 8)*64 + k1    ], ah[ks*4+1], al[ks*4+1]);
        tf32_split(wo[(c0 + lg    )*64 + k1 + 4], ah[ks*4+2], al[ks*4+2]);
        tf32_split(wo[(c0 + lg + 8)*64 + k1 + 4], ah[ks*4+3], al[ks*4+3]);
    }
    const float b1 = bo[c0 + lg];
    const float b2 = bo[c0 + lg + 8];

    __syncthreads();

    float c[8][4];
    #pragma unroll
    for (int n = 0; n < 8; n++) {
        c[n][0] = b1; c[n][1] = b1; c[n][2] = b2; c[n][3] = b2;
    }

    #pragma unroll 1
    for (int ks = 0; ks < 8; ks++) {
        const int kr0 = (ks*8 + la) * XP + hf*64 + lg;
        const int kr1 = kr0 + 4*XP;
        #pragma unroll
        for (int n = 0; n < 8; n++) {
            uint32_t bh0 = __float_as_uint(ohi[kr0 + n*8]);
            uint32_t bh1 = __float_as_uint(ohi[kr1 + n*8]);
            uint32_t bl0 = __float_as_uint(olo[kr0 + n*8]);
            uint32_t bl1 = __float_as_uint(olo[kr1 + n*8]);
            mma_tf32(c[n], ah[ks*4+0], ah[ks*4+1], ah[ks*4+2], ah[ks*4+3], bh0, bh1);
            mma_tf32(c[n], ah[ks*4+0], ah[ks*4+1], ah[ks*4+2], ah[ks*4+3], bl0, bl1);
            mma_tf32(c[n], al[ks*4+0], al[ks*4+1], al[ks*4+2], al[ks*4+3], bh0, bh1);
        }
    }

    #pragma unroll
    for (int n = 0; n < 8; n++) {
        size_t col = (size_t)(s0 + hf*64 + n*8 + 2*la);
        *(float2*)&out[(size_t)(c0 + lg    )*S_TOT + col] = make_float2(c[n][0], c[n][1]);
        *(float2*)&out[(size_t)(c0 + lg + 8)*S_TOT + col] = make_float2(c[n][2], c[n][3]);
    }
}

/* ------------------------------------------------------------------ */
extern "C" void kernel_launch(void* const* d_in, const int* in_sizes, int n_in,
                              void* d_out, int out_size)
{
    const float* x  = (const float*)d_in[0];
    const float* wq = (const float*)d_in[1];
    const float* bq = (const float*)d_in[2];
    const float* wk = (const float*)d_in[3];
    const float* bk = (const float*)d_in[4];
    const float* wv = (const float*)d_in[5];
    const float* bv = (const float*)d_in[6];
    const float* wo = (const float*)d_in[7];
    const float* bo = (const float*)d_in[8];

    cudaFuncSetAttribute(qkv_kernel,    cudaFuncAttributeMaxDynamicSharedMemorySize, P1_SMEM);
    cudaFuncSetAttribute(attn_kernel,   cudaFuncAttributeMaxDynamicSharedMemorySize, AT_SMEM);
    cudaFuncSetAttribute(proj_o_kernel, cudaFuncAttributeMaxDynamicSharedMemorySize, P3_SMEM);

    qkv_kernel<<<S_TOT/128, 384, P1_SMEM>>>(x, wq, bq, wk, bk, wv, bv);
    attn_kernel<<<NSLAB, 256, AT_SMEM>>>();
    proj_o_kernel<<<S_TOT/128, 256, P3_SMEM>>>((float*)d_out, wo, bo);
}

// round 6
// speedup vs baseline: 1.5589x; 1.0699x over previous
#include <cuda_runtime.h>
#include <cuda_bf16.h>
#include <math.h>
#include <stdint.h>

#define CH    64
#define DDIM  48
#define WDIM  128
#define HDIM  128
#define S_TOT (DDIM*WDIM*HDIM)   /* 786432 spatial positions */
#define SLAB  (WDIM*HDIM)        /* 16384 per (c,d) slab     */
#define NSLAB (CH*DDIM)          /* 3072 attention problems  */

#define QSCALE 0.594603557501360533f   /* 8^(-1/4) */

__device__ float g_q[CH * S_TOT];
__device__ float g_k[CH * S_TOT];
__device__ float g_v[CH * S_TOT];
__device__ float g_o[CH * S_TOT];

/* ---------------- mma.sync helpers (legal in compute_103 PTX) ---------- */
__device__ __forceinline__ void mma_tf32(float c[4],
                                         uint32_t a0, uint32_t a1, uint32_t a2, uint32_t a3,
                                         uint32_t b0, uint32_t b1) {
    asm volatile(
        "mma.sync.aligned.m16n8k8.row.col.f32.tf32.tf32.f32 "
        "{%0,%1,%2,%3}, {%4,%5,%6,%7}, {%8,%9}, {%0,%1,%2,%3};"
        : "+f"(c[0]), "+f"(c[1]), "+f"(c[2]), "+f"(c[3])
        : "r"(a0), "r"(a1), "r"(a2), "r"(a3), "r"(b0), "r"(b1));
}
__device__ __forceinline__ void mma_bf16(float c[4],
                                         uint32_t a0, uint32_t a1, uint32_t a2, uint32_t a3,
                                         uint32_t b0, uint32_t b1) {
    asm volatile(
        "mma.sync.aligned.m16n8k16.row.col.f32.bf16.bf16.f32 "
        "{%0,%1,%2,%3}, {%4,%5,%6,%7}, {%8,%9}, {%0,%1,%2,%3};"
        : "+f"(c[0]), "+f"(c[1]), "+f"(c[2]), "+f"(c[3])
        : "r"(a0), "r"(a1), "r"(a2), "r"(a3), "r"(b0), "r"(b1));
}
__device__ __forceinline__ uint32_t f2tf32_rna(float f) {
    uint32_t u;
    asm("cvt.rna.tf32.f32 %0, %1;" : "=r"(u) : "f"(f));
    return u;
}
__device__ __forceinline__ void tf32_split(float x, uint32_t& hi, uint32_t& lo) {
    uint32_t h = __float_as_uint(x) & 0xFFFFE000u;
    hi = h;
    lo = __float_as_uint(x - __uint_as_float(h));
}
__device__ __forceinline__ float tf32_lo(float x) {
    return x - __uint_as_float(__float_as_uint(x) & 0xFFFFE000u);
}
/* 2-term bf16 Dekker split of a pair, packed as bf16x2 words */
__device__ __forceinline__ void bf16_split2(float x, float y, uint32_t& h, uint32_t& l) {
    __nv_bfloat162 hb = __floats2bfloat162_rn(x, y);
    float hx = __bfloat162float(hb.x);
    float hy = __bfloat162float(hb.y);
    __nv_bfloat162 lb = __floats2bfloat162_rn(x - hx, y - hy);
    h = *(uint32_t*)&hb;
    l = *(uint32_t*)&lb;
}

/* ------------------------------------------------------------------ */
/* Phase 1: fused QKV projection via split-tf32 mma.sync.              */
/* q/k: 3-term split (scores need accuracy). v: single-MMA rna.        */
/* ------------------------------------------------------------------ */
#define XP 136                         /* x smem pitch (floats) */
#define P1_SMEM (2 * 64 * XP * 4)      /* xhi + xlo = 69632 B   */

__global__ void __launch_bounds__(384) qkv_kernel(
    const float* __restrict__ x,
    const float* __restrict__ wq, const float* __restrict__ bq,
    const float* __restrict__ wk, const float* __restrict__ bk,
    const float* __restrict__ wv, const float* __restrict__ bv)
{
    extern __shared__ float sm[];
    float* xhi = sm;             /* [64][136] raw fp32 (HW truncates) */
    float* xlo = sm + 64*XP;     /* [64][136] exact residual          */

    const int tid  = threadIdx.x;
    const int lane = tid & 31;
    const int wrp  = tid >> 5;
    const int lg   = lane >> 2;
    const int la   = lane & 3;
    const int s0   = blockIdx.x * 128;

    for (int i = tid; i < 64*32; i += 384) {
        int r = i >> 5, c4 = (i & 31) << 2;
        float4 v = *(const float4*)&x[(size_t)r * S_TOT + s0 + c4];
        *(float4*)&xhi[r*XP + c4] = v;
        *(float4*)&xlo[r*XP + c4] =
            make_float4(tf32_lo(v.x), tf32_lo(v.y), tf32_lo(v.z), tf32_lo(v.w));
    }

    const int p  = wrp >> 2;                 /* 0=q 1=k 2=v */
    const int c0 = (wrp & 3) * 16;
    const float* W = (p == 0) ? wq : (p == 1) ? wk : wv;
    const float* B = (p == 0) ? bq : (p == 1) ? bk : bv;

    uint32_t ah[32], al[32];
    if (p < 2) {
        #pragma unroll
        for (int ks = 0; ks < 8; ks++) {
            int k1 = ks*8 + la;
            tf32_split(W[(c0 + lg    )*64 + k1    ], ah[ks*4+0], al[ks*4+0]);
            tf32_split(W[(c0 + lg + 8)*64 + k1    ], ah[ks*4+1], al[ks*4+1]);
            tf32_split(W[(c0 + lg    )*64 + k1 + 4], ah[ks*4+2], al[ks*4+2]);
            tf32_split(W[(c0 + lg + 8)*64 + k1 + 4], ah[ks*4+3], al[ks*4+3]);
        }
    } else {
        #pragma unroll
        for (int ks = 0; ks < 8; ks++) {
            int k1 = ks*8 + la;
            ah[ks*4+0] = f2tf32_rna(W[(c0 + lg    )*64 + k1    ]);
            ah[ks*4+1] = f2tf32_rna(W[(c0 + lg + 8)*64 + k1    ]);
            ah[ks*4+2] = f2tf32_rna(W[(c0 + lg    )*64 + k1 + 4]);
            ah[ks*4+3] = f2tf32_rna(W[(c0 + lg + 8)*64 + k1 + 4]);
        }
    }
    const float b1 = B[c0 + lg];
    const float b2 = B[c0 + lg + 8];
    const float scale = (p == 0) ? QSCALE : 1.0f;
    float* g = (p == 0) ? g_q : (p == 1) ? g_k : g_v;

    __syncthreads();

    #pragma unroll 1
    for (int hf = 0; hf < 2; hf++) {
        float c[8][4];
        #pragma unroll
        for (int n = 0; n < 8; n++) {
            c[n][0] = b1; c[n][1] = b1; c[n][2] = b2; c[n][3] = b2;
        }

        if (p < 2) {
            #pragma unroll 1
            for (int ks = 0; ks < 8; ks++) {
                const int kr0 = (ks*8 + la) * XP + hf*64 + lg;
                const int kr1 = kr0 + 4*XP;
                #pragma unroll
                for (int n = 0; n < 8; n++) {
                    uint32_t bh0 = __float_as_uint(xhi[kr0 + n*8]);
                    uint32_t bh1 = __float_as_uint(xhi[kr1 + n*8]);
                    uint32_t bl0 = __float_as_uint(xlo[kr0 + n*8]);
                    uint32_t bl1 = __float_as_uint(xlo[kr1 + n*8]);
                    mma_tf32(c[n], ah[ks*4+0], ah[ks*4+1], ah[ks*4+2], ah[ks*4+3], bh0, bh1);
                    mma_tf32(c[n], ah[ks*4+0], ah[ks*4+1], ah[ks*4+2], ah[ks*4+3], bl0, bl1);
                    mma_tf32(c[n], al[ks*4+0], al[ks*4+1], al[ks*4+2], al[ks*4+3], bh0, bh1);
                }
            }
        } else {
            #pragma unroll 1
            for (int ks = 0; ks < 8; ks++) {
                const int kr0 = (ks*8 + la) * XP + hf*64 + lg;
                const int kr1 = kr0 + 4*XP;
                #pragma unroll
                for (int n = 0; n < 8; n++) {
                    uint32_t bh0 = f2tf32_rna(xhi[kr0 + n*8]);
                    uint32_t bh1 = f2tf32_rna(xhi[kr1 + n*8]);
                    mma_tf32(c[n], ah[ks*4+0], ah[ks*4+1], ah[ks*4+2], ah[ks*4+3], bh0, bh1);
                }
            }
        }

        #pragma unroll
        for (int n = 0; n < 8; n++) {
            size_t col = (size_t)(s0 + hf*64 + n*8 + 2*la);
            *(float2*)&g[(size_t)(c0 + lg    )*S_TOT + col] =
                make_float2(c[n][0]*scale, c[n][1]*scale);
            *(float2*)&g[(size_t)(c0 + lg + 8)*S_TOT + col] =
                make_float2(c[n][2]*scale, c[n][3]*scale);
        }
    }
}

/* ------------------------------------------------------------------ */
/* Phase 2: per-(c,d) attention via bf16 m16n8k16 2-term splits.       */
/*  smem (bytes):                                                      */
/*   Qhi [128][136]bf16 @0       Qlo @34816   (reused as O fp32 stage) */
/*   Khi @69632                  Klo @104448  (reused as Ahi/Alo)      */
/*   Vph [64][132]u32 @139264    Vpl @173056  (key-pair packed bf16x2) */
/* ------------------------------------------------------------------ */
#define ATQ_HI 0
#define ATQ_LO 34816
#define ATK_HI 69632
#define ATK_LO 104448
#define ATV_HI 139264
#define ATV_LO 173056
#define AT_SMEM 206848

__global__ void __launch_bounds__(256) attn_kernel()
{
    extern __shared__ char smc[];
    const int tid  = threadIdx.x;
    const int lane = tid & 31;
    const int wrp  = tid >> 5;
    const int lg   = lane >> 2;
    const int la   = lane & 3;
    const size_t base = (size_t)blockIdx.x * SLAB;

    /* ---- stage Q,K (bf16 hi/lo rows) and V (key-pair packed) ---- */
    for (int i = tid; i < 128*32; i += 256) {
        int r = i >> 5, c4 = (i & 31) << 2;
        uint32_t h0, l0, h1, l1;

        float4 q = *(const float4*)&g_q[base + r*128 + c4];
        bf16_split2(q.x, q.y, h0, l0);
        bf16_split2(q.z, q.w, h1, l1);
        *(uint2*)(smc + ATQ_HI + r*272 + c4*2) = make_uint2(h0, h1);
        *(uint2*)(smc + ATQ_LO + r*272 + c4*2) = make_uint2(l0, l1);

        float4 k = *(const float4*)&g_k[base + r*128 + c4];
        bf16_split2(k.x, k.y, h0, l0);
        bf16_split2(k.z, k.w, h1, l1);
        *(uint2*)(smc + ATK_HI + r*272 + c4*2) = make_uint2(h0, h1);
        *(uint2*)(smc + ATK_LO + r*272 + c4*2) = make_uint2(l0, l1);

        float4 v = *(const float4*)&g_v[base + r*128 + c4];
        {
            const int kp = r >> 1, hh = (r & 1) * 2;
            float vv[4] = {v.x, v.y, v.z, v.w};
            #pragma unroll
            for (int j = 0; j < 4; j++) {
                __nv_bfloat16 vh = __float2bfloat16(vv[j]);
                __nv_bfloat16 vl = __float2bfloat16(vv[j] - __bfloat162float(vh));
                *(unsigned short*)(smc + ATV_HI + (kp*132 + c4 + j)*4 + hh) =
                    *(unsigned short*)&vh;
                *(unsigned short*)(smc + ATV_LO + (kp*132 + c4 + j)*4 + hh) =
                    *(unsigned short*)&vl;
            }
        }
    }
    __syncthreads();

    const int r0 = wrp * 16;
    const int ra = r0 + lg, rb = ra + 8;

    /* ================= S = Q K^T : 3 bf16 MMAs per (kt,n) ============ */
    float s[16][4];
    #pragma unroll
    for (int n = 0; n < 16; n++) {
        s[n][0] = 0.f; s[n][1] = 0.f; s[n][2] = 0.f; s[n][3] = 0.f;
    }

    #pragma unroll 1
    for (int kt = 0; kt < 8; kt++) {
        const int k0 = kt * 16;
        const char* qh = smc + ATQ_HI + (r0 + lg)*272 + (k0 + 2*la)*2;
        const char* ql = smc + ATQ_LO + (r0 + lg)*272 + (k0 + 2*la)*2;
        uint32_t ah0 = *(const uint32_t*)(qh);
        uint32_t ah1 = *(const uint32_t*)(qh + 8*272);
        uint32_t ah2 = *(const uint32_t*)(qh + 16);
        uint32_t ah3 = *(const uint32_t*)(qh + 8*272 + 16);
        uint32_t al0 = *(const uint32_t*)(ql);
        uint32_t al1 = *(const uint32_t*)(ql + 8*272);
        uint32_t al2 = *(const uint32_t*)(ql + 16);
        uint32_t al3 = *(const uint32_t*)(ql + 8*272 + 16);

        #pragma unroll
        for (int n = 0; n < 16; n++) {
            const char* kh = smc + ATK_HI + (n*8 + lg)*272 + (k0 + 2*la)*2;
            const char* kl = smc + ATK_LO + (n*8 + lg)*272 + (k0 + 2*la)*2;
            uint32_t bh0 = *(const uint32_t*)(kh);
            uint32_t bh1 = *(const uint32_t*)(kh + 16);
            uint32_t bl0 = *(const uint32_t*)(kl);
            uint32_t bl1 = *(const uint32_t*)(kl + 16);
            mma_bf16(s[n], ah0, ah1, ah2, ah3, bh0, bh1);
            mma_bf16(s[n], ah0, ah1, ah2, ah3, bl0, bl1);
            mma_bf16(s[n], al0, al1, al2, al3, bh0, bh1);
        }
    }

    /* ================= row softmax ==================================== */
    float ia, ib;
    {
        float ma = -1e30f, mb = -1e30f;
        #pragma unroll
        for (int n = 0; n < 16; n++) {
            ma = fmaxf(ma, fmaxf(s[n][0], s[n][1]));
            mb = fmaxf(mb, fmaxf(s[n][2], s[n][3]));
        }
        ma = fmaxf(ma, __shfl_xor_sync(0xffffffffu, ma, 1));
        ma = fmaxf(ma, __shfl_xor_sync(0xffffffffu, ma, 2));
        mb = fmaxf(mb, __shfl_xor_sync(0xffffffffu, mb, 1));
        mb = fmaxf(mb, __shfl_xor_sync(0xffffffffu, mb, 2));

        float sa = 0.f, sb = 0.f;
        #pragma unroll
        for (int n = 0; n < 16; n++) {
            s[n][0] = __expf(s[n][0] - ma);  sa += s[n][0];
            s[n][1] = __expf(s[n][1] - ma);  sa += s[n][1];
            s[n][2] = __expf(s[n][2] - mb);  sb += s[n][2];
            s[n][3] = __expf(s[n][3] - mb);  sb += s[n][3];
        }
        sa += __shfl_xor_sync(0xffffffffu, sa, 1);
        sa += __shfl_xor_sync(0xffffffffu, sa, 2);
        sb += __shfl_xor_sync(0xffffffffu, sb, 1);
        sb += __shfl_xor_sync(0xffffffffu, sb, 2);
        ia = 1.0f / sa;  ib = 1.0f / sb;
    }

    /* all warps must be done reading K before A overwrites it */
    __syncthreads();
    #pragma unroll
    for (int n = 0; n < 16; n++) {
        uint32_t h, l;
        bf16_split2(s[n][0] * ia, s[n][1] * ia, h, l);
        *(uint32_t*)(smc + ATK_HI + ra*272 + (n*8 + 2*la)*2) = h;
        *(uint32_t*)(smc + ATK_LO + ra*272 + (n*8 + 2*la)*2) = l;
        bf16_split2(s[n][2] * ib, s[n][3] * ib, h, l);
        *(uint32_t*)(smc + ATK_HI + rb*272 + (n*8 + 2*la)*2) = h;
        *(uint32_t*)(smc + ATK_LO + rb*272 + (n*8 + 2*la)*2) = l;
    }
    __syncwarp();

    /* ================= O = A V : 3 bf16 MMAs per (kt,n) =============== */
    float o[16][4];
    #pragma unroll
    for (int n = 0; n < 16; n++) {
        o[n][0] = 0.f; o[n][1] = 0.f; o[n][2] = 0.f; o[n][3] = 0.f;
    }

    const uint32_t* Vh = (const uint32_t*)(smc + ATV_HI);
    const uint32_t* Vl = (const uint32_t*)(smc + ATV_LO);

    #pragma unroll 1
    for (int kt = 0; kt < 8; kt++) {
        const int k0 = kt * 16;
        const char* pah = smc + ATK_HI + (r0 + lg)*272 + (k0 + 2*la)*2;
        const char* pal = smc + ATK_LO + (r0 + lg)*272 + (k0 + 2*la)*2;
        uint32_t ah0 = *(const uint32_t*)(pah);
        uint32_t ah1 = *(const uint32_t*)(pah + 8*272);
        uint32_t ah2 = *(const uint32_t*)(pah + 16);
        uint32_t ah3 = *(const uint32_t*)(pah + 8*272 + 16);
        uint32_t al0 = *(const uint32_t*)(pal);
        uint32_t al1 = *(const uint32_t*)(pal + 8*272);
        uint32_t al2 = *(const uint32_t*)(pal + 16);
        uint32_t al3 = *(const uint32_t*)(pal + 8*272 + 16);

        const int w0 = (kt*8 + la) * 132;       /* key-pair row = k0/2 + la */
        #pragma unroll
        for (int n = 0; n < 16; n++) {
            uint32_t bh0 = Vh[w0 + n*8 + lg];
            uint32_t bh1 = Vh[w0 + 4*132 + n*8 + lg];
            uint32_t bl0 = Vl[w0 + n*8 + lg];
            uint32_t bl1 = Vl[w0 + 4*132 + n*8 + lg];
            mma_bf16(o[n], ah0, ah1, ah2, ah3, bh0, bh1);
            mma_bf16(o[n], ah0, ah1, ah2, ah3, bl0, bl1);
            mma_bf16(o[n], al0, al1, al2, al3, bh0, bh1);
        }
    }

    /* ---- stage O through the dead Q region for coalesced writes ---- */
    float* Os = (float*)smc;                    /* [128][132] fp32 */
    #pragma unroll
    for (int n = 0; n < 16; n++) {
        *(float2*)&Os[ra*132 + n*8 + 2*la] = make_float2(o[n][0], o[n][1]);
        *(float2*)&Os[rb*132 + n*8 + 2*la] = make_float2(o[n][2], o[n][3]);
    }
    __syncthreads();
    for (int i = tid; i < 128*32; i += 256) {
        int r = i >> 5, c4 = (i & 31) << 2;
        *(float4*)&g_o[base + r*128 + c4] = *(float4*)&Os[r*132 + c4];
    }
}

/* ------------------------------------------------------------------ */
/* Phase 3: output projection, 2-MMA: rna(W) x (ohi + olo).            */
/* ------------------------------------------------------------------ */
#define P3_SMEM (2 * 64 * XP * 4)

__global__ void __launch_bounds__(256) proj_o_kernel(
    float* __restrict__ out,
    const float* __restrict__ wo, const float* __restrict__ bo)
{
    extern __shared__ float sm[];
    float* ohi = sm;
    float* olo = sm + 64*XP;

    const int tid  = threadIdx.x;
    const int lane = tid & 31;
    const int wrp  = tid >> 5;
    const int lg   = lane >> 2;
    const int la   = lane & 3;
    const int s0   = blockIdx.x * 128;

    for (int i = tid; i < 64*32; i += 256) {
        int r = i >> 5, c4 = (i & 31) << 2;
        float4 v = *(const float4*)&g_o[(size_t)r * S_TOT + s0 + c4];
        *(float4*)&ohi[r*XP + c4] = v;
        *(float4*)&olo[r*XP + c4] =
            make_float4(tf32_lo(v.x), tf32_lo(v.y), tf32_lo(v.z), tf32_lo(v.w));
    }

    const int c0 = (wrp & 3) * 16;
    const int hf = wrp >> 2;

    uint32_t ah[32];
    #pragma unroll
    for (int ks = 0; ks < 8; ks++) {
        int k1 = ks*8 + la;
        ah[ks*4+0] = f2tf32_rna(wo[(c0 + lg    )*64 + k1    ]);
        ah[ks*4+1] = f2tf32_rna(wo[(c0 + lg + 8)*64 + k1    ]);
        ah[ks*4+2] = f2tf32_rna(wo[(c0 + lg    )*64 + k1 + 4]);
        ah[ks*4+3] = f2tf32_rna(wo[(c0 + lg + 8)*64 + k1 + 4]);
    }
    const float b1 = bo[c0 + lg];
    const float b2 = bo[c0 + lg + 8];

    __syncthreads();

    float c[8][4];
    #pragma unroll
    for (int n = 0; n < 8; n++) {
        c[n][0] = b1; c[n][1] = b1; c[n][2] = b2; c[n][3] = b2;
    }

    #pragma unroll 1
    for (int ks = 0; ks < 8; ks++) {
        const int kr0 = (ks*8 + la) * XP + hf*64 + lg;
        const int kr1 = kr0 + 4*XP;
        #pragma unroll
        for (int n = 0; n < 8; n++) {
            uint32_t bh0 = __float_as_uint(ohi[kr0 + n*8]);
            uint32_t bh1 = __float_as_uint(ohi[kr1 + n*8]);
            uint32_t bl0 = __float_as_uint(olo[kr0 + n*8]);
            uint32_t bl1 = __float_as_uint(olo[kr1 + n*8]);
            mma_tf32(c[n], ah[ks*4+0], ah[ks*4+1], ah[ks*4+2], ah[ks*4+3], bh0, bh1);
            mma_tf32(c[n], ah[ks*4+0], ah[ks*4+1], ah[ks*4+2], ah[ks*4+3], bl0, bl1);
        }
    }

    #pragma unroll
    for (int n = 0; n < 8; n++) {
        size_t col = (size_t)(s0 + hf*64 + n*8 + 2*la);
        *(float2*)&out[(size_t)(c0 + lg    )*S_TOT + col] = make_float2(c[n][0], c[n][1]);
        *(float2*)&out[(size_t)(c0 + lg + 8)*S_TOT + col] = make_float2(c[n][2], c[n][3]);
    }
}

/* ------------------------------------------------------------------ */
extern "C" void kernel_launch(void* const* d_in, const int* in_sizes, int n_in,
                              void* d_out, int out_size)
{
    const float* x  = (const float*)d_in[0];
    const float* wq = (const float*)d_in[1];
    const float* bq = (const float*)d_in[2];
    const float* wk = (const float*)d_in[3];
    const float* bk = (const float*)d_in[4];
    const float* wv = (const float*)d_in[5];
    const float* bv = (const float*)d_in[6];
    const float* wo = (const float*)d_in[7];
    const float* bo = (const float*)d_in[8];

    cudaFuncSetAttribute(qkv_kernel,    cudaFuncAttributeMaxDynamicSharedMemorySize, P1_SMEM);
    cudaFuncSetAttribute(attn_kernel,   cudaFuncAttributeMaxDynamicSharedMemorySize, AT_SMEM);
    cudaFuncSetAttribute(proj_o_kernel, cudaFuncAttributeMaxDynamicSharedMemorySize, P3_SMEM);

    qkv_kernel<<<S_TOT/128, 384, P1_SMEM>>>(x, wq, bq, wk, bk, wv, bv);
    attn_kernel<<<NSLAB, 256, AT_SMEM>>>();
    proj_o_kernel<<<S_TOT/128, 256, P3_SMEM>>>((float*)d_out, wo, bo);
}

// round 7
// speedup vs baseline: 1.5823x; 1.0150x over previous
#include <cuda_runtime.h>
#include <cuda_bf16.h>
#include <math.h>
#include <stdint.h>

#define CH    64
#define DDIM  48
#define WDIM  128
#define HDIM  128
#define S_TOT (DDIM*WDIM*HDIM)   /* 786432 spatial positions */
#define SLAB  (WDIM*HDIM)        /* 16384 per (c,d) slab     */
#define NSLAB (CH*DDIM)          /* 3072 attention problems  */

#define QSCALE 0.594603557501360533f   /* 8^(-1/4) */

/* q/k/v stored pre-split as bf16 hi/lo, row-major [c][s] */
__device__ unsigned short g_qh[CH * S_TOT], g_ql[CH * S_TOT];
__device__ unsigned short g_kh[CH * S_TOT], g_kl[CH * S_TOT];
__device__ unsigned short g_vh[CH * S_TOT], g_vl[CH * S_TOT];
__device__ float g_o[CH * S_TOT];

/* ---------------- mma.sync helpers (legal in compute_103 PTX) ---------- */
__device__ __forceinline__ void mma_bf16(float c[4],
                                         uint32_t a0, uint32_t a1, uint32_t a2, uint32_t a3,
                                         uint32_t b0, uint32_t b1) {
    asm volatile(
        "mma.sync.aligned.m16n8k16.row.col.f32.bf16.bf16.f32 "
        "{%0,%1,%2,%3}, {%4,%5,%6,%7}, {%8,%9}, {%0,%1,%2,%3};"
        : "+f"(c[0]), "+f"(c[1]), "+f"(c[2]), "+f"(c[3])
        : "r"(a0), "r"(a1), "r"(a2), "r"(a3), "r"(b0), "r"(b1));
}
/* 2-term bf16 Dekker split of a pair (x->low half, y->high half) */
__device__ __forceinline__ void bf16_split2(float x, float y, uint32_t& h, uint32_t& l) {
    __nv_bfloat162 hb = __floats2bfloat162_rn(x, y);
    float rx = x - __bfloat162float(hb.x);
    float ry = y - __bfloat162float(hb.y);
    __nv_bfloat162 lb = __floats2bfloat162_rn(rx, ry);
    h = *(uint32_t*)&hb;
    l = *(uint32_t*)&lb;
}

/* ------------------------------------------------------------------ */
/* Phase 1: fused QKV projection, bf16 m16n8k16, 3-term split.         */
/* x staged as k-pair packed bf16x2 hi/lo words: xp[kp][s], kp=k/2.    */
/* 384 thr = 12 warps: warp w -> tensor p=w>>2, M-tile (w&3)*16.       */
/* ------------------------------------------------------------------ */
#define XPW 136                           /* u32 pitch, 136%32=8 -> cf */
#define P1_SMEM (2 * 32 * XPW * 4)        /* 34816 B                   */

__global__ void __launch_bounds__(384) qkv_kernel(
    const float* __restrict__ x,
    const float* __restrict__ wq, const float* __restrict__ bq,
    const float* __restrict__ wk, const float* __restrict__ bk,
    const float* __restrict__ wv, const float* __restrict__ bv)
{
    extern __shared__ uint32_t smu[];
    uint32_t* xph = smu;              /* [32][136] */
    uint32_t* xpl = smu + 32*XPW;

    const int tid  = threadIdx.x;
    const int lane = tid & 31;
    const int wrp  = tid >> 5;
    const int lg   = lane >> 2;
    const int la   = lane & 3;
    const int s0   = blockIdx.x * 128;

    /* ---- stage x: pack channel-pairs, split to bf16 hi/lo ---- */
    for (int i = tid; i < 32*32; i += 384) {
        int kp = i >> 5, q4 = i & 31;
        int col0 = q4 * 4;
        float4 a = *(const float4*)&x[(size_t)(2*kp  ) * S_TOT + s0 + col0];
        float4 b = *(const float4*)&x[(size_t)(2*kp+1) * S_TOT + s0 + col0];
        uint4 wh, wl;
        bf16_split2(a.x, b.x, wh.x, wl.x);
        bf16_split2(a.y, b.y, wh.y, wl.y);
        bf16_split2(a.z, b.z, wh.z, wl.z);
        bf16_split2(a.w, b.w, wh.w, wl.w);
        *(uint4*)&xph[kp*XPW + col0] = wh;
        *(uint4*)&xpl[kp*XPW + col0] = wl;
    }

    /* ---- per-warp W fragments (bf16 hi/lo, registers) ---- */
    const int p  = wrp >> 2;                 /* 0=q 1=k 2=v */
    const int c0 = (wrp & 3) * 16;
    const float* W = (p == 0) ? wq : (p == 1) ? wk : wv;
    const float* B = (p == 0) ? bq : (p == 1) ? bk : bv;

    uint32_t ah[16], al[16];
    #pragma unroll
    for (int kt = 0; kt < 4; kt++) {
        int kk = kt*16 + 2*la;
        float2 w0 = *(const float2*)&W[(c0 + lg    )*64 + kk    ];
        float2 w1 = *(const float2*)&W[(c0 + lg + 8)*64 + kk    ];
        float2 w2 = *(const float2*)&W[(c0 + lg    )*64 + kk + 8];
        float2 w3 = *(const float2*)&W[(c0 + lg + 8)*64 + kk + 8];
        bf16_split2(w0.x, w0.y, ah[kt*4+0], al[kt*4+0]);
        bf16_split2(w1.x, w1.y, ah[kt*4+1], al[kt*4+1]);
        bf16_split2(w2.x, w2.y, ah[kt*4+2], al[kt*4+2]);
        bf16_split2(w3.x, w3.y, ah[kt*4+3], al[kt*4+3]);
    }
    const float b1 = B[c0 + lg];
    const float b2 = B[c0 + lg + 8];
    const float scale = (p == 0) ? QSCALE : 1.0f;
    unsigned short* gh = (p == 0) ? g_qh : (p == 1) ? g_kh : g_vh;
    unsigned short* gl = (p == 0) ? g_ql : (p == 1) ? g_kl : g_vl;

    __syncthreads();

    #pragma unroll 1
    for (int hf = 0; hf < 2; hf++) {
        float c[8][4];
        #pragma unroll
        for (int n = 0; n < 8; n++) {
            c[n][0] = b1; c[n][1] = b1; c[n][2] = b2; c[n][3] = b2;
        }

        #pragma unroll 1
        for (int kt = 0; kt < 4; kt++) {
            const int base0 = (8*kt + la)*XPW + hf*64 + lg;
            const int base1 = base0 + 4*XPW;
            #pragma unroll
            for (int n = 0; n < 8; n++) {
                uint32_t bh0 = xph[base0 + n*8];
                uint32_t bh1 = xph[base1 + n*8];
                uint32_t bl0 = xpl[base0 + n*8];
                uint32_t bl1 = xpl[base1 + n*8];
                mma_bf16(c[n], ah[kt*4+0], ah[kt*4+1], ah[kt*4+2], ah[kt*4+3], bh0, bh1);
                mma_bf16(c[n], ah[kt*4+0], ah[kt*4+1], ah[kt*4+2], ah[kt*4+3], bl0, bl1);
                mma_bf16(c[n], al[kt*4+0], al[kt*4+1], al[kt*4+2], al[kt*4+3], bh0, bh1);
            }
        }

        /* split results to bf16 hi/lo, store packed pairs (cols 2la,2la+1) */
        #pragma unroll
        for (int n = 0; n < 8; n++) {
            size_t col = (size_t)(s0 + hf*64 + n*8 + 2*la);
            size_t i1 = (size_t)(c0 + lg    )*S_TOT + col;
            size_t i2 = (size_t)(c0 + lg + 8)*S_TOT + col;
            uint32_t h, l;
            bf16_split2(c[n][0]*scale, c[n][1]*scale, h, l);
            *(uint32_t*)&gh[i1] = h;  *(uint32_t*)&gl[i1] = l;
            bf16_split2(c[n][2]*scale, c[n][3]*scale, h, l);
            *(uint32_t*)&gh[i2] = h;  *(uint32_t*)&gl[i2] = l;
        }
    }
}

/* ------------------------------------------------------------------ */
/* Phase 2: per-(c,d) attention, bf16 k16, copy-only staging.          */
/* smem (bytes): Qhi@0 Qlo@34816 Khi@69632 Klo@104448 (128 rows x      */
/* 272B), Vph@139264 Vpl@174080 (64 x 136 u32, key-pair packed).       */
/* ------------------------------------------------------------------ */
#define AQH 0
#define AQL 34816
#define AKH 69632
#define AKL 104448
#define AVH 139264
#define AVL 174080
#define AT_SMEM 208896

__global__ void __launch_bounds__(256) attn_kernel()
{
    extern __shared__ char smc[];
    const int tid  = threadIdx.x;
    const int lane = tid & 31;
    const int wrp  = tid >> 5;
    const int lg   = lane >> 2;
    const int la   = lane & 3;
    const size_t base = (size_t)blockIdx.x * SLAB;

    /* ---- Q/K: straight uint4 copies into padded rows ---- */
    for (int i = tid; i < 2048; i += 256) {
        int r = i >> 4, u = i & 15;
        const size_t gsrc = base + r*128 + u*8;
        const int    dst  = r*272 + u*16;
        *(uint4*)(smc + AQH + dst) = *(const uint4*)(g_qh + gsrc);
        *(uint4*)(smc + AQL + dst) = *(const uint4*)(g_ql + gsrc);
        *(uint4*)(smc + AKH + dst) = *(const uint4*)(g_kh + gsrc);
        *(uint4*)(smc + AKL + dst) = *(const uint4*)(g_kl + gsrc);
    }
    /* ---- V: byte_perm pair-packing (rows 2kp,2kp+1 interleave) ---- */
    uint32_t* Vph = (uint32_t*)(smc + AVH);
    uint32_t* Vpl = (uint32_t*)(smc + AVL);
    for (int i = tid; i < 1024; i += 256) {
        int kp = i >> 4, u = i & 15;
        int col0 = u * 8;
        uint4 e = *(const uint4*)(g_vh + base + (2*kp  )*128 + col0);
        uint4 o = *(const uint4*)(g_vh + base + (2*kp+1)*128 + col0);
        uint4 w0, w1;
        w0.x = __byte_perm(e.x, o.x, 0x5410);  w0.y = __byte_perm(e.x, o.x, 0x7632);
        w0.z = __byte_perm(e.y, o.y, 0x5410);  w0.w = __byte_perm(e.y, o.y, 0x7632);
        w1.x = __byte_perm(e.z, o.z, 0x5410);  w1.y = __byte_perm(e.z, o.z, 0x7632);
        w1.z = __byte_perm(e.w, o.w, 0x5410);  w1.w = __byte_perm(e.w, o.w, 0x7632);
        *(uint4*)&Vph[kp*136 + col0    ] = w0;
        *(uint4*)&Vph[kp*136 + col0 + 4] = w1;
        e = *(const uint4*)(g_vl + base + (2*kp  )*128 + col0);
        o = *(const uint4*)(g_vl + base + (2*kp+1)*128 + col0);
        w0.x = __byte_perm(e.x, o.x, 0x5410);  w0.y = __byte_perm(e.x, o.x, 0x7632);
        w0.z = __byte_perm(e.y, o.y, 0x5410);  w0.w = __byte_perm(e.y, o.y, 0x7632);
        w1.x = __byte_perm(e.z, o.z, 0x5410);  w1.y = __byte_perm(e.z, o.z, 0x7632);
        w1.z = __byte_perm(e.w, o.w, 0x5410);  w1.w = __byte_perm(e.w, o.w, 0x7632);
        *(uint4*)&Vpl[kp*136 + col0    ] = w0;
        *(uint4*)&Vpl[kp*136 + col0 + 4] = w1;
    }
    __syncthreads();

    const int r0 = wrp * 16;
    const int ra = r0 + lg, rb = ra + 8;

    /* ================= S = Q K^T : 3 bf16 MMAs per (kt,n) ============ */
    float s[16][4];
    #pragma unroll
    for (int n = 0; n < 16; n++) {
        s[n][0] = 0.f; s[n][1] = 0.f; s[n][2] = 0.f; s[n][3] = 0.f;
    }

    #pragma unroll 1
    for (int kt = 0; kt < 8; kt++) {
        const int k0 = kt * 16;
        const char* qh = smc + AQH + (r0 + lg)*272 + (k0 + 2*la)*2;
        const char* ql = smc + AQL + (r0 + lg)*272 + (k0 + 2*la)*2;
        uint32_t ah0 = *(const uint32_t*)(qh);
        uint32_t ah1 = *(const uint32_t*)(qh + 8*272);
        uint32_t ah2 = *(const uint32_t*)(qh + 16);
        uint32_t ah3 = *(const uint32_t*)(qh + 8*272 + 16);
        uint32_t al0 = *(const uint32_t*)(ql);
        uint32_t al1 = *(const uint32_t*)(ql + 8*272);
        uint32_t al2 = *(const uint32_t*)(ql + 16);
        uint32_t al3 = *(const uint32_t*)(ql + 8*272 + 16);

        #pragma unroll
        for (int n = 0; n < 16; n++) {
            const char* kh = smc + AKH + (n*8 + lg)*272 + (k0 + 2*la)*2;
            const char* kl = smc + AKL + (n*8 + lg)*272 + (k0 + 2*la)*2;
            uint32_t bh0 = *(const uint32_t*)(kh);
            uint32_t bh1 = *(const uint32_t*)(kh + 16);
            uint32_t bl0 = *(const uint32_t*)(kl);
            uint32_t bl1 = *(const uint32_t*)(kl + 16);
            mma_bf16(s[n], ah0, ah1, ah2, ah3, bh0, bh1);
            mma_bf16(s[n], ah0, ah1, ah2, ah3, bl0, bl1);
            mma_bf16(s[n], al0, al1, al2, al3, bh0, bh1);
        }
    }

    /* ================= row softmax ==================================== */
    float ia, ib;
    {
        float ma = -1e30f, mb = -1e30f;
        #pragma unroll
        for (int n = 0; n < 16; n++) {
            ma = fmaxf(ma, fmaxf(s[n][0], s[n][1]));
            mb = fmaxf(mb, fmaxf(s[n][2], s[n][3]));
        }
        ma = fmaxf(ma, __shfl_xor_sync(0xffffffffu, ma, 1));
        ma = fmaxf(ma, __shfl_xor_sync(0xffffffffu, ma, 2));
        mb = fmaxf(mb, __shfl_xor_sync(0xffffffffu, mb, 1));
        mb = fmaxf(mb, __shfl_xor_sync(0xffffffffu, mb, 2));

        float sa = 0.f, sb = 0.f;
        #pragma unroll
        for (int n = 0; n < 16; n++) {
            s[n][0] = __expf(s[n][0] - ma);  sa += s[n][0];
            s[n][1] = __expf(s[n][1] - ma);  sa += s[n][1];
            s[n][2] = __expf(s[n][2] - mb);  sb += s[n][2];
            s[n][3] = __expf(s[n][3] - mb);  sb += s[n][3];
        }
        sa += __shfl_xor_sync(0xffffffffu, sa, 1);
        sa += __shfl_xor_sync(0xffffffffu, sa, 2);
        sb += __shfl_xor_sync(0xffffffffu, sb, 1);
        sb += __shfl_xor_sync(0xffffffffu, sb, 2);
        ia = 1.0f / sa;  ib = 1.0f / sb;
    }

    /* all warps done reading K before A overwrites it */
    __syncthreads();
    #pragma unroll
    for (int n = 0; n < 16; n++) {
        uint32_t h, l;
        bf16_split2(s[n][0] * ia, s[n][1] * ia, h, l);
        *(uint32_t*)(smc + AKH + ra*272 + (n*8 + 2*la)*2) = h;
        *(uint32_t*)(smc + AKL + ra*272 + (n*8 + 2*la)*2) = l;
        bf16_split2(s[n][2] * ib, s[n][3] * ib, h, l);
        *(uint32_t*)(smc + AKH + rb*272 + (n*8 + 2*la)*2) = h;
        *(uint32_t*)(smc + AKL + rb*272 + (n*8 + 2*la)*2) = l;
    }
    __syncwarp();

    /* ================= O = A V : 3 bf16 MMAs per (kt,n) =============== */
    float o[16][4];
    #pragma unroll
    for (int n = 0; n < 16; n++) {
        o[n][0] = 0.f; o[n][1] = 0.f; o[n][2] = 0.f; o[n][3] = 0.f;
    }

    #pragma unroll 1
    for (int kt = 0; kt < 8; kt++) {
        const int k0 = kt * 16;
        const char* pah = smc + AKH + (r0 + lg)*272 + (k0 + 2*la)*2;
        const char* pal = smc + AKL + (r0 + lg)*272 + (k0 + 2*la)*2;
        uint32_t ah0 = *(const uint32_t*)(pah);
        uint32_t ah1 = *(const uint32_t*)(pah + 8*272);
        uint32_t ah2 = *(const uint32_t*)(pah + 16);
        uint32_t ah3 = *(const uint32_t*)(pah + 8*272 + 16);
        uint32_t al0 = *(const uint32_t*)(pal);
        uint32_t al1 = *(const uint32_t*)(pal + 8*272);
        uint32_t al2 = *(const uint32_t*)(pal + 16);
        uint32_t al3 = *(const uint32_t*)(pal + 8*272 + 16);

        const int w0 = (kt*8 + la) * 136;
        #pragma unroll
        for (int n = 0; n < 16; n++) {
            uint32_t bh0 = Vph[w0 + n*8 + lg];
            uint32_t bh1 = Vph[w0 + 4*136 + n*8 + lg];
            uint32_t bl0 = Vpl[w0 + n*8 + lg];
            uint32_t bl1 = Vpl[w0 + 4*136 + n*8 + lg];
            mma_bf16(o[n], ah0, ah1, ah2, ah3, bh0, bh1);
            mma_bf16(o[n], ah0, ah1, ah2, ah3, bl0, bl1);
            mma_bf16(o[n], al0, al1, al2, al3, bh0, bh1);
        }
    }

    /* ---- stage O through dead Q region for coalesced fp32 writes ---- */
    float* Os = (float*)smc;                    /* [128][132] fp32 */
    #pragma unroll
    for (int n = 0; n < 16; n++) {
        *(float2*)&Os[ra*132 + n*8 + 2*la] = make_float2(o[n][0], o[n][1]);
        *(float2*)&Os[rb*132 + n*8 + 2*la] = make_float2(o[n][2], o[n][3]);
    }
    __syncthreads();
    for (int i = tid; i < 128*32; i += 256) {
        int r = i >> 5, c4 = (i & 31) << 2;
        *(float4*)&g_o[base + r*128 + c4] = *(float4*)&Os[r*132 + c4];
    }
}

/* ------------------------------------------------------------------ */
/* Phase 3: output projection, bf16 k16, 3-term split.                 */
/* ------------------------------------------------------------------ */
#define P3_SMEM (2 * 32 * XPW * 4)

__global__ void __launch_bounds__(256) proj_o_kernel(
    float* __restrict__ out,
    const float* __restrict__ wo, const float* __restrict__ bo)
{
    extern __shared__ uint32_t smu[];
    uint32_t* oph = smu;
    uint32_t* opl = smu + 32*XPW;

    const int tid  = threadIdx.x;
    const int lane = tid & 31;
    const int wrp  = tid >> 5;
    const int lg   = lane >> 2;
    const int la   = lane & 3;
    const int s0   = blockIdx.x * 128;

    for (int i = tid; i < 32*32; i += 256) {
        int kp = i >> 5, q4 = i & 31;
        int col0 = q4 * 4;
        float4 a = *(const float4*)&g_o[(size_t)(2*kp  ) * S_TOT + s0 + col0];
        float4 b = *(const float4*)&g_o[(size_t)(2*kp+1) * S_TOT + s0 + col0];
        uint4 wh, wl;
        bf16_split2(a.x, b.x, wh.x, wl.x);
        bf16_split2(a.y, b.y, wh.y, wl.y);
        bf16_split2(a.z, b.z, wh.z, wl.z);
        bf16_split2(a.w, b.w, wh.w, wl.w);
        *(uint4*)&oph[kp*XPW + col0] = wh;
        *(uint4*)&opl[kp*XPW + col0] = wl;
    }

    const int c0 = (wrp & 3) * 16;
    const int hf = wrp >> 2;

    uint32_t ah[16], al[16];
    #pragma unroll
    for (int kt = 0; kt < 4; kt++) {
        int kk = kt*16 + 2*la;
        float2 w0 = *(const float2*)&wo[(c0 + lg    )*64 + kk    ];
        float2 w1 = *(const float2*)&wo[(c0 + lg + 8)*64 + kk    ];
        float2 w2 = *(const float2*)&wo[(c0 + lg    )*64 + kk + 8];
        float2 w3 = *(const float2*)&wo[(c0 + lg + 8)*64 + kk + 8];
        bf16_split2(w0.x, w0.y, ah[kt*4+0], al[kt*4+0]);
        bf16_split2(w1.x, w1.y, ah[kt*4+1], al[kt*4+1]);
        bf16_split2(w2.x, w2.y, ah[kt*4+2], al[kt*4+2]);
        bf16_split2(w3.x, w3.y, ah[kt*4+3], al[kt*4+3]);
    }
    const float b1 = bo[c0 + lg];
    const float b2 = bo[c0 + lg + 8];

    __syncthreads();

    float c[8][4];
    #pragma unroll
    for (int n = 0; n < 8; n++) {
        c[n][0] = b1; c[n][1] = b1; c[n][2] = b2; c[n][3] = b2;
    }

    #pragma unroll 1
    for (int kt = 0; kt < 4; kt++) {
        const int base0 = (8*kt + la)*XPW + hf*64 + lg;
        const int base1 = base0 + 4*XPW;
        #pragma unroll
        for (int n = 0; n < 8; n++) {
            uint32_t bh0 = oph[base0 + n*8];
            uint32_t bh1 = oph[base1 + n*8];
            uint32_t bl0 = opl[base0 + n*8];
            uint32_t bl1 = opl[base1 + n*8];
            mma_bf16(c[n], ah[kt*4+0], ah[kt*4+1], ah[kt*4+2], ah[kt*4+3], bh0, bh1);
            mma_bf16(c[n], ah[kt*4+0], ah[kt*4+1], ah[kt*4+2], ah[kt*4+3], bl0, bl1);
            mma_bf16(c[n], al[kt*4+0], al[kt*4+1], al[kt*4+2], al[kt*4+3], bh0, bh1);
        }
    }

    #pragma unroll
    for (int n = 0; n < 8; n++) {
        size_t col = (size_t)(s0 + hf*64 + n*8 + 2*la);
        *(float2*)&out[(size_t)(c0 + lg    )*S_TOT + col] = make_float2(c[n][0], c[n][1]);
        *(float2*)&out[(size_t)(c0 + lg + 8)*S_TOT + col] = make_float2(c[n][2], c[n][3]);
    }
}

/* ------------------------------------------------------------------ */
extern "C" void kernel_launch(void* const* d_in, const int* in_sizes, int n_in,
                              void* d_out, int out_size)
{
    const float* x  = (const float*)d_in[0];
    const float* wq = (const float*)d_in[1];
    const float* bq = (const float*)d_in[2];
    const float* wk = (const float*)d_in[3];
    const float* bk = (const float*)d_in[4];
    const float* wv = (const float*)d_in[5];
    const float* bv = (const float*)d_in[6];
    const float* wo = (const float*)d_in[7];
    const float* bo = (const float*)d_in[8];

    cudaFuncSetAttribute(qkv_kernel,    cudaFuncAttributeMaxDynamicSharedMemorySize, P1_SMEM);
    cudaFuncSetAttribute(attn_kernel,   cudaFuncAttributeMaxDynamicSharedMemorySize, AT_SMEM);
    cudaFuncSetAttribute(proj_o_kernel, cudaFuncAttributeMaxDynamicSharedMemorySize, P3_SMEM);

    qkv_kernel<<<S_TOT/128, 384, P1_SMEM>>>(x, wq, bq, wk, bk, wv, bv);
    attn_kernel<<<NSLAB, 256, AT_SMEM>>>();
    proj_o_kernel<<<S_TOT/128, 256, P3_SMEM>>>((float*)d_out, wo, bo);
}

// round 8
// speedup vs baseline: 1.7901x; 1.1313x over previous
#include <cuda_runtime.h>
#include <cuda_bf16.h>
#include <math.h>
#include <stdint.h>

#define CH    64
#define DDIM  48
#define WDIM  128
#define HDIM  128
#define S_TOT (DDIM*WDIM*HDIM)   /* 786432 spatial positions */
#define SLAB  (WDIM*HDIM)        /* 16384 per (c,d) slab     */
#define NSLAB (CH*DDIM)          /* 3072 attention problems  */

#define QSCALE 0.594603557501360533f   /* 8^(-1/4) */

/* q/k/v as interleaved {bf16x2 hi-pair, bf16x2 lo-pair} per column pair */
__device__ uint2 g_qi[CH * S_TOT / 2];
__device__ uint2 g_ki[CH * S_TOT / 2];
__device__ uint2 g_vi[CH * S_TOT / 2];
__device__ float g_o[CH * S_TOT];

/* ---------------- mma.sync helpers (legal in compute_103 PTX) ---------- */
__device__ __forceinline__ void mma_bf16(float c[4],
                                         uint32_t a0, uint32_t a1, uint32_t a2, uint32_t a3,
                                         uint32_t b0, uint32_t b1) {
    asm volatile(
        "mma.sync.aligned.m16n8k16.row.col.f32.bf16.bf16.f32 "
        "{%0,%1,%2,%3}, {%4,%5,%6,%7}, {%8,%9}, {%0,%1,%2,%3};"
        : "+f"(c[0]), "+f"(c[1]), "+f"(c[2]), "+f"(c[3])
        : "r"(a0), "r"(a1), "r"(a2), "r"(a3), "r"(b0), "r"(b1));
}
/* 2-term bf16 Dekker split of a pair (x->low half, y->high half) */
__device__ __forceinline__ void bf16_split2(float x, float y, uint32_t& h, uint32_t& l) {
    __nv_bfloat162 hb = __floats2bfloat162_rn(x, y);
    float rx = x - __bfloat162float(hb.x);
    float ry = y - __bfloat162float(hb.y);
    __nv_bfloat162 lb = __floats2bfloat162_rn(rx, ry);
    h = *(uint32_t*)&hb;
    l = *(uint32_t*)&lb;
}

/* ------------------------------------------------------------------ */
/* Phase 1: fused QKV projection, bf16 m16n8k16, 3-term split.         */
/* 256 spatial per block. 384 thr = 12 warps: p = w>>2, mt = w&3.      */
/* ------------------------------------------------------------------ */
#define XPW 264                           /* u32 pitch: 264%32=8 -> cf */
#define P1_SMEM (2 * 32 * XPW * 4)        /* 67584 B                   */

__global__ void __launch_bounds__(384, 2) qkv_kernel(
    const float* __restrict__ x,
    const float* __restrict__ wq, const float* __restrict__ bq,
    const float* __restrict__ wk, const float* __restrict__ bk,
    const float* __restrict__ wv, const float* __restrict__ bv)
{
    extern __shared__ uint32_t smu[];
    uint32_t* xph = smu;              /* [32][264] bf16x2 hi */
    uint32_t* xpl = smu + 32*XPW;     /* [32][264] bf16x2 lo */

    const int tid  = threadIdx.x;
    const int lane = tid & 31;
    const int wrp  = tid >> 5;
    const int lg   = lane >> 2;
    const int la   = lane & 3;
    const int s0   = blockIdx.x * 256;

    /* ---- per-warp W fragments (issued early to hide latency) ---- */
    const int p  = wrp >> 2;                 /* 0=q 1=k 2=v */
    const int c0 = (wrp & 3) * 16;
    const float* W = (p == 0) ? wq : (p == 1) ? wk : wv;
    const float* B = (p == 0) ? bq : (p == 1) ? bk : bv;

    uint32_t ah[16], al[16];
    #pragma unroll
    for (int kt = 0; kt < 4; kt++) {
        int kk = kt*16 + 2*la;
        float2 w0 = *(const float2*)&W[(c0 + lg    )*64 + kk    ];
        float2 w1 = *(const float2*)&W[(c0 + lg + 8)*64 + kk    ];
        float2 w2 = *(const float2*)&W[(c0 + lg    )*64 + kk + 8];
        float2 w3 = *(const float2*)&W[(c0 + lg + 8)*64 + kk + 8];
        bf16_split2(w0.x, w0.y, ah[kt*4+0], al[kt*4+0]);
        bf16_split2(w1.x, w1.y, ah[kt*4+1], al[kt*4+1]);
        bf16_split2(w2.x, w2.y, ah[kt*4+2], al[kt*4+2]);
        bf16_split2(w3.x, w3.y, ah[kt*4+3], al[kt*4+3]);
    }
    const float b1 = B[c0 + lg];
    const float b2 = B[c0 + lg + 8];
    const float scale = (p == 0) ? QSCALE : 1.0f;
    uint2* gi = (p == 0) ? g_qi : (p == 1) ? g_ki : g_vi;

    /* ---- stage x: pack channel-pairs, split to bf16 hi/lo ---- */
    for (int i = tid; i < 32*64; i += 384) {
        int kp = i >> 6, q4 = i & 63;
        int col0 = q4 * 4;
        float4 a = *(const float4*)&x[(size_t)(2*kp  ) * S_TOT + s0 + col0];
        float4 b = *(const float4*)&x[(size_t)(2*kp+1) * S_TOT + s0 + col0];
        uint4 wh, wl;
        bf16_split2(a.x, b.x, wh.x, wl.x);
        bf16_split2(a.y, b.y, wh.y, wl.y);
        bf16_split2(a.z, b.z, wh.z, wl.z);
        bf16_split2(a.w, b.w, wh.w, wl.w);
        *(uint4*)&xph[kp*XPW + col0] = wh;
        *(uint4*)&xpl[kp*XPW + col0] = wl;
    }
    __syncthreads();

    /* ---- 4 column-quarters of 64 ---- */
    #pragma unroll 1
    for (int qt = 0; qt < 4; qt++) {
        float c[8][4];
        #pragma unroll
        for (int n = 0; n < 8; n++) {
            c[n][0] = b1; c[n][1] = b1; c[n][2] = b2; c[n][3] = b2;
        }

        #pragma unroll 1
        for (int kt = 0; kt < 4; kt++) {
            const int base0 = (8*kt + la)*XPW + qt*64 + lg;
            const int base1 = base0 + 4*XPW;
            #pragma unroll
            for (int n = 0; n < 8; n++) {
                uint32_t bh0 = xph[base0 + n*8];
                uint32_t bh1 = xph[base1 + n*8];
                uint32_t bl0 = xpl[base0 + n*8];
                uint32_t bl1 = xpl[base1 + n*8];
                mma_bf16(c[n], ah[kt*4+0], ah[kt*4+1], ah[kt*4+2], ah[kt*4+3], bh0, bh1);
                mma_bf16(c[n], ah[kt*4+0], ah[kt*4+1], ah[kt*4+2], ah[kt*4+3], bl0, bl1);
                mma_bf16(c[n], al[kt*4+0], al[kt*4+1], al[kt*4+2], al[kt*4+3], bh0, bh1);
            }
        }

        /* epilogue: interleaved {hi,lo} uint2 stores (32B/row contiguous) */
        #pragma unroll
        for (int n = 0; n < 8; n++) {
            const int scol = ((s0 + qt*64 + n*8) >> 1) + la;
            uint32_t h, l;
            bf16_split2(c[n][0]*scale, c[n][1]*scale, h, l);
            gi[(size_t)(c0 + lg    )*(S_TOT/2) + scol] = make_uint2(h, l);
            bf16_split2(c[n][2]*scale, c[n][3]*scale, h, l);
            gi[(size_t)(c0 + lg + 8)*(S_TOT/2) + scol] = make_uint2(h, l);
        }
    }
}

/* ------------------------------------------------------------------ */
/* Phase 2: per-(c,d) attention, bf16 k16 (core validated in R7).      */
/* smem (bytes): Qhi@0 Qlo@34816 Khi@69632 Klo@104448 (128 x 272B),    */
/* Vph@139264 Vpl@174080 (64 x 136 u32, key-pair packed).              */
/* ------------------------------------------------------------------ */
#define AQH 0
#define AQL 34816
#define AKH 69632
#define AKL 104448
#define AVH 139264
#define AVL 174080
#define AT_SMEM 208896

__global__ void __launch_bounds__(256) attn_kernel()
{
    extern __shared__ char smc[];
    const int tid  = threadIdx.x;
    const int lane = tid & 31;
    const int wrp  = tid >> 5;
    const int lg   = lane >> 2;
    const int la   = lane & 3;
    const size_t base = (size_t)blockIdx.x * SLAB;

    /* ---- Q/K: single uint4 stream each, de-interleave to hi/lo ---- */
    const uint4* Qi4 = (const uint4*)g_qi + (size_t)blockIdx.x * 4096;
    const uint4* Ki4 = (const uint4*)g_ki + (size_t)blockIdx.x * 4096;
    for (int i = tid; i < 4096; i += 256) {
        int r = i >> 5, u = i & 31;
        const int dst = r*272 + u*8;
        uint4 q4 = Qi4[i];
        *(uint2*)(smc + AQH + dst) = make_uint2(q4.x, q4.z);
        *(uint2*)(smc + AQL + dst) = make_uint2(q4.y, q4.w);
        uint4 k4 = Ki4[i];
        *(uint2*)(smc + AKH + dst) = make_uint2(k4.x, k4.z);
        *(uint2*)(smc + AKL + dst) = make_uint2(k4.y, k4.w);
    }
    /* ---- V: byte_perm key-pair packing from interleaved stream ---- */
    uint32_t* Vph = (uint32_t*)(smc + AVH);
    uint32_t* Vpl = (uint32_t*)(smc + AVL);
    const uint4* Vi4 = (const uint4*)g_vi + (size_t)blockIdx.x * 4096;
    for (int i = tid; i < 2048; i += 256) {
        int kp = i >> 5, u = i & 31;
        uint4 e = Vi4[(2*kp  )*32 + u];   /* {h01,l01,h23,l23} cols 4u.. */
        uint4 o = Vi4[(2*kp+1)*32 + u];
        uint4 wh, wl;
        wh.x = __byte_perm(e.x, o.x, 0x5410);  wh.y = __byte_perm(e.x, o.x, 0x7632);
        wh.z = __byte_perm(e.z, o.z, 0x5410);  wh.w = __byte_perm(e.z, o.z, 0x7632);
        wl.x = __byte_perm(e.y, o.y, 0x5410);  wl.y = __byte_perm(e.y, o.y, 0x7632);
        wl.z = __byte_perm(e.w, o.w, 0x5410);  wl.w = __byte_perm(e.w, o.w, 0x7632);
        *(uint4*)&Vph[kp*136 + u*4] = wh;
        *(uint4*)&Vpl[kp*136 + u*4] = wl;
    }
    __syncthreads();

    const int r0 = wrp * 16;
    const int ra = r0 + lg, rb = ra + 8;

    /* ================= S = Q K^T : 3 bf16 MMAs per (kt,n) ============ */
    float s[16][4];
    #pragma unroll
    for (int n = 0; n < 16; n++) {
        s[n][0] = 0.f; s[n][1] = 0.f; s[n][2] = 0.f; s[n][3] = 0.f;
    }

    #pragma unroll 1
    for (int kt = 0; kt < 8; kt++) {
        const int k0 = kt * 16;
        const char* qh = smc + AQH + (r0 + lg)*272 + (k0 + 2*la)*2;
        const char* ql = smc + AQL + (r0 + lg)*272 + (k0 + 2*la)*2;
        uint32_t ah0 = *(const uint32_t*)(qh);
        uint32_t ah1 = *(const uint32_t*)(qh + 8*272);
        uint32_t ah2 = *(const uint32_t*)(qh + 16);
        uint32_t ah3 = *(const uint32_t*)(qh + 8*272 + 16);
        uint32_t al0 = *(const uint32_t*)(ql);
        uint32_t al1 = *(const uint32_t*)(ql + 8*272);
        uint32_t al2 = *(const uint32_t*)(ql + 16);
        uint32_t al3 = *(const uint32_t*)(ql + 8*272 + 16);

        #pragma unroll
        for (int n = 0; n < 16; n++) {
            const char* kh = smc + AKH + (n*8 + lg)*272 + (k0 + 2*la)*2;
            const char* kl = smc + AKL + (n*8 + lg)*272 + (k0 + 2*la)*2;
            uint32_t bh0 = *(const uint32_t*)(kh);
            uint32_t bh1 = *(const uint32_t*)(kh + 16);
            uint32_t bl0 = *(const uint32_t*)(kl);
            uint32_t bl1 = *(const uint32_t*)(kl + 16);
            mma_bf16(s[n], ah0, ah1, ah2, ah3, bh0, bh1);
            mma_bf16(s[n], ah0, ah1, ah2, ah3, bl0, bl1);
            mma_bf16(s[n], al0, al1, al2, al3, bh0, bh1);
        }
    }

    /* ================= row softmax ==================================== */
    float ia, ib;
    {
        float ma = -1e30f, mb = -1e30f;
        #pragma unroll
        for (int n = 0; n < 16; n++) {
            ma = fmaxf(ma, fmaxf(s[n][0], s[n][1]));
            mb = fmaxf(mb, fmaxf(s[n][2], s[n][3]));
        }
        ma = fmaxf(ma, __shfl_xor_sync(0xffffffffu, ma, 1));
        ma = fmaxf(ma, __shfl_xor_sync(0xffffffffu, ma, 2));
        mb = fmaxf(mb, __shfl_xor_sync(0xffffffffu, mb, 1));
        mb = fmaxf(mb, __shfl_xor_sync(0xffffffffu, mb, 2));

        float sa = 0.f, sb = 0.f;
        #pragma unroll
        for (int n = 0; n < 16; n++) {
            s[n][0] = __expf(s[n][0] - ma);  sa += s[n][0];
            s[n][1] = __expf(s[n][1] - ma);  sa += s[n][1];
            s[n][2] = __expf(s[n][2] - mb);  sb += s[n][2];
            s[n][3] = __expf(s[n][3] - mb);  sb += s[n][3];
        }
        sa += __shfl_xor_sync(0xffffffffu, sa, 1);
        sa += __shfl_xor_sync(0xffffffffu, sa, 2);
        sb += __shfl_xor_sync(0xffffffffu, sb, 1);
        sb += __shfl_xor_sync(0xffffffffu, sb, 2);
        ia = 1.0f / sa;  ib = 1.0f / sb;
    }

    /* all warps done reading K before A overwrites it */
    __syncthreads();
    #pragma unroll
    for (int n = 0; n < 16; n++) {
        uint32_t h, l;
        bf16_split2(s[n][0] * ia, s[n][1] * ia, h, l);
        *(uint32_t*)(smc + AKH + ra*272 + (n*8 + 2*la)*2) = h;
        *(uint32_t*)(smc + AKL + ra*272 + (n*8 + 2*la)*2) = l;
        bf16_split2(s[n][2] * ib, s[n][3] * ib, h, l);
        *(uint32_t*)(smc + AKH + rb*272 + (n*8 + 2*la)*2) = h;
        *(uint32_t*)(smc + AKL + rb*272 + (n*8 + 2*la)*2) = l;
    }
    __syncwarp();

    /* ================= O = A V : 3 bf16 MMAs per (kt,n) =============== */
    float o[16][4];
    #pragma unroll
    for (int n = 0; n < 16; n++) {
        o[n][0] = 0.f; o[n][1] = 0.f; o[n][2] = 0.f; o[n][3] = 0.f;
    }

    #pragma unroll 1
    for (int kt = 0; kt < 8; kt++) {
        const int k0 = kt * 16;
        const char* pah = smc + AKH + (r0 + lg)*272 + (k0 + 2*la)*2;
        const char* pal = smc + AKL + (r0 + lg)*272 + (k0 + 2*la)*2;
        uint32_t ah0 = *(const uint32_t*)(pah);
        uint32_t ah1 = *(const uint32_t*)(pah + 8*272);
        uint32_t ah2 = *(const uint32_t*)(pah + 16);
        uint32_t ah3 = *(const uint32_t*)(pah + 8*272 + 16);
        uint32_t al0 = *(const uint32_t*)(pal);
        uint32_t al1 = *(const uint32_t*)(pal + 8*272);
        uint32_t al2 = *(const uint32_t*)(pal + 16);
        uint32_t al3 = *(const uint32_t*)(pal + 8*272 + 16);

        const int w0 = (kt*8 + la) * 136;
        #pragma unroll
        for (int n = 0; n < 16; n++) {
            uint32_t bh0 = Vph[w0 + n*8 + lg];
            uint32_t bh1 = Vph[w0 + 4*136 + n*8 + lg];
            uint32_t bl0 = Vpl[w0 + n*8 + lg];
            uint32_t bl1 = Vpl[w0 + 4*136 + n*8 + lg];
            mma_bf16(o[n], ah0, ah1, ah2, ah3, bh0, bh1);
            mma_bf16(o[n], ah0, ah1, ah2, ah3, bl0, bl1);
            mma_bf16(o[n], al0, al1, al2, al3, bh0, bh1);
        }
    }

    /* ---- stage O through dead Q region for coalesced fp32 writes ---- */
    float* Os = (float*)smc;                    /* [128][132] fp32 */
    #pragma unroll
    for (int n = 0; n < 16; n++) {
        *(float2*)&Os[ra*132 + n*8 + 2*la] = make_float2(o[n][0], o[n][1]);
        *(float2*)&Os[rb*132 + n*8 + 2*la] = make_float2(o[n][2], o[n][3]);
    }
    __syncthreads();
    for (int i = tid; i < 128*32; i += 256) {
        int r = i >> 5, c4 = (i & 31) << 2;
        *(float4*)&g_o[base + r*128 + c4] = *(float4*)&Os[r*132 + c4];
    }
}

/* ------------------------------------------------------------------ */
/* Phase 3: output projection, bf16 k16, 3-term split, 256-col tile.   */
/* 256 thr = 8 warps: mt = w&3, col-half = w>>2.                       */
/* ------------------------------------------------------------------ */
#define P3_SMEM (2 * 32 * XPW * 4)

__global__ void __launch_bounds__(256, 2) proj_o_kernel(
    float* __restrict__ out,
    const float* __restrict__ wo, const float* __restrict__ bo)
{
    extern __shared__ uint32_t smu[];
    uint32_t* oph = smu;
    uint32_t* opl = smu + 32*XPW;

    const int tid  = threadIdx.x;
    const int lane = tid & 31;
    const int wrp  = tid >> 5;
    const int lg   = lane >> 2;
    const int la   = lane & 3;
    const int s0   = blockIdx.x * 256;

    const int c0 = (wrp & 3) * 16;
    const int hf = wrp >> 2;             /* col half: 0 or 1 (128 cols) */

    uint32_t ah[16], al[16];
    #pragma unroll
    for (int kt = 0; kt < 4; kt++) {
        int kk = kt*16 + 2*la;
        float2 w0 = *(const float2*)&wo[(c0 + lg    )*64 + kk    ];
        float2 w1 = *(const float2*)&wo[(c0 + lg + 8)*64 + kk    ];
        float2 w2 = *(const float2*)&wo[(c0 + lg    )*64 + kk + 8];
        float2 w3 = *(const float2*)&wo[(c0 + lg + 8)*64 + kk + 8];
        bf16_split2(w0.x, w0.y, ah[kt*4+0], al[kt*4+0]);
        bf16_split2(w1.x, w1.y, ah[kt*4+1], al[kt*4+1]);
        bf16_split2(w2.x, w2.y, ah[kt*4+2], al[kt*4+2]);
        bf16_split2(w3.x, w3.y, ah[kt*4+3], al[kt*4+3]);
    }
    const float b1 = bo[c0 + lg];
    const float b2 = bo[c0 + lg + 8];

    for (int i = tid; i < 32*64; i += 256) {
        int kp = i >> 6, q4 = i & 63;
        int col0 = q4 * 4;
        float4 a = *(const float4*)&g_o[(size_t)(2*kp  ) * S_TOT + s0 + col0];
        float4 b = *(const float4*)&g_o[(size_t)(2*kp+1) * S_TOT + s0 + col0];
        uint4 wh, wl;
        bf16_split2(a.x, b.x, wh.x, wl.x);
        bf16_split2(a.y, b.y, wh.y, wl.y);
        bf16_split2(a.z, b.z, wh.z, wl.z);
        bf16_split2(a.w, b.w, wh.w, wl.w);
        *(uint4*)&oph[kp*XPW + col0] = wh;
        *(uint4*)&opl[kp*XPW + col0] = wl;
    }
    __syncthreads();

    #pragma unroll 1
    for (int qq = 0; qq < 2; qq++) {      /* two 64-col quarters in half */
        float c[8][4];
        #pragma unroll
        for (int n = 0; n < 8; n++) {
            c[n][0] = b1; c[n][1] = b1; c[n][2] = b2; c[n][3] = b2;
        }

        #pragma unroll 1
        for (int kt = 0; kt < 4; kt++) {
            const int base0 = (8*kt + la)*XPW + hf*128 + qq*64 + lg;
            const int base1 = base0 + 4*XPW;
            #pragma unroll
            for (int n = 0; n < 8; n++) {
                uint32_t bh0 = oph[base0 + n*8];
                uint32_t bh1 = oph[base1 + n*8];
                uint32_t bl0 = opl[base0 + n*8];
                uint32_t bl1 = opl[base1 + n*8];
                mma_bf16(c[n], ah[kt*4+0], ah[kt*4+1], ah[kt*4+2], ah[kt*4+3], bh0, bh1);
                mma_bf16(c[n], ah[kt*4+0], ah[kt*4+1], ah[kt*4+2], ah[kt*4+3], bl0, bl1);
                mma_bf16(c[n], al[kt*4+0], al[kt*4+1], al[kt*4+2], al[kt*4+3], bh0, bh1);
            }
        }

        #pragma unroll
        for (int n = 0; n < 8; n++) {
            size_t col = (size_t)(s0 + hf*128 + qq*64 + n*8 + 2*la);
            *(float2*)&out[(size_t)(c0 + lg    )*S_TOT + col] = make_float2(c[n][0], c[n][1]);
            *(float2*)&out[(size_t)(c0 + lg + 8)*S_TOT + col] = make_float2(c[n][2], c[n][3]);
        }
    }
}

/* ------------------------------------------------------------------ */
extern "C" void kernel_launch(void* const* d_in, const int* in_sizes, int n_in,
                              void* d_out, int out_size)
{
    const float* x  = (const float*)d_in[0];
    const float* wq = (const float*)d_in[1];
    const float* bq = (const float*)d_in[2];
    const float* wk = (const float*)d_in[3];
    const float* bk = (const float*)d_in[4];
    const float* wv = (const float*)d_in[5];
    const float* bv = (const float*)d_in[6];
    const float* wo = (const float*)d_in[7];
    const float* bo = (const float*)d_in[8];

    cudaFuncSetAttribute(qkv_kernel,    cudaFuncAttributeMaxDynamicSharedMemorySize, P1_SMEM);
    cudaFuncSetAttribute(attn_kernel,   cudaFuncAttributeMaxDynamicSharedMemorySize, AT_SMEM);
    cudaFuncSetAttribute(proj_o_kernel, cudaFuncAttributeMaxDynamicSharedMemorySize, P3_SMEM);

    qkv_kernel<<<S_TOT/256, 384, P1_SMEM>>>(x, wq, bq, wk, bk, wv, bv);
    attn_kernel<<<NSLAB, 256, AT_SMEM>>>();
    proj_o_kernel<<<S_TOT/256, 256, P3_SMEM>>>((float*)d_out, wo, bo);
}

// round 9
// speedup vs baseline: 2.0210x; 1.1290x over previous
#include <cuda_runtime.h>
#include <cuda_bf16.h>
#include <cuda_fp16.h>
#include <math.h>
#include <stdint.h>

#define CH    64
#define DDIM  48
#define WDIM  128
#define HDIM  128
#define S_TOT (DDIM*WDIM*HDIM)   /* 786432 spatial positions */
#define SLAB  (WDIM*HDIM)        /* 16384 per (c,d) slab     */
#define NSLAB (CH*DDIM)          /* 3072 attention problems  */

#define QSCALE 0.594603557501360533f   /* 8^(-1/4) */

/* q/k as interleaved {bf16x2 hi-pair, bf16x2 lo-pair}; v as fp16x2 pairs */
__device__ uint2    g_qi[CH * S_TOT / 2];
__device__ uint2    g_ki[CH * S_TOT / 2];
__device__ uint32_t g_vf[CH * S_TOT / 2];
__device__ float    g_o [CH * S_TOT];

/* ---------------- mma.sync helpers (legal in compute_103 PTX) ---------- */
__device__ __forceinline__ void mma_bf16(float c[4],
                                         uint32_t a0, uint32_t a1, uint32_t a2, uint32_t a3,
                                         uint32_t b0, uint32_t b1) {
    asm volatile(
        "mma.sync.aligned.m16n8k16.row.col.f32.bf16.bf16.f32 "
        "{%0,%1,%2,%3}, {%4,%5,%6,%7}, {%8,%9}, {%0,%1,%2,%3};"
        : "+f"(c[0]), "+f"(c[1]), "+f"(c[2]), "+f"(c[3])
        : "r"(a0), "r"(a1), "r"(a2), "r"(a3), "r"(b0), "r"(b1));
}
__device__ __forceinline__ void mma_f16(float c[4],
                                        uint32_t a0, uint32_t a1, uint32_t a2, uint32_t a3,
                                        uint32_t b0, uint32_t b1) {
    asm volatile(
        "mma.sync.aligned.m16n8k16.row.col.f32.f16.f16.f32 "
        "{%0,%1,%2,%3}, {%4,%5,%6,%7}, {%8,%9}, {%0,%1,%2,%3};"
        : "+f"(c[0]), "+f"(c[1]), "+f"(c[2]), "+f"(c[3])
        : "r"(a0), "r"(a1), "r"(a2), "r"(a3), "r"(b0), "r"(b1));
}
/* 2-term bf16 Dekker split of a pair (x->low half, y->high half) */
__device__ __forceinline__ void bf16_split2(float x, float y, uint32_t& h, uint32_t& l) {
    __nv_bfloat162 hb = __floats2bfloat162_rn(x, y);
    float rx = x - __bfloat162float(hb.x);
    float ry = y - __bfloat162float(hb.y);
    __nv_bfloat162 lb = __floats2bfloat162_rn(rx, ry);
    h = *(uint32_t*)&hb;
    l = *(uint32_t*)&lb;
}
__device__ __forceinline__ uint32_t f16pack(float x, float y) {
    __half2 h = __floats2half2_rn(x, y);
    return *(uint32_t*)&h;
}

/* ------------------------------------------------------------------ */
/* Phase 1: fused QKV projection, bf16 m16n8k16, 3-term split.         */
/* 256 spatial per block. 384 thr = 12 warps: p = w>>2, mt = w&3.      */
/* q/k emit interleaved hi/lo uint2; v emits fp16x2.                   */
/* ------------------------------------------------------------------ */
#define XPW 264                           /* u32 pitch: 264%32=8 -> cf */
#define P1_SMEM (2 * 32 * XPW * 4)        /* 67584 B                   */

__global__ void __launch_bounds__(384, 2) qkv_kernel(
    const float* __restrict__ x,
    const float* __restrict__ wq, const float* __restrict__ bq,
    const float* __restrict__ wk, const float* __restrict__ bk,
    const float* __restrict__ wv, const float* __restrict__ bv)
{
    extern __shared__ uint32_t smu[];
    uint32_t* xph = smu;              /* [32][264] bf16x2 hi */
    uint32_t* xpl = smu + 32*XPW;     /* [32][264] bf16x2 lo */

    const int tid  = threadIdx.x;
    const int lane = tid & 31;
    const int wrp  = tid >> 5;
    const int lg   = lane >> 2;
    const int la   = lane & 3;
    const int s0   = blockIdx.x * 256;

    const int p  = wrp >> 2;                 /* 0=q 1=k 2=v */
    const int c0 = (wrp & 3) * 16;
    const float* W = (p == 0) ? wq : (p == 1) ? wk : wv;
    const float* B = (p == 0) ? bq : (p == 1) ? bk : bv;

    uint32_t ah[16], al[16];
    #pragma unroll
    for (int kt = 0; kt < 4; kt++) {
        int kk = kt*16 + 2*la;
        float2 w0 = *(const float2*)&W[(c0 + lg    )*64 + kk    ];
        float2 w1 = *(const float2*)&W[(c0 + lg + 8)*64 + kk    ];
        float2 w2 = *(const float2*)&W[(c0 + lg    )*64 + kk + 8];
        float2 w3 = *(const float2*)&W[(c0 + lg + 8)*64 + kk + 8];
        bf16_split2(w0.x, w0.y, ah[kt*4+0], al[kt*4+0]);
        bf16_split2(w1.x, w1.y, ah[kt*4+1], al[kt*4+1]);
        bf16_split2(w2.x, w2.y, ah[kt*4+2], al[kt*4+2]);
        bf16_split2(w3.x, w3.y, ah[kt*4+3], al[kt*4+3]);
    }
    const float b1 = B[c0 + lg];
    const float b2 = B[c0 + lg + 8];
    const float scale = (p == 0) ? QSCALE : 1.0f;
    uint2* gi = (p == 0) ? g_qi : g_ki;      /* p==2 uses g_vf below */

    /* ---- stage x: pack channel-pairs, split to bf16 hi/lo ---- */
    for (int i = tid; i < 32*64; i += 384) {
        int kp = i >> 6, q4 = i & 63;
        int col0 = q4 * 4;
        float4 a = *(const float4*)&x[(size_t)(2*kp  ) * S_TOT + s0 + col0];
        float4 b = *(const float4*)&x[(size_t)(2*kp+1) * S_TOT + s0 + col0];
        uint4 wh, wl;
        bf16_split2(a.x, b.x, wh.x, wl.x);
        bf16_split2(a.y, b.y, wh.y, wl.y);
        bf16_split2(a.z, b.z, wh.z, wl.z);
        bf16_split2(a.w, b.w, wh.w, wl.w);
        *(uint4*)&xph[kp*XPW + col0] = wh;
        *(uint4*)&xpl[kp*XPW + col0] = wl;
    }
    __syncthreads();

    #pragma unroll 1
    for (int qt = 0; qt < 4; qt++) {
        float c[8][4];
        #pragma unroll
        for (int n = 0; n < 8; n++) {
            c[n][0] = b1; c[n][1] = b1; c[n][2] = b2; c[n][3] = b2;
        }

        #pragma unroll 1
        for (int kt = 0; kt < 4; kt++) {
            const int base0 = (8*kt + la)*XPW + qt*64 + lg;
            const int base1 = base0 + 4*XPW;
            #pragma unroll
            for (int n = 0; n < 8; n++) {
                uint32_t bh0 = xph[base0 + n*8];
                uint32_t bh1 = xph[base1 + n*8];
                uint32_t bl0 = xpl[base0 + n*8];
                uint32_t bl1 = xpl[base1 + n*8];
                mma_bf16(c[n], ah[kt*4+0], ah[kt*4+1], ah[kt*4+2], ah[kt*4+3], bh0, bh1);
                mma_bf16(c[n], ah[kt*4+0], ah[kt*4+1], ah[kt*4+2], ah[kt*4+3], bl0, bl1);
                mma_bf16(c[n], al[kt*4+0], al[kt*4+1], al[kt*4+2], al[kt*4+3], bh0, bh1);
            }
        }

        if (p < 2) {
            #pragma unroll
            for (int n = 0; n < 8; n++) {
                const int scol = ((s0 + qt*64 + n*8) >> 1) + la;
                uint32_t h, l;
                bf16_split2(c[n][0]*scale, c[n][1]*scale, h, l);
                gi[(size_t)(c0 + lg    )*(S_TOT/2) + scol] = make_uint2(h, l);
                bf16_split2(c[n][2]*scale, c[n][3]*scale, h, l);
                gi[(size_t)(c0 + lg + 8)*(S_TOT/2) + scol] = make_uint2(h, l);
            }
        } else {
            #pragma unroll
            for (int n = 0; n < 8; n++) {
                const int scol = ((s0 + qt*64 + n*8) >> 1) + la;
                g_vf[(size_t)(c0 + lg    )*(S_TOT/2) + scol] = f16pack(c[n][0], c[n][1]);
                g_vf[(size_t)(c0 + lg + 8)*(S_TOT/2) + scol] = f16pack(c[n][2], c[n][3]);
            }
        }
    }
}

/* ------------------------------------------------------------------ */
/* Phase 2: per-(c,d) attention. QK: bf16 3-term; AV: single fp16 MMA. */
/* smem (bytes): Qhi@0 Qlo@34816 Khi@69632 Klo@104448 (128 x 272B;     */
/* AKH reused for fp16 A), Vp@139264 (64 x 136 u32 key-pair fp16x2).   */
/* ------------------------------------------------------------------ */
#define AQH 0
#define AQL 34816
#define AKH 69632
#define AKL 104448
#define AVP 139264
#define AT_SMEM 174080

__global__ void __launch_bounds__(256) attn_kernel()
{
    extern __shared__ char smc[];
    const int tid  = threadIdx.x;
    const int lane = tid & 31;
    const int wrp  = tid >> 5;
    const int lg   = lane >> 2;
    const int la   = lane & 3;
    const size_t base = (size_t)blockIdx.x * SLAB;

    /* ---- Q/K: single uint4 stream each, de-interleave to hi/lo ---- */
    const uint4* Qi4 = (const uint4*)g_qi + (size_t)blockIdx.x * 4096;
    const uint4* Ki4 = (const uint4*)g_ki + (size_t)blockIdx.x * 4096;
    for (int i = tid; i < 4096; i += 256) {
        int r = i >> 5, u = i & 31;
        const int dst = r*272 + u*8;
        uint4 q4 = Qi4[i];
        *(uint2*)(smc + AQH + dst) = make_uint2(q4.x, q4.z);
        *(uint2*)(smc + AQL + dst) = make_uint2(q4.y, q4.w);
        uint4 k4 = Ki4[i];
        *(uint2*)(smc + AKH + dst) = make_uint2(k4.x, k4.z);
        *(uint2*)(smc + AKL + dst) = make_uint2(k4.y, k4.w);
    }
    /* ---- V: fp16 key-pair packing via byte_perm ---- */
    uint32_t* Vp = (uint32_t*)(smc + AVP);
    const uint4* Vf4 = (const uint4*)g_vf + (size_t)blockIdx.x * 2048;
    for (int i = tid; i < 1024; i += 256) {
        int kp = i >> 4, u = i & 15;          /* features 8u..8u+7 */
        uint4 e = Vf4[(2*kp  )*16 + u];
        uint4 o = Vf4[(2*kp+1)*16 + u];
        uint4 w0, w1;
        w0.x = __byte_perm(e.x, o.x, 0x5410);  w0.y = __byte_perm(e.x, o.x, 0x7632);
        w0.z = __byte_perm(e.y, o.y, 0x5410);  w0.w = __byte_perm(e.y, o.y, 0x7632);
        w1.x = __byte_perm(e.z, o.z, 0x5410);  w1.y = __byte_perm(e.z, o.z, 0x7632);
        w1.z = __byte_perm(e.w, o.w, 0x5410);  w1.w = __byte_perm(e.w, o.w, 0x7632);
        *(uint4*)&Vp[kp*136 + u*8    ] = w0;
        *(uint4*)&Vp[kp*136 + u*8 + 4] = w1;
    }
    __syncthreads();

    const int r0 = wrp * 16;
    const int ra = r0 + lg, rb = ra + 8;

    /* ================= S = Q K^T : 3 bf16 MMAs per (kt,n) ============ */
    float s[16][4];
    #pragma unroll
    for (int n = 0; n < 16; n++) {
        s[n][0] = 0.f; s[n][1] = 0.f; s[n][2] = 0.f; s[n][3] = 0.f;
    }

    #pragma unroll 1
    for (int kt = 0; kt < 8; kt++) {
        const int k0 = kt * 16;
        const char* qh = smc + AQH + (r0 + lg)*272 + (k0 + 2*la)*2;
        const char* ql = smc + AQL + (r0 + lg)*272 + (k0 + 2*la)*2;
        uint32_t ah0 = *(const uint32_t*)(qh);
        uint32_t ah1 = *(const uint32_t*)(qh + 8*272);
        uint32_t ah2 = *(const uint32_t*)(qh + 16);
        uint32_t ah3 = *(const uint32_t*)(qh + 8*272 + 16);
        uint32_t al0 = *(const uint32_t*)(ql);
        uint32_t al1 = *(const uint32_t*)(ql + 8*272);
        uint32_t al2 = *(const uint32_t*)(ql + 16);
        uint32_t al3 = *(const uint32_t*)(ql + 8*272 + 16);

        #pragma unroll
        for (int n = 0; n < 16; n++) {
            const char* kh = smc + AKH + (n*8 + lg)*272 + (k0 + 2*la)*2;
            const char* kl = smc + AKL + (n*8 + lg)*272 + (k0 + 2*la)*2;
            uint32_t bh0 = *(const uint32_t*)(kh);
            uint32_t bh1 = *(const uint32_t*)(kh + 16);
            uint32_t bl0 = *(const uint32_t*)(kl);
            uint32_t bl1 = *(const uint32_t*)(kl + 16);
            mma_bf16(s[n], ah0, ah1, ah2, ah3, bh0, bh1);
            mma_bf16(s[n], ah0, ah1, ah2, ah3, bl0, bl1);
            mma_bf16(s[n], al0, al1, al2, al3, bh0, bh1);
        }
    }

    /* ================= row softmax ==================================== */
    float ia, ib;
    {
        float ma = -1e30f, mb = -1e30f;
        #pragma unroll
        for (int n = 0; n < 16; n++) {
            ma = fmaxf(ma, fmaxf(s[n][0], s[n][1]));
            mb = fmaxf(mb, fmaxf(s[n][2], s[n][3]));
        }
        ma = fmaxf(ma, __shfl_xor_sync(0xffffffffu, ma, 1));
        ma = fmaxf(ma, __shfl_xor_sync(0xffffffffu, ma, 2));
        mb = fmaxf(mb, __shfl_xor_sync(0xffffffffu, mb, 1));
        mb = fmaxf(mb, __shfl_xor_sync(0xffffffffu, mb, 2));

        float sa = 0.f, sb = 0.f;
        #pragma unroll
        for (int n = 0; n < 16; n++) {
            s[n][0] = __expf(s[n][0] - ma);  sa += s[n][0];
            s[n][1] = __expf(s[n][1] - ma);  sa += s[n][1];
            s[n][2] = __expf(s[n][2] - mb);  sb += s[n][2];
            s[n][3] = __expf(s[n][3] - mb);  sb += s[n][3];
        }
        sa += __shfl_xor_sync(0xffffffffu, sa, 1);
        sa += __shfl_xor_sync(0xffffffffu, sa, 2);
        sb += __shfl_xor_sync(0xffffffffu, sb, 1);
        sb += __shfl_xor_sync(0xffffffffu, sb, 2);
        ia = 1.0f / sa;  ib = 1.0f / sb;
    }

    /* all warps done reading K before A (fp16) overwrites it */
    __syncthreads();
    #pragma unroll
    for (int n = 0; n < 16; n++) {
        *(uint32_t*)(smc + AKH + ra*272 + (n*8 + 2*la)*2) =
            f16pack(s[n][0] * ia, s[n][1] * ia);
        *(uint32_t*)(smc + AKH + rb*272 + (n*8 + 2*la)*2) =
            f16pack(s[n][2] * ib, s[n][3] * ib);
    }
    __syncwarp();

    /* ================= O = A V : single fp16 MMA per (kt,n) =========== */
    float o[16][4];
    #pragma unroll
    for (int n = 0; n < 16; n++) {
        o[n][0] = 0.f; o[n][1] = 0.f; o[n][2] = 0.f; o[n][3] = 0.f;
    }

    #pragma unroll 1
    for (int kt = 0; kt < 8; kt++) {
        const int k0 = kt * 16;
        const char* pa = smc + AKH + (r0 + lg)*272 + (k0 + 2*la)*2;
        uint32_t a0 = *(const uint32_t*)(pa);
        uint32_t a1 = *(const uint32_t*)(pa + 8*272);
        uint32_t a2 = *(const uint32_t*)(pa + 16);
        uint32_t a3 = *(const uint32_t*)(pa + 8*272 + 16);

        const int w0 = (kt*8 + la) * 136;
        #pragma unroll
        for (int n = 0; n < 16; n++) {
            uint32_t b0 = Vp[w0 + n*8 + lg];
            uint32_t b1 = Vp[w0 + 4*136 + n*8 + lg];
            mma_f16(o[n], a0, a1, a2, a3, b0, b1);
        }
    }

    /* ---- stage O through dead Q region for coalesced fp32 writes ---- */
    float* Os = (float*)smc;                    /* [128][132] fp32 */
    #pragma unroll
    for (int n = 0; n < 16; n++) {
        *(float2*)&Os[ra*132 + n*8 + 2*la] = make_float2(o[n][0], o[n][1]);
        *(float2*)&Os[rb*132 + n*8 + 2*la] = make_float2(o[n][2], o[n][3]);
    }
    __syncthreads();
    for (int i = tid; i < 128*32; i += 256) {
        int r = i >> 5, c4 = (i & 31) << 2;
        *(float4*)&g_o[base + r*128 + c4] = *(float4*)&Os[r*132 + c4];
    }
}

/* ------------------------------------------------------------------ */
/* Phase 3: output projection, bf16 k16, 3-term split, 256-col tile.   */
/* ------------------------------------------------------------------ */
#define P3_SMEM (2 * 32 * XPW * 4)

__global__ void __launch_bounds__(256, 2) proj_o_kernel(
    float* __restrict__ out,
    const float* __restrict__ wo, const float* __restrict__ bo)
{
    extern __shared__ uint32_t smu[];
    uint32_t* oph = smu;
    uint32_t* opl = smu + 32*XPW;

    const int tid  = threadIdx.x;
    const int lane = tid & 31;
    const int wrp  = tid >> 5;
    const int lg   = lane >> 2;
    const int la   = lane & 3;
    const int s0   = blockIdx.x * 256;

    const int c0 = (wrp & 3) * 16;
    const int hf = wrp >> 2;

    uint32_t ah[16], al[16];
    #pragma unroll
    for (int kt = 0; kt < 4; kt++) {
        int kk = kt*16 + 2*la;
        float2 w0 = *(const float2*)&wo[(c0 + lg    )*64 + kk    ];
        float2 w1 = *(const float2*)&wo[(c0 + lg + 8)*64 + kk    ];
        float2 w2 = *(const float2*)&wo[(c0 + lg    )*64 + kk + 8];
        float2 w3 = *(const float2*)&wo[(c0 + lg + 8)*64 + kk + 8];
        bf16_split2(w0.x, w0.y, ah[kt*4+0], al[kt*4+0]);
        bf16_split2(w1.x, w1.y, ah[kt*4+1], al[kt*4+1]);
        bf16_split2(w2.x, w2.y, ah[kt*4+2], al[kt*4+2]);
        bf16_split2(w3.x, w3.y, ah[kt*4+3], al[kt*4+3]);
    }
    const float b1 = bo[c0 + lg];
    const float b2 = bo[c0 + lg + 8];

    for (int i = tid; i < 32*64; i += 256) {
        int kp = i >> 6, q4 = i & 63;
        int col0 = q4 * 4;
        float4 a = *(const float4*)&g_o[(size_t)(2*kp  ) * S_TOT + s0 + col0];
        float4 b = *(const float4*)&g_o[(size_t)(2*kp+1) * S_TOT + s0 + col0];
        uint4 wh, wl;
        bf16_split2(a.x, b.x, wh.x, wl.x);
        bf16_split2(a.y, b.y, wh.y, wl.y);
        bf16_split2(a.z, b.z, wh.z, wl.z);
        bf16_split2(a.w, b.w, wh.w, wl.w);
        *(uint4*)&oph[kp*XPW + col0] = wh;
        *(uint4*)&opl[kp*XPW + col0] = wl;
    }
    __syncthreads();

    #pragma unroll 1
    for (int qq = 0; qq < 2; qq++) {
        float c[8][4];
        #pragma unroll
        for (int n = 0; n < 8; n++) {
            c[n][0] = b1; c[n][1] = b1; c[n][2] = b2; c[n][3] = b2;
        }

        #pragma unroll 1
        for (int kt = 0; kt < 4; kt++) {
            const int base0 = (8*kt + la)*XPW + hf*128 + qq*64 + lg;
            const int base1 = base0 + 4*XPW;
            #pragma unroll
            for (int n = 0; n < 8; n++) {
                uint32_t bh0 = oph[base0 + n*8];
                uint32_t bh1 = oph[base1 + n*8];
                uint32_t bl0 = opl[base0 + n*8];
                uint32_t bl1 = opl[base1 + n*8];
                mma_bf16(c[n], ah[kt*4+0], ah[kt*4+1], ah[kt*4+2], ah[kt*4+3], bh0, bh1);
                mma_bf16(c[n], ah[kt*4+0], ah[kt*4+1], ah[kt*4+2], ah[kt*4+3], bl0, bl1);
                mma_bf16(c[n], al[kt*4+0], al[kt*4+1], al[kt*4+2], al[kt*4+3], bh0, bh1);
            }
        }

        #pragma unroll
        for (int n = 0; n < 8; n++) {
            size_t col = (size_t)(s0 + hf*128 + qq*64 + n*8 + 2*la);
            *(float2*)&out[(size_t)(c0 + lg    )*S_TOT + col] = make_float2(c[n][0], c[n][1]);
            *(float2*)&out[(size_t)(c0 + lg + 8)*S_TOT + col] = make_float2(c[n][2], c[n][3]);
        }
    }
}

/* ------------------------------------------------------------------ */
extern "C" void kernel_launch(void* const* d_in, const int* in_sizes, int n_in,
                              void* d_out, int out_size)
{
    const float* x  = (const float*)d_in[0];
    const float* wq = (const float*)d_in[1];
    const float* bq = (const float*)d_in[2];
    const float* wk = (const float*)d_in[3];
    const float* bk = (const float*)d_in[4];
    const float* wv = (const float*)d_in[5];
    const float* bv = (const float*)d_in[6];
    const float* wo = (const float*)d_in[7];
    const float* bo = (const float*)d_in[8];

    cudaFuncSetAttribute(qkv_kernel,    cudaFuncAttributeMaxDynamicSharedMemorySize, P1_SMEM);
    cudaFuncSetAttribute(attn_kernel,   cudaFuncAttributeMaxDynamicSharedMemorySize, AT_SMEM);
    cudaFuncSetAttribute(proj_o_kernel, cudaFuncAttributeMaxDynamicSharedMemorySize, P3_SMEM);

    qkv_kernel<<<S_TOT/256, 384, P1_SMEM>>>(x, wq, bq, wk, bk, wv, bv);
    attn_kernel<<<NSLAB, 256, AT_SMEM>>>();
    proj_o_kernel<<<S_TOT/256, 256, P3_SMEM>>>((float*)d_out, wo, bo);
}

// round 10
// speedup vs baseline: 2.5167x; 1.2453x over previous
#include <cuda_runtime.h>
#include <cuda_bf16.h>
#include <cuda_fp16.h>
#include <math.h>
#include <stdint.h>

#define CH    64
#define DDIM  48
#define WDIM  128
#define HDIM  128
#define S_TOT (DDIM*WDIM*HDIM)   /* 786432 spatial positions */
#define SLAB  (WDIM*HDIM)        /* 16384 per (c,d) slab     */
#define NSLAB (CH*DDIM)          /* 3072 attention problems  */

#define QSCALE 0.594603557501360533f   /* 8^(-1/4) */

/* q/k as interleaved {bf16x2 hi-pair, bf16x2 lo-pair}; v as fp16x2 pairs */
__device__ uint2    g_qi[CH * S_TOT / 2];
__device__ uint2    g_ki[CH * S_TOT / 2];
__device__ uint32_t g_vf[CH * S_TOT / 2];
__device__ float    g_o [CH * S_TOT];

/* ---------------- mma.sync helpers (legal in compute_103 PTX) ---------- */
__device__ __forceinline__ void mma_bf16(float c[4],
                                         uint32_t a0, uint32_t a1, uint32_t a2, uint32_t a3,
                                         uint32_t b0, uint32_t b1) {
    asm volatile(
        "mma.sync.aligned.m16n8k16.row.col.f32.bf16.bf16.f32 "
        "{%0,%1,%2,%3}, {%4,%5,%6,%7}, {%8,%9}, {%0,%1,%2,%3};"
        : "+f"(c[0]), "+f"(c[1]), "+f"(c[2]), "+f"(c[3])
        : "r"(a0), "r"(a1), "r"(a2), "r"(a3), "r"(b0), "r"(b1));
}
__device__ __forceinline__ void mma_f16(float c[4],
                                        uint32_t a0, uint32_t a1, uint32_t a2, uint32_t a3,
                                        uint32_t b0, uint32_t b1) {
    asm volatile(
        "mma.sync.aligned.m16n8k16.row.col.f32.f16.f16.f32 "
        "{%0,%1,%2,%3}, {%4,%5,%6,%7}, {%8,%9}, {%0,%1,%2,%3};"
        : "+f"(c[0]), "+f"(c[1]), "+f"(c[2]), "+f"(c[3])
        : "r"(a0), "r"(a1), "r"(a2), "r"(a3), "r"(b0), "r"(b1));
}
/* 2-term bf16 Dekker split of a pair (x->low half, y->high half) */
__device__ __forceinline__ void bf16_split2(float x, float y, uint32_t& h, uint32_t& l) {
    __nv_bfloat162 hb = __floats2bfloat162_rn(x, y);
    float rx = x - __bfloat162float(hb.x);
    float ry = y - __bfloat162float(hb.y);
    __nv_bfloat162 lb = __floats2bfloat162_rn(rx, ry);
    h = *(uint32_t*)&hb;
    l = *(uint32_t*)&lb;
}
__device__ __forceinline__ uint32_t f16pack(float x, float y) {
    __half2 h = __floats2half2_rn(x, y);
    return *(uint32_t*)&h;
}

/* ------------------------------------------------------------------ */
/* Phase 1: fused QKV projection, bf16 m16n8k16, 3-term split.         */
/* x staged as interleaved uint2 {hi,lo} per channel-pair word.        */
/* ------------------------------------------------------------------ */
#define XP2 268                           /* uint2 pitch (bank-checked) */
#define P1_SMEM (32 * XP2 * 8)            /* 68608 B                    */

__global__ void __launch_bounds__(384, 2) qkv_kernel(
    const float* __restrict__ x,
    const float* __restrict__ wq, const float* __restrict__ bq,
    const float* __restrict__ wk, const float* __restrict__ bk,
    const float* __restrict__ wv, const float* __restrict__ bv)
{
    extern __shared__ uint2 xs[];          /* [32][268] {hi,lo} */

    const int tid  = threadIdx.x;
    const int lane = tid & 31;
    const int wrp  = tid >> 5;
    const int lg   = lane >> 2;
    const int la   = lane & 3;
    const int s0   = blockIdx.x * 256;

    const int p  = wrp >> 2;                 /* 0=q 1=k 2=v */
    const int c0 = (wrp & 3) * 16;
    const float* W = (p == 0) ? wq : (p == 1) ? wk : wv;
    const float* B = (p == 0) ? bq : (p == 1) ? bk : bv;

    uint32_t ah[16], al[16];
    #pragma unroll
    for (int kt = 0; kt < 4; kt++) {
        int kk = kt*16 + 2*la;
        float2 w0 = *(const float2*)&W[(c0 + lg    )*64 + kk    ];
        float2 w1 = *(const float2*)&W[(c0 + lg + 8)*64 + kk    ];
        float2 w2 = *(const float2*)&W[(c0 + lg    )*64 + kk + 8];
        float2 w3 = *(const float2*)&W[(c0 + lg + 8)*64 + kk + 8];
        bf16_split2(w0.x, w0.y, ah[kt*4+0], al[kt*4+0]);
        bf16_split2(w1.x, w1.y, ah[kt*4+1], al[kt*4+1]);
        bf16_split2(w2.x, w2.y, ah[kt*4+2], al[kt*4+2]);
        bf16_split2(w3.x, w3.y, ah[kt*4+3], al[kt*4+3]);
    }
    const float b1 = B[c0 + lg];
    const float b2 = B[c0 + lg + 8];
    const float scale = (p == 0) ? QSCALE : 1.0f;
    uint2* gi = (p == 0) ? g_qi : g_ki;

    /* ---- stage x: channel-pair words, interleaved {hi,lo} ---- */
    for (int i = tid; i < 32*64; i += 384) {
        int kp = i >> 6, q4 = i & 63;
        int col0 = q4 * 4;
        float4 a = *(const float4*)&x[(size_t)(2*kp  ) * S_TOT + s0 + col0];
        float4 b = *(const float4*)&x[(size_t)(2*kp+1) * S_TOT + s0 + col0];
        uint4 wh, wl;
        bf16_split2(a.x, b.x, wh.x, wl.x);
        bf16_split2(a.y, b.y, wh.y, wl.y);
        bf16_split2(a.z, b.z, wh.z, wl.z);
        bf16_split2(a.w, b.w, wh.w, wl.w);
        *(uint4*)&xs[kp*XP2 + col0    ] = make_uint4(wh.x, wl.x, wh.y, wl.y);
        *(uint4*)&xs[kp*XP2 + col0 + 2] = make_uint4(wh.z, wl.z, wh.w, wl.w);
    }
    __syncthreads();

    #pragma unroll 1
    for (int qt = 0; qt < 4; qt++) {
        float c[8][4];
        #pragma unroll
        for (int n = 0; n < 8; n++) {
            c[n][0] = b1; c[n][1] = b1; c[n][2] = b2; c[n][3] = b2;
        }

        #pragma unroll 1
        for (int kt = 0; kt < 4; kt++) {
            const int b0i = (8*kt + la)*XP2 + qt*64 + lg;
            const int b1i = b0i + 4*XP2;
            #pragma unroll
            for (int n = 0; n < 8; n++) {
                uint2 B0 = xs[b0i + n*8];
                uint2 B1 = xs[b1i + n*8];
                mma_bf16(c[n], ah[kt*4+0], ah[kt*4+1], ah[kt*4+2], ah[kt*4+3], B0.x, B1.x);
                mma_bf16(c[n], ah[kt*4+0], ah[kt*4+1], ah[kt*4+2], ah[kt*4+3], B0.y, B1.y);
                mma_bf16(c[n], al[kt*4+0], al[kt*4+1], al[kt*4+2], al[kt*4+3], B0.x, B1.x);
            }
        }

        if (p < 2) {
            #pragma unroll
            for (int n = 0; n < 8; n++) {
                const int scol = ((s0 + qt*64 + n*8) >> 1) + la;
                uint32_t h, l;
                bf16_split2(c[n][0]*scale, c[n][1]*scale, h, l);
                gi[(size_t)(c0 + lg    )*(S_TOT/2) + scol] = make_uint2(h, l);
                bf16_split2(c[n][2]*scale, c[n][3]*scale, h, l);
                gi[(size_t)(c0 + lg + 8)*(S_TOT/2) + scol] = make_uint2(h, l);
            }
        } else {
            #pragma unroll
            for (int n = 0; n < 8; n++) {
                const int scol = ((s0 + qt*64 + n*8) >> 1) + la;
                g_vf[(size_t)(c0 + lg    )*(S_TOT/2) + scol] = f16pack(c[n][0], c[n][1]);
                g_vf[(size_t)(c0 + lg + 8)*(S_TOT/2) + scol] = f16pack(c[n][2], c[n][3]);
            }
        }
    }
}

/* ------------------------------------------------------------------ */
/* Phase 2: attention. Q from GLOBAL (uint2 = a-frag pair), K in smem  */
/* interleaved uint2 (1 LDS.64 per b-frag pair), A overlays dead K,    */
/* O written directly to global. 104.4KB smem -> 2 CTAs/SM.            */
/* ------------------------------------------------------------------ */
#define KIP 68                              /* uint2 pitch for K rows  */
#define ATV_OFF 69632
#define AT_SMEM (69632 + 34816)             /* 104448 B                */

__global__ void __launch_bounds__(256, 2) attn_kernel()
{
    extern __shared__ char smc[];
    uint2*    KI = (uint2*)smc;                   /* [128][68] {hi,lo}  */
    uint32_t* Aq = (uint32_t*)smc;                /* [128][68] fp16 A   */
    uint32_t* Vp = (uint32_t*)(smc + ATV_OFF);    /* [64][136] fp16x2   */

    const int tid  = threadIdx.x;
    const int lane = tid & 31;
    const int wrp  = tid >> 5;
    const int lg   = lane >> 2;
    const int la   = lane & 3;
    const size_t base = (size_t)blockIdx.x * SLAB;

    /* ---- K: raw uint4 copy (format already interleaved) ---- */
    const uint4* Ki4 = (const uint4*)g_ki + (size_t)blockIdx.x * 4096;
    for (int i = tid; i < 4096; i += 256) {
        int r = i >> 5, u = i & 31;
        *(uint4*)&KI[r*KIP + 2*u] = Ki4[i];
    }
    /* ---- V: fp16 key-pair packing via byte_perm ---- */
    const uint4* Vf4 = (const uint4*)g_vf + (size_t)blockIdx.x * 2048;
    for (int i = tid; i < 1024; i += 256) {
        int kp = i >> 4, u = i & 15;
        uint4 e = Vf4[(2*kp  )*16 + u];
        uint4 o = Vf4[(2*kp+1)*16 + u];
        uint4 w0, w1;
        w0.x = __byte_perm(e.x, o.x, 0x5410);  w0.y = __byte_perm(e.x, o.x, 0x7632);
        w0.z = __byte_perm(e.y, o.y, 0x5410);  w0.w = __byte_perm(e.y, o.y, 0x7632);
        w1.x = __byte_perm(e.z, o.z, 0x5410);  w1.y = __byte_perm(e.z, o.z, 0x7632);
        w1.z = __byte_perm(e.w, o.w, 0x5410);  w1.w = __byte_perm(e.w, o.w, 0x7632);
        *(uint4*)&Vp[kp*136 + u*8    ] = w0;
        *(uint4*)&Vp[kp*136 + u*8 + 4] = w1;
    }
    __syncthreads();

    const int r0 = wrp * 16;
    const int ra = r0 + lg, rb = ra + 8;

    /* ================= S = Q K^T : Q a-frags direct from global ====== */
    float s[16][4];
    #pragma unroll
    for (int n = 0; n < 16; n++) {
        s[n][0] = 0.f; s[n][1] = 0.f; s[n][2] = 0.f; s[n][3] = 0.f;
    }

    const uint2* Qg = g_qi + (size_t)blockIdx.x * 8192 + (size_t)(r0 + lg)*64 + la;
    uint2 qa[2][4];
    qa[0][0] = Qg[0];  qa[0][1] = Qg[512];
    qa[0][2] = Qg[4];  qa[0][3] = Qg[516];

    #pragma unroll 1
    for (int kt = 0; kt < 8; kt++) {
        const int cur = kt & 1;
        if (kt < 7) {
            const uint2* qn = Qg + (kt + 1)*8;
            qa[cur^1][0] = qn[0];  qa[cur^1][1] = qn[512];
            qa[cur^1][2] = qn[4];  qa[cur^1][3] = qn[516];
        }
        const uint32_t ah0 = qa[cur][0].x, al0 = qa[cur][0].y;
        const uint32_t ah1 = qa[cur][1].x, al1 = qa[cur][1].y;
        const uint32_t ah2 = qa[cur][2].x, al2 = qa[cur][2].y;
        const uint32_t ah3 = qa[cur][3].x, al3 = qa[cur][3].y;

        const uint2* kb = &KI[lg*KIP + kt*8 + la];
        #pragma unroll
        for (int n = 0; n < 16; n++) {
            uint2 B0 = kb[n*8*KIP];
            uint2 B1 = kb[n*8*KIP + 4];
            mma_bf16(s[n], ah0, ah1, ah2, ah3, B0.x, B1.x);
            mma_bf16(s[n], ah0, ah1, ah2, ah3, B0.y, B1.y);
            mma_bf16(s[n], al0, al1, al2, al3, B0.x, B1.x);
        }
    }

    /* ================= row softmax ==================================== */
    float ia, ib;
    {
        float ma = -1e30f, mb = -1e30f;
        #pragma unroll
        for (int n = 0; n < 16; n++) {
            ma = fmaxf(ma, fmaxf(s[n][0], s[n][1]));
            mb = fmaxf(mb, fmaxf(s[n][2], s[n][3]));
        }
        ma = fmaxf(ma, __shfl_xor_sync(0xffffffffu, ma, 1));
        ma = fmaxf(ma, __shfl_xor_sync(0xffffffffu, ma, 2));
        mb = fmaxf(mb, __shfl_xor_sync(0xffffffffu, mb, 1));
        mb = fmaxf(mb, __shfl_xor_sync(0xffffffffu, mb, 2));

        float sa = 0.f, sb = 0.f;
        #pragma unroll
        for (int n = 0; n < 16; n++) {
            s[n][0] = __expf(s[n][0] - ma);  sa += s[n][0];
            s[n][1] = __expf(s[n][1] - ma);  sa += s[n][1];
            s[n][2] = __expf(s[n][2] - mb);  sb += s[n][2];
            s[n][3] = __expf(s[n][3] - mb);  sb += s[n][3];
        }
        sa += __shfl_xor_sync(0xffffffffu, sa, 1);
        sa += __shfl_xor_sync(0xffffffffu, sa, 2);
        sb += __shfl_xor_sync(0xffffffffu, sb, 1);
        sb += __shfl_xor_sync(0xffffffffu, sb, 2);
        ia = 1.0f / sa;  ib = 1.0f / sb;
    }

    /* all warps done reading K before A (fp16) overlays it */
    __syncthreads();
    #pragma unroll
    for (int n = 0; n < 16; n++) {
        Aq[ra*KIP + n*4 + la] = f16pack(s[n][0] * ia, s[n][1] * ia);
        Aq[rb*KIP + n*4 + la] = f16pack(s[n][2] * ib, s[n][3] * ib);
    }
    __syncwarp();

    /* ================= O = A V : single fp16 MMA per (kt,n) =========== */
    float o[16][4];
    #pragma unroll
    for (int n = 0; n < 16; n++) {
        o[n][0] = 0.f; o[n][1] = 0.f; o[n][2] = 0.f; o[n][3] = 0.f;
    }

    #pragma unroll 1
    for (int kt = 0; kt < 8; kt++) {
        const uint32_t* pa = &Aq[(r0 + lg)*KIP + kt*8 + la];
        uint32_t a0 = pa[0];
        uint32_t a1 = pa[8*KIP];
        uint32_t a2 = pa[4];
        uint32_t a3 = pa[8*KIP + 4];

        const int w0 = (kt*8 + la) * 136;
        #pragma unroll
        for (int n = 0; n < 16; n++) {
            uint32_t b0 = Vp[w0 + n*8 + lg];
            uint32_t b1 = Vp[w0 + 4*136 + n*8 + lg];
            mma_f16(o[n], a0, a1, a2, a3, b0, b1);
        }
    }

    /* ---- O direct to global: 32B contiguous per quarter-warp ---- */
    #pragma unroll
    for (int n = 0; n < 16; n++) {
        *(float2*)&g_o[base + (size_t)ra*128 + n*8 + 2*la] = make_float2(o[n][0], o[n][1]);
        *(float2*)&g_o[base + (size_t)rb*128 + n*8 + 2*la] = make_float2(o[n][2], o[n][3]);
    }
}

/* ------------------------------------------------------------------ */
/* Phase 3: output projection, bf16 k16, 3-term, interleaved smem.     */
/* ------------------------------------------------------------------ */
#define P3_SMEM (32 * XP2 * 8)

__global__ void __launch_bounds__(256, 2) proj_o_kernel(
    float* __restrict__ out,
    const float* __restrict__ wo, const float* __restrict__ bo)
{
    extern __shared__ uint2 osx[];          /* [32][268] {hi,lo} */

    const int tid  = threadIdx.x;
    const int lane = tid & 31;
    const int wrp  = tid >> 5;
    const int lg   = lane >> 2;
    const int la   = lane & 3;
    const int s0   = blockIdx.x * 256;

    const int c0 = (wrp & 3) * 16;
    const int hf = wrp >> 2;

    uint32_t ah[16], al[16];
    #pragma unroll
    for (int kt = 0; kt < 4; kt++) {
        int kk = kt*16 + 2*la;
        float2 w0 = *(const float2*)&wo[(c0 + lg    )*64 + kk    ];
        float2 w1 = *(const float2*)&wo[(c0 + lg + 8)*64 + kk    ];
        float2 w2 = *(const float2*)&wo[(c0 + lg    )*64 + kk + 8];
        float2 w3 = *(const float2*)&wo[(c0 + lg + 8)*64 + kk + 8];
        bf16_split2(w0.x, w0.y, ah[kt*4+0], al[kt*4+0]);
        bf16_split2(w1.x, w1.y, ah[kt*4+1], al[kt*4+1]);
        bf16_split2(w2.x, w2.y, ah[kt*4+2], al[kt*4+2]);
        bf16_split2(w3.x, w3.y, ah[kt*4+3], al[kt*4+3]);
    }
    const float b1 = bo[c0 + lg];
    const float b2 = bo[c0 + lg + 8];

    for (int i = tid; i < 32*64; i += 256) {
        int kp = i >> 6, q4 = i & 63;
        int col0 = q4 * 4;
        float4 a = *(const float4*)&g_o[(size_t)(2*kp  ) * S_TOT + s0 + col0];
        float4 b = *(const float4*)&g_o[(size_t)(2*kp+1) * S_TOT + s0 + col0];
        uint4 wh, wl;
        bf16_split2(a.x, b.x, wh.x, wl.x);
        bf16_split2(a.y, b.y, wh.y, wl.y);
        bf16_split2(a.z, b.z, wh.z, wl.z);
        bf16_split2(a.w, b.w, wh.w, wl.w);
        *(uint4*)&osx[kp*XP2 + col0    ] = make_uint4(wh.x, wl.x, wh.y, wl.y);
        *(uint4*)&osx[kp*XP2 + col0 + 2] = make_uint4(wh.z, wl.z, wh.w, wl.w);
    }
    __syncthreads();

    #pragma unroll 1
    for (int qq = 0; qq < 2; qq++) {
        float c[8][4];
        #pragma unroll
        for (int n = 0; n < 8; n++) {
            c[n][0] = b1; c[n][1] = b1; c[n][2] = b2; c[n][3] = b2;
        }

        #pragma unroll 1
        for (int kt = 0; kt < 4; kt++) {
            const int b0i = (8*kt + la)*XP2 + hf*128 + qq*64 + lg;
            const int b1i = b0i + 4*XP2;
            #pragma unroll
            for (int n = 0; n < 8; n++) {
                uint2 B0 = osx[b0i + n*8];
                uint2 B1 = osx[b1i + n*8];
                mma_bf16(c[n], ah[kt*4+0], ah[kt*4+1], ah[kt*4+2], ah[kt*4+3], B0.x, B1.x);
                mma_bf16(c[n], ah[kt*4+0], ah[kt*4+1], ah[kt*4+2], ah[kt*4+3], B0.y, B1.y);
                mma_bf16(c[n], al[kt*4+0], al[kt*4+1], al[kt*4+2], al[kt*4+3], B0.x, B1.x);
            }
        }

        #pragma unroll
        for (int n = 0; n < 8; n++) {
            size_t col = (size_t)(s0 + hf*128 + qq*64 + n*8 + 2*la);
            *(float2*)&out[(size_t)(c0 + lg    )*S_TOT + col] = make_float2(c[n][0], c[n][1]);
            *(float2*)&out[(size_t)(c0 + lg + 8)*S_TOT + col] = make_float2(c[n][2], c[n][3]);
        }
    }
}

/* ------------------------------------------------------------------ */
extern "C" void kernel_launch(void* const* d_in, const int* in_sizes, int n_in,
                              void* d_out, int out_size)
{
    const float* x  = (const float*)d_in[0];
    const float* wq = (const float*)d_in[1];
    const float* bq = (const float*)d_in[2];
    const float* wk = (const float*)d_in[3];
    const float* bk = (const float*)d_in[4];
    const float* wv = (const float*)d_in[5];
    const float* bv = (const float*)d_in[6];
    const float* wo = (const float*)d_in[7];
    const float* bo = (const float*)d_in[8];

    cudaFuncSetAttribute(qkv_kernel,    cudaFuncAttributeMaxDynamicSharedMemorySize, P1_SMEM);
    cudaFuncSetAttribute(attn_kernel,   cudaFuncAttributeMaxDynamicSharedMemorySize, AT_SMEM);
    cudaFuncSetAttribute(proj_o_kernel, cudaFuncAttributeMaxDynamicSharedMemorySize, P3_SMEM);

    qkv_kernel<<<S_TOT/256, 384, P1_SMEM>>>(x, wq, bq, wk, bk, wv, bv);
    attn_kernel<<<NSLAB, 256, AT_SMEM>>>();
    proj_o_kernel<<<S_TOT/256, 256, P3_SMEM>>>((float*)d_out, wo, bo);
}

// round 11
// speedup vs baseline: 2.5338x; 1.0068x over previous
#include <cuda_runtime.h>
#include <cuda_bf16.h>
#include <cuda_fp16.h>
#include <math.h>
#include <stdint.h>

#define CH    64
#define DDIM  48
#define WDIM  128
#define HDIM  128
#define S_TOT (DDIM*WDIM*HDIM)   /* 786432 spatial positions */
#define SLAB  (WDIM*HDIM)        /* 16384 per (c,d) slab     */
#define NSLAB (CH*DDIM)          /* 3072 attention problems  */

#define QSCALE 0.594603557501360533f   /* 8^(-1/4) */

/* q/k in FRAGMENT-ORDERED uint4: [c][d][kt][w][la] =
   {hi(hp=kt*8+la), lo(hp), hi(hp+4), lo(hp+4)}, hp = h-pair index.
   v as fp16x2 column pairs (unchanged). */
__device__ uint4    g_q4[CH * S_TOT / 4];
__device__ uint4    g_k4[CH * S_TOT / 4];
__device__ uint32_t g_vf[CH * S_TOT / 2];
__device__ float    g_o [CH * S_TOT];

/* ---------------- mma.sync helpers (legal in compute_103 PTX) ---------- */
__device__ __forceinline__ void mma_bf16(float c[4],
                                         uint32_t a0, uint32_t a1, uint32_t a2, uint32_t a3,
                                         uint32_t b0, uint32_t b1) {
    asm volatile(
        "mma.sync.aligned.m16n8k16.row.col.f32.bf16.bf16.f32 "
        "{%0,%1,%2,%3}, {%4,%5,%6,%7}, {%8,%9}, {%0,%1,%2,%3};"
        : "+f"(c[0]), "+f"(c[1]), "+f"(c[2]), "+f"(c[3])
        : "r"(a0), "r"(a1), "r"(a2), "r"(a3), "r"(b0), "r"(b1));
}
__device__ __forceinline__ void mma_f16(float c[4],
                                        uint32_t a0, uint32_t a1, uint32_t a2, uint32_t a3,
                                        uint32_t b0, uint32_t b1) {
    asm volatile(
        "mma.sync.aligned.m16n8k16.row.col.f32.f16.f16.f32 "
        "{%0,%1,%2,%3}, {%4,%5,%6,%7}, {%8,%9}, {%0,%1,%2,%3};"
        : "+f"(c[0]), "+f"(c[1]), "+f"(c[2]), "+f"(c[3])
        : "r"(a0), "r"(a1), "r"(a2), "r"(a3), "r"(b0), "r"(b1));
}
/* 2-term bf16 Dekker split of a pair (x->low half, y->high half) */
__device__ __forceinline__ void bf16_split2(float x, float y, uint32_t& h, uint32_t& l) {
    __nv_bfloat162 hb = __floats2bfloat162_rn(x, y);
    float rx = x - __bfloat162float(hb.x);
    float ry = y - __bfloat162float(hb.y);
    __nv_bfloat162 lb = __floats2bfloat162_rn(rx, ry);
    h = *(uint32_t*)&hb;
    l = *(uint32_t*)&lb;
}
__device__ __forceinline__ uint32_t f16pack(float x, float y) {
    __half2 h = __floats2half2_rn(x, y);
    return *(uint32_t*)&h;
}

/* ------------------------------------------------------------------ */
/* Phase 1: fused QKV projection, bf16 m16n8k16, 3-term split.         */
/* q/k emitted in fragment-ordered uint4; v as fp16x2.                 */
/* ------------------------------------------------------------------ */
#define XP2 268                           /* uint2 pitch (bank-checked) */
#define P1_SMEM (32 * XP2 * 8)            /* 68608 B                    */

__global__ void __launch_bounds__(384, 2) qkv_kernel(
    const float* __restrict__ x,
    const float* __restrict__ wq, const float* __restrict__ bq,
    const float* __restrict__ wk, const float* __restrict__ bk,
    const float* __restrict__ wv, const float* __restrict__ bv)
{
    extern __shared__ uint2 xs[];          /* [32][268] {hi,lo} */

    const int tid  = threadIdx.x;
    const int lane = tid & 31;
    const int wrp  = tid >> 5;
    const int lg   = lane >> 2;
    const int la   = lane & 3;
    const int s0   = blockIdx.x * 256;
    const int d    = s0 / 16384;
    const int wb   = (s0 % 16384) / 128;   /* base w row (block = 2 rows) */

    const int p  = wrp >> 2;                 /* 0=q 1=k 2=v */
    const int c0 = (wrp & 3) * 16;
    const float* W = (p == 0) ? wq : (p == 1) ? wk : wv;
    const float* B = (p == 0) ? bq : (p == 1) ? bk : bv;

    uint32_t ah[16], al[16];
    #pragma unroll
    for (int kt = 0; kt < 4; kt++) {
        int kk = kt*16 + 2*la;
        float2 w0 = *(const float2*)&W[(c0 + lg    )*64 + kk    ];
        float2 w1 = *(const float2*)&W[(c0 + lg + 8)*64 + kk    ];
        float2 w2 = *(const float2*)&W[(c0 + lg    )*64 + kk + 8];
        float2 w3 = *(const float2*)&W[(c0 + lg + 8)*64 + kk + 8];
        bf16_split2(w0.x, w0.y, ah[kt*4+0], al[kt*4+0]);
        bf16_split2(w1.x, w1.y, ah[kt*4+1], al[kt*4+1]);
        bf16_split2(w2.x, w2.y, ah[kt*4+2], al[kt*4+2]);
        bf16_split2(w3.x, w3.y, ah[kt*4+3], al[kt*4+3]);
    }
    const float b1 = B[c0 + lg];
    const float b2 = B[c0 + lg + 8];
    const float scale = (p == 0) ? QSCALE : 1.0f;
    uint4* g4 = (p == 0) ? g_q4 : g_k4;

    /* ---- stage x: channel-pair words, interleaved {hi,lo} ---- */
    for (int i = tid; i < 32*64; i += 384) {
        int kp = i >> 6, q4 = i & 63;
        int col0 = q4 * 4;
        float4 a = *(const float4*)&x[(size_t)(2*kp  ) * S_TOT + s0 + col0];
        float4 b = *(const float4*)&x[(size_t)(2*kp+1) * S_TOT + s0 + col0];
        uint4 wh, wl;
        bf16_split2(a.x, b.x, wh.x, wl.x);
        bf16_split2(a.y, b.y, wh.y, wl.y);
        bf16_split2(a.z, b.z, wh.z, wl.z);
        bf16_split2(a.w, b.w, wh.w, wl.w);
        *(uint4*)&xs[kp*XP2 + col0    ] = make_uint4(wh.x, wl.x, wh.y, wl.y);
        *(uint4*)&xs[kp*XP2 + col0 + 2] = make_uint4(wh.z, wl.z, wh.w, wl.w);
    }
    __syncthreads();

    #pragma unroll 1
    for (int qt = 0; qt < 4; qt++) {
        float c[8][4];
        #pragma unroll
        for (int n = 0; n < 8; n++) {
            c[n][0] = b1; c[n][1] = b1; c[n][2] = b2; c[n][3] = b2;
        }

        #pragma unroll 1
        for (int kt = 0; kt < 4; kt++) {
            const int b0i = (8*kt + la)*XP2 + qt*64 + lg;
            const int b1i = b0i + 4*XP2;
            #pragma unroll
            for (int n = 0; n < 8; n++) {
                uint2 B0 = xs[b0i + n*8];
                uint2 B1 = xs[b1i + n*8];
                mma_bf16(c[n], ah[kt*4+0], ah[kt*4+1], ah[kt*4+2], ah[kt*4+3], B0.x, B1.x);
                mma_bf16(c[n], ah[kt*4+0], ah[kt*4+1], ah[kt*4+2], ah[kt*4+3], B0.y, B1.y);
                mma_bf16(c[n], al[kt*4+0], al[kt*4+1], al[kt*4+2], al[kt*4+3], B0.x, B1.x);
            }
        }

        if (p < 2) {
            /* fragment-ordered uint4: kt_h=(qt&1)*4+n/2, w=wb+(qt>>1) */
            const int w = wb + (qt >> 1);
            #pragma unroll
            for (int ne = 0; ne < 8; ne += 2) {
                const int kt_h = (qt & 1)*4 + (ne >> 1);
                const size_t fi = (size_t)d*4096 + kt_h*512 + w*4 + la;
                uint32_t h0, l0, h1, l1;
                bf16_split2(c[ne  ][0]*scale, c[ne  ][1]*scale, h0, l0);
                bf16_split2(c[ne+1][0]*scale, c[ne+1][1]*scale, h1, l1);
                g4[(size_t)(c0 + lg    )*(S_TOT/4) + fi] = make_uint4(h0, l0, h1, l1);
                bf16_split2(c[ne  ][2]*scale, c[ne  ][3]*scale, h0, l0);
                bf16_split2(c[ne+1][2]*scale, c[ne+1][3]*scale, h1, l1);
                g4[(size_t)(c0 + lg + 8)*(S_TOT/4) + fi] = make_uint4(h0, l0, h1, l1);
            }
        } else {
            #pragma unroll
            for (int n = 0; n < 8; n++) {
                const int scol = ((s0 + qt*64 + n*8) >> 1) + la;
                g_vf[(size_t)(c0 + lg    )*(S_TOT/2) + scol] = f16pack(c[n][0], c[n][1]);
                g_vf[(size_t)(c0 + lg + 8)*(S_TOT/2) + scol] = f16pack(c[n][2], c[n][3]);
            }
        }
    }
}

/* ------------------------------------------------------------------ */
/* Phase 2: attention. Q a-frags = 2 LDG.128/kt; K raw uint4 copy,     */
/* b-frag = 1 LDS.128; A frag-packed uint2; V as before.               */
/* smem: K/A 65536 B + Vp 34816 B = 100352 -> 2 CTAs/SM.               */
/* ------------------------------------------------------------------ */
#define ATV_OFF 65536
#define AT_SMEM (65536 + 34816)

__global__ void __launch_bounds__(256, 2) attn_kernel()
{
    extern __shared__ char smc[];
    uint4*    Ksm = (uint4*)smc;                  /* [8][128][4] uint4  */
    uint2*    Fa  = (uint2*)smc;                  /* [8][128][4] uint2  */
    uint32_t* Vp  = (uint32_t*)(smc + ATV_OFF);   /* [64][136] fp16x2   */

    const int tid  = threadIdx.x;
    const int lane = tid & 31;
    const int wrp  = tid >> 5;
    const int lg   = lane >> 2;
    const int la   = lane & 3;
    const size_t base = (size_t)blockIdx.x * SLAB;

    /* ---- K: raw uint4 copy (global already fragment-ordered) ---- */
    const uint4* Kg4 = g_k4 + (size_t)blockIdx.x * 4096;
    for (int i = tid; i < 4096; i += 256)
        Ksm[i] = Kg4[i];
    /* ---- V: fp16 key-pair packing via byte_perm ---- */
    const uint4* Vf4 = (const uint4*)g_vf + (size_t)blockIdx.x * 2048;
    for (int i = tid; i < 1024; i += 256) {
        int kp = i >> 4, u = i & 15;
        uint4 e = Vf4[(2*kp  )*16 + u];
        uint4 o = Vf4[(2*kp+1)*16 + u];
        uint4 w0, w1;
        w0.x = __byte_perm(e.x, o.x, 0x5410);  w0.y = __byte_perm(e.x, o.x, 0x7632);
        w0.z = __byte_perm(e.y, o.y, 0x5410);  w0.w = __byte_perm(e.y, o.y, 0x7632);
        w1.x = __byte_perm(e.z, o.z, 0x5410);  w1.y = __byte_perm(e.z, o.z, 0x7632);
        w1.z = __byte_perm(e.w, o.w, 0x5410);  w1.w = __byte_perm(e.w, o.w, 0x7632);
        *(uint4*)&Vp[kp*136 + u*8    ] = w0;
        *(uint4*)&Vp[kp*136 + u*8 + 4] = w1;
    }
    __syncthreads();

    const int r0 = wrp * 16;
    const int ra = r0 + lg, rb = ra + 8;

    /* ================= S = Q K^T ====================================== */
    float s[16][4];
    #pragma unroll
    for (int n = 0; n < 16; n++) {
        s[n][0] = 0.f; s[n][1] = 0.f; s[n][2] = 0.f; s[n][3] = 0.f;
    }

    const uint4* Qg4 = g_q4 + (size_t)blockIdx.x * 4096 + (size_t)(r0 + lg)*4 + la;
    uint4 qa[2][2];
    qa[0][0] = Qg4[0];
    qa[0][1] = Qg4[32];

    #pragma unroll 1
    for (int kt = 0; kt < 8; kt++) {
        const int cur = kt & 1;
        if (kt < 7) {
            qa[cur^1][0] = Qg4[(kt+1)*512];
            qa[cur^1][1] = Qg4[(kt+1)*512 + 32];
        }
        const uint32_t ah0 = qa[cur][0].x, al0 = qa[cur][0].y;
        const uint32_t ah2 = qa[cur][0].z, al2 = qa[cur][0].w;
        const uint32_t ah1 = qa[cur][1].x, al1 = qa[cur][1].y;
        const uint32_t ah3 = qa[cur][1].z, al3 = qa[cur][1].w;

        const uint4* kb = &Ksm[kt*512 + lg*4 + la];
        #pragma unroll
        for (int n = 0; n < 16; n++) {
            uint4 Bf = kb[n*32];
            mma_bf16(s[n], ah0, ah1, ah2, ah3, Bf.x, Bf.z);
            mma_bf16(s[n], ah0, ah1, ah2, ah3, Bf.y, Bf.w);
            mma_bf16(s[n], al0, al1, al2, al3, Bf.x, Bf.z);
        }
    }

    /* ================= row softmax ==================================== */
    float ia, ib;
    {
        float ma = -1e30f, mb = -1e30f;
        #pragma unroll
        for (int n = 0; n < 16; n++) {
            ma = fmaxf(ma, fmaxf(s[n][0], s[n][1]));
            mb = fmaxf(mb, fmaxf(s[n][2], s[n][3]));
        }
        ma = fmaxf(ma, __shfl_xor_sync(0xffffffffu, ma, 1));
        ma = fmaxf(ma, __shfl_xor_sync(0xffffffffu, ma, 2));
        mb = fmaxf(mb, __shfl_xor_sync(0xffffffffu, mb, 1));
        mb = fmaxf(mb, __shfl_xor_sync(0xffffffffu, mb, 2));

        float sa = 0.f, sb = 0.f;
        #pragma unroll
        for (int n = 0; n < 16; n++) {
            s[n][0] = __expf(s[n][0] - ma);  sa += s[n][0];
            s[n][1] = __expf(s[n][1] - ma);  sa += s[n][1];
            s[n][2] = __expf(s[n][2] - mb);  sb += s[n][2];
            s[n][3] = __expf(s[n][3] - mb);  sb += s[n][3];
        }
        sa += __shfl_xor_sync(0xffffffffu, sa, 1);
        sa += __shfl_xor_sync(0xffffffffu, sa, 2);
        sb += __shfl_xor_sync(0xffffffffu, sb, 1);
        sb += __shfl_xor_sync(0xffffffffu, sb, 2);
        ia = 1.0f / sa;  ib = 1.0f / sb;
    }

    /* all warps done reading K before A overlays it */
    __syncthreads();
    #pragma unroll
    for (int kt = 0; kt < 8; kt++) {
        Fa[kt*512 + ra*4 + la] =
            make_uint2(f16pack(s[2*kt  ][0]*ia, s[2*kt  ][1]*ia),
                       f16pack(s[2*kt+1][0]*ia, s[2*kt+1][1]*ia));
        Fa[kt*512 + rb*4 + la] =
            make_uint2(f16pack(s[2*kt  ][2]*ib, s[2*kt  ][3]*ib),
                       f16pack(s[2*kt+1][2]*ib, s[2*kt+1][3]*ib));
    }
    __syncwarp();

    /* ================= O = A V ======================================== */
    float o[16][4];
    #pragma unroll
    for (int n = 0; n < 16; n++) {
        o[n][0] = 0.f; o[n][1] = 0.f; o[n][2] = 0.f; o[n][3] = 0.f;
    }

    #pragma unroll 1
    for (int kt = 0; kt < 8; kt++) {
        uint2 u2a = Fa[kt*512 + (r0 + lg    )*4 + la];
        uint2 u2b = Fa[kt*512 + (r0 + lg + 8)*4 + la];
        const uint32_t a0 = u2a.x, a2 = u2a.y;
        const uint32_t a1 = u2b.x, a3 = u2b.y;

        const int w0v = (kt*8 + la) * 136;
        #pragma unroll
        for (int n = 0; n < 16; n++) {
            uint32_t b0 = Vp[w0v + n*8 + lg];
            uint32_t b1 = Vp[w0v + 4*136 + n*8 + lg];
            mma_f16(o[n], a0, a1, a2, a3, b0, b1);
        }
    }

    /* ---- O direct to global ---- */
    #pragma unroll
    for (int n = 0; n < 16; n++) {
        *(float2*)&g_o[base + (size_t)ra*128 + n*8 + 2*la] = make_float2(o[n][0], o[n][1]);
        *(float2*)&g_o[base + (size_t)rb*128 + n*8 + 2*la] = make_float2(o[n][2], o[n][3]);
    }
}

/* ------------------------------------------------------------------ */
/* Phase 3: output projection, bf16 k16, 3-term, interleaved smem.     */
/* ------------------------------------------------------------------ */
#define P3_SMEM (32 * XP2 * 8)

__global__ void __launch_bounds__(256, 2) proj_o_kernel(
    float* __restrict__ out,
    const float* __restrict__ wo, const float* __restrict__ bo)
{
    extern __shared__ uint2 osx[];          /* [32][268] {hi,lo} */

    const int tid  = threadIdx.x;
    const int lane = tid & 31;
    const int wrp  = tid >> 5;
    const int lg   = lane >> 2;
    const int la   = lane & 3;
    const int s0   = blockIdx.x * 256;

    const int c0 = (wrp & 3) * 16;
    const int hf = wrp >> 2;

    uint32_t ah[16], al[16];
    #pragma unroll
    for (int kt = 0; kt < 4; kt++) {
        int kk = kt*16 + 2*la;
        float2 w0 = *(const float2*)&wo[(c0 + lg    )*64 + kk    ];
        float2 w1 = *(const float2*)&wo[(c0 + lg + 8)*64 + kk    ];
        float2 w2 = *(const float2*)&wo[(c0 + lg    )*64 + kk + 8];
        float2 w3 = *(const float2*)&wo[(c0 + lg + 8)*64 + kk + 8];
        bf16_split2(w0.x, w0.y, ah[kt*4+0], al[kt*4+0]);
        bf16_split2(w1.x, w1.y, ah[kt*4+1], al[kt*4+1]);
        bf16_split2(w2.x, w2.y, ah[kt*4+2], al[kt*4+2]);
        bf16_split2(w3.x, w3.y, ah[kt*4+3], al[kt*4+3]);
    }
    const float b1 = bo[c0 + lg];
    const float b2 = bo[c0 + lg + 8];

    for (int i = tid; i < 32*64; i += 256) {
        int kp = i >> 6, q4 = i & 63;
        int col0 = q4 * 4;
        float4 a = *(const float4*)&g_o[(size_t)(2*kp  ) * S_TOT + s0 + col0];
        float4 b = *(const float4*)&g_o[(size_t)(2*kp+1) * S_TOT + s0 + col0];
        uint4 wh, wl;
        bf16_split2(a.x, b.x, wh.x, wl.x);
        bf16_split2(a.y, b.y, wh.y, wl.y);
        bf16_split2(a.z, b.z, wh.z, wl.z);
        bf16_split2(a.w, b.w, wh.w, wl.w);
        *(uint4*)&osx[kp*XP2 + col0    ] = make_uint4(wh.x, wl.x, wh.y, wl.y);
        *(uint4*)&osx[kp*XP2 + col0 + 2] = make_uint4(wh.z, wl.z, wh.w, wl.w);
    }
    __syncthreads();

    #pragma unroll 1
    for (int qq = 0; qq < 2; qq++) {
        float c[8][4];
        #pragma unroll
        for (int n = 0; n < 8; n++) {
            c[n][0] = b1; c[n][1] = b1; c[n][2] = b2; c[n][3] = b2;
        }

        #pragma unroll 1
        for (int kt = 0; kt < 4; kt++) {
            const int b0i = (8*kt + la)*XP2 + hf*128 + qq*64 + lg;
            const int b1i = b0i + 4*XP2;
            #pragma unroll
            for (int n = 0; n < 8; n++) {
                uint2 B0 = osx[b0i + n*8];
                uint2 B1 = osx[b1i + n*8];
                mma_bf16(c[n], ah[kt*4+0], ah[kt*4+1], ah[kt*4+2], ah[kt*4+3], B0.x, B1.x);
                mma_bf16(c[n], ah[kt*4+0], ah[kt*4+1], ah[kt*4+2], ah[kt*4+3], B0.y, B1.y);
                mma_bf16(c[n], al[kt*4+0], al[kt*4+1], al[kt*4+2], al[kt*4+3], B0.x, B1.x);
            }
        }

        #pragma unroll
        for (int n = 0; n < 8; n++) {
            size_t col = (size_t)(s0 + hf*128 + qq*64 + n*8 + 2*la);
            *(float2*)&out[(size_t)(c0 + lg    )*S_TOT + col] = make_float2(c[n][0], c[n][1]);
            *(float2*)&out[(size_t)(c0 + lg + 8)*S_TOT + col] = make_float2(c[n][2], c[n][3]);
        }
    }
}

/* ------------------------------------------------------------------ */
extern "C" void kernel_launch(void* const* d_in, const int* in_sizes, int n_in,
                              void* d_out, int out_size)
{
    const float* x  = (const float*)d_in[0];
    const float* wq = (const float*)d_in[1];
    const float* bq = (const float*)d_in[2];
    const float* wk = (const float*)d_in[3];
    const float* bk = (const float*)d_in[4];
    const float* wv = (const float*)d_in[5];
    const float* bv = (const float*)d_in[6];
    const float* wo = (const float*)d_in[7];
    const float* bo = (const float*)d_in[8];

    cudaFuncSetAttribute(qkv_kernel,    cudaFuncAttributeMaxDynamicSharedMemorySize, P1_SMEM);
    cudaFuncSetAttribute(attn_kernel,   cudaFuncAttributeMaxDynamicSharedMemorySize, AT_SMEM);
    cudaFuncSetAttribute(proj_o_kernel, cudaFuncAttributeMaxDynamicSharedMemorySize, P3_SMEM);

    qkv_kernel<<<S_TOT/256, 384, P1_SMEM>>>(x, wq, bq, wk, bk, wv, bv);
    attn_kernel<<<NSLAB, 256, AT_SMEM>>>();
    proj_o_kernel<<<S_TOT/256, 256, P3_SMEM>>>((float*)d_out, wo, bo);
}

// round 13
// speedup vs baseline: 2.6582x; 1.0491x over previous
#include <cuda_runtime.h>
#include <cuda_bf16.h>
#include <cuda_fp16.h>
#include <math.h>
#include <stdint.h>

#define CH    64
#define DDIM  48
#define WDIM  128
#define HDIM  128
#define S_TOT (DDIM*WDIM*HDIM)   /* 786432 spatial positions */
#define SLAB  (WDIM*HDIM)        /* 16384 per (c,d) slab     */
#define NSLAB (CH*DDIM)          /* 3072 attention problems  */

#define QSCALE 0.594603557501360533f   /* 8^(-1/4) */

/* q/k fragment-ordered uint4 {hi,lo,hi+4,lo+4}; v fp16x2 pairs; O fp16 */
__device__ uint4          g_q4[CH * S_TOT / 4];
__device__ uint4          g_k4[CH * S_TOT / 4];
__device__ uint32_t       g_vf[CH * S_TOT / 2];
__device__ unsigned short g_of[CH * S_TOT];

/* ---------------- mma.sync helpers (legal in compute_103 PTX) ---------- */
__device__ __forceinline__ void mma_bf16(float c[4],
                                         uint32_t a0, uint32_t a1, uint32_t a2, uint32_t a3,
                                         uint32_t b0, uint32_t b1) {
    asm volatile(
        "mma.sync.aligned.m16n8k16.row.col.f32.bf16.bf16.f32 "
        "{%0,%1,%2,%3}, {%4,%5,%6,%7}, {%8,%9}, {%0,%1,%2,%3};"
        : "+f"(c[0]), "+f"(c[1]), "+f"(c[2]), "+f"(c[3])
        : "r"(a0), "r"(a1), "r"(a2), "r"(a3), "r"(b0), "r"(b1));
}
__device__ __forceinline__ void mma_f16(float c[4],
                                        uint32_t a0, uint32_t a1, uint32_t a2, uint32_t a3,
                                        uint32_t b0, uint32_t b1) {
    asm volatile(
        "mma.sync.aligned.m16n8k16.row.col.f32.f16.f16.f32 "
        "{%0,%1,%2,%3}, {%4,%5,%6,%7}, {%8,%9}, {%0,%1,%2,%3};"
        : "+f"(c[0]), "+f"(c[1]), "+f"(c[2]), "+f"(c[3])
        : "r"(a0), "r"(a1), "r"(a2), "r"(a3), "r"(b0), "r"(b1));
}
/* 2-term bf16 Dekker split of a pair (x->low half, y->high half) */
__device__ __forceinline__ void bf16_split2(float x, float y, uint32_t& h, uint32_t& l) {
    __nv_bfloat162 hb = __floats2bfloat162_rn(x, y);
    float rx = x - __bfloat162float(hb.x);
    float ry = y - __bfloat162float(hb.y);
    __nv_bfloat162 lb = __floats2bfloat162_rn(rx, ry);
    h = *(uint32_t*)&hb;
    l = *(uint32_t*)&lb;
}
/* 2-term fp16 Dekker split of a pair */
__device__ __forceinline__ void f16_split2(float x, float y, uint32_t& h, uint32_t& l) {
    __half hx = __float2half_rn(x), hy = __float2half_rn(y);
    __half lx = __float2half_rn(x - __half2float(hx));
    __half ly = __float2half_rn(y - __half2float(hy));
    __half2 hh = __halves2half2(hx, hy);
    __half2 ll = __halves2half2(lx, ly);
    h = *(uint32_t*)&hh;
    l = *(uint32_t*)&ll;
}
__device__ __forceinline__ uint32_t f16pack(float x, float y) {
    __half2 h = __floats2half2_rn(x, y);
    return *(uint32_t*)&h;
}

/* ------------------------------------------------------------------ */
/* Phase 1: fused QKV projection, bf16 m16n8k16, 3-term split.         */
/* ------------------------------------------------------------------ */
#define XP2 268                           /* uint2 pitch (bank-checked) */
#define P1_SMEM (32 * XP2 * 8)            /* 68608 B                    */

__global__ void __launch_bounds__(384, 2) qkv_kernel(
    const float* __restrict__ x,
    const float* __restrict__ wq, const float* __restrict__ bq,
    const float* __restrict__ wk, const float* __restrict__ bk,
    const float* __restrict__ wv, const float* __restrict__ bv)
{
    extern __shared__ uint2 xs[];          /* [32][268] {hi,lo} */

    const int tid  = threadIdx.x;
    const int lane = tid & 31;
    const int wrp  = tid >> 5;
    const int lg   = lane >> 2;
    const int la   = lane & 3;
    const int s0   = blockIdx.x * 256;
    const int d    = s0 / 16384;
    const int wb   = (s0 % 16384) / 128;

    const int p  = wrp >> 2;                 /* 0=q 1=k 2=v */
    const int c0 = (wrp & 3) * 16;
    const float* W = (p == 0) ? wq : (p == 1) ? wk : wv;
    const float* B = (p == 0) ? bq : (p == 1) ? bk : bv;

    uint32_t ah[16], al[16];
    #pragma unroll
    for (int kt = 0; kt < 4; kt++) {
        int kk = kt*16 + 2*la;
        float2 w0 = *(const float2*)&W[(c0 + lg    )*64 + kk    ];
        float2 w1 = *(const float2*)&W[(c0 + lg + 8)*64 + kk    ];
        float2 w2 = *(const float2*)&W[(c0 + lg    )*64 + kk + 8];
        float2 w3 = *(const float2*)&W[(c0 + lg + 8)*64 + kk + 8];
        bf16_split2(w0.x, w0.y, ah[kt*4+0], al[kt*4+0]);
        bf16_split2(w1.x, w1.y, ah[kt*4+1], al[kt*4+1]);
        bf16_split2(w2.x, w2.y, ah[kt*4+2], al[kt*4+2]);
        bf16_split2(w3.x, w3.y, ah[kt*4+3], al[kt*4+3]);
    }
    const float b1 = B[c0 + lg];
    const float b2 = B[c0 + lg + 8];
    const float scale = (p == 0) ? QSCALE : 1.0f;
    uint4* g4 = (p == 0) ? g_q4 : g_k4;

    for (int i = tid; i < 32*64; i += 384) {
        int kp = i >> 6, q4 = i & 63;
        int col0 = q4 * 4;
        float4 a = *(const float4*)&x[(size_t)(2*kp  ) * S_TOT + s0 + col0];
        float4 b = *(const float4*)&x[(size_t)(2*kp+1) * S_TOT + s0 + col0];
        uint4 wh, wl;
        bf16_split2(a.x, b.x, wh.x, wl.x);
        bf16_split2(a.y, b.y, wh.y, wl.y);
        bf16_split2(a.z, b.z, wh.z, wl.z);
        bf16_split2(a.w, b.w, wh.w, wl.w);
        *(uint4*)&xs[kp*XP2 + col0    ] = make_uint4(wh.x, wl.x, wh.y, wl.y);
        *(uint4*)&xs[kp*XP2 + col0 + 2] = make_uint4(wh.z, wl.z, wh.w, wl.w);
    }
    __syncthreads();

    #pragma unroll 1
    for (int qt = 0; qt < 4; qt++) {
        float c[8][4];
        #pragma unroll
        for (int n = 0; n < 8; n++) {
            c[n][0] = b1; c[n][1] = b1; c[n][2] = b2; c[n][3] = b2;
        }

        #pragma unroll 1
        for (int kt = 0; kt < 4; kt++) {
            const int b0i = (8*kt + la)*XP2 + qt*64 + lg;
            const int b1i = b0i + 4*XP2;
            #pragma unroll
            for (int n = 0; n < 8; n++) {
                uint2 B0 = xs[b0i + n*8];
                uint2 B1 = xs[b1i + n*8];
                mma_bf16(c[n], ah[kt*4+0], ah[kt*4+1], ah[kt*4+2], ah[kt*4+3], B0.x, B1.x);
                mma_bf16(c[n], ah[kt*4+0], ah[kt*4+1], ah[kt*4+2], ah[kt*4+3], B0.y, B1.y);
                mma_bf16(c[n], al[kt*4+0], al[kt*4+1], al[kt*4+2], al[kt*4+3], B0.x, B1.x);
            }
        }

        if (p < 2) {
            const int w = wb + (qt >> 1);
            #pragma unroll
            for (int ne = 0; ne < 8; ne += 2) {
                const int kt_h = (qt & 1)*4 + (ne >> 1);
                const size_t fi = (size_t)d*4096 + kt_h*512 + w*4 + la;
                uint32_t h0, l0, h1, l1;
                bf16_split2(c[ne  ][0]*scale, c[ne  ][1]*scale, h0, l0);
                bf16_split2(c[ne+1][0]*scale, c[ne+1][1]*scale, h1, l1);
                g4[(size_t)(c0 + lg    )*(S_TOT/4) + fi] = make_uint4(h0, l0, h1, l1);
                bf16_split2(c[ne  ][2]*scale, c[ne  ][3]*scale, h0, l0);
                bf16_split2(c[ne+1][2]*scale, c[ne+1][3]*scale, h1, l1);
                g4[(size_t)(c0 + lg + 8)*(S_TOT/4) + fi] = make_uint4(h0, l0, h1, l1);
            }
        } else {
            #pragma unroll
            for (int n = 0; n < 8; n++) {
                const int scol = ((s0 + qt*64 + n*8) >> 1) + la;
                g_vf[(size_t)(c0 + lg    )*(S_TOT/2) + scol] = f16pack(c[n][0], c[n][1]);
                g_vf[(size_t)(c0 + lg + 8)*(S_TOT/2) + scol] = f16pack(c[n][2], c[n][3]);
            }
        }
    }
}

/* ------------------------------------------------------------------ */
/* Phase 2: attention (compute unchanged); O written as fp16.          */
/* ------------------------------------------------------------------ */
#define ATV_OFF 65536
#define AT_SMEM (65536 + 34816)

__global__ void __launch_bounds__(256, 2) attn_kernel()
{
    extern __shared__ char smc[];
    uint4*    Ksm = (uint4*)smc;                  /* [8][128][4] uint4  */
    uint2*    Fa  = (uint2*)smc;                  /* [8][128][4] uint2  */
    uint32_t* Vp  = (uint32_t*)(smc + ATV_OFF);   /* [64][136] fp16x2   */

    const int tid  = threadIdx.x;
    const int lane = tid & 31;
    const int wrp  = tid >> 5;
    const int lg   = lane >> 2;
    const int la   = lane & 3;
    const size_t base = (size_t)blockIdx.x * SLAB;

    const uint4* Kg4 = g_k4 + (size_t)blockIdx.x * 4096;
    for (int i = tid; i < 4096; i += 256)
        Ksm[i] = Kg4[i];
    const uint4* Vf4 = (const uint4*)g_vf + (size_t)blockIdx.x * 2048;
    for (int i = tid; i < 1024; i += 256) {
        int kp = i >> 4, u = i & 15;
        uint4 e = Vf4[(2*kp  )*16 + u];
        uint4 o = Vf4[(2*kp+1)*16 + u];
        uint4 w0, w1;
        w0.x = __byte_perm(e.x, o.x, 0x5410);  w0.y = __byte_perm(e.x, o.x, 0x7632);
        w0.z = __byte_perm(e.y, o.y, 0x5410);  w0.w = __byte_perm(e.y, o.y, 0x7632);
        w1.x = __byte_perm(e.z, o.z, 0x5410);  w1.y = __byte_perm(e.z, o.z, 0x7632);
        w1.z = __byte_perm(e.w, o.w, 0x5410);  w1.w = __byte_perm(e.w, o.w, 0x7632);
        *(uint4*)&Vp[kp*136 + u*8    ] = w0;
        *(uint4*)&Vp[kp*136 + u*8 + 4] = w1;
    }
    __syncthreads();

    const int r0 = wrp * 16;
    const int ra = r0 + lg, rb = ra + 8;

    /* ================= S = Q K^T ====================================== */
    float s[16][4];
    #pragma unroll
    for (int n = 0; n < 16; n++) {
        s[n][0] = 0.f; s[n][1] = 0.f; s[n][2] = 0.f; s[n][3] = 0.f;
    }

    const uint4* Qg4 = g_q4 + (size_t)blockIdx.x * 4096 + (size_t)(r0 + lg)*4 + la;
    uint4 qa[2][2];
    qa[0][0] = Qg4[0];
    qa[0][1] = Qg4[32];

    #pragma unroll 1
    for (int kt = 0; kt < 8; kt++) {
        const int cur = kt & 1;
        if (kt < 7) {
            qa[cur^1][0] = Qg4[(kt+1)*512];
            qa[cur^1][1] = Qg4[(kt+1)*512 + 32];
        }
        const uint32_t ah0 = qa[cur][0].x, al0 = qa[cur][0].y;
        const uint32_t ah2 = qa[cur][0].z, al2 = qa[cur][0].w;
        const uint32_t ah1 = qa[cur][1].x, al1 = qa[cur][1].y;
        const uint32_t ah3 = qa[cur][1].z, al3 = qa[cur][1].w;

        const uint4* kb = &Ksm[kt*512 + lg*4 + la];
        #pragma unroll
        for (int n = 0; n < 16; n++) {
            uint4 Bf = kb[n*32];
            mma_bf16(s[n], ah0, ah1, ah2, ah3, Bf.x, Bf.z);
            mma_bf16(s[n], ah0, ah1, ah2, ah3, Bf.y, Bf.w);
            mma_bf16(s[n], al0, al1, al2, al3, Bf.x, Bf.z);
        }
    }

    /* ================= row softmax ==================================== */
    float ia, ib;
    {
        float ma = -1e30f, mb = -1e30f;
        #pragma unroll
        for (int n = 0; n < 16; n++) {
            ma = fmaxf(ma, fmaxf(s[n][0], s[n][1]));
            mb = fmaxf(mb, fmaxf(s[n][2], s[n][3]));
        }
        ma = fmaxf(ma, __shfl_xor_sync(0xffffffffu, ma, 1));
        ma = fmaxf(ma, __shfl_xor_sync(0xffffffffu, ma, 2));
        mb = fmaxf(mb, __shfl_xor_sync(0xffffffffu, mb, 1));
        mb = fmaxf(mb, __shfl_xor_sync(0xffffffffu, mb, 2));

        float sa = 0.f, sb = 0.f;
        #pragma unroll
        for (int n = 0; n < 16; n++) {
            s[n][0] = __expf(s[n][0] - ma);  sa += s[n][0];
            s[n][1] = __expf(s[n][1] - ma);  sa += s[n][1];
            s[n][2] = __expf(s[n][2] - mb);  sb += s[n][2];
            s[n][3] = __expf(s[n][3] - mb);  sb += s[n][3];
        }
        sa += __shfl_xor_sync(0xffffffffu, sa, 1);
        sa += __shfl_xor_sync(0xffffffffu, sa, 2);
        sb += __shfl_xor_sync(0xffffffffu, sb, 1);
        sb += __shfl_xor_sync(0xffffffffu, sb, 2);
        ia = 1.0f / sa;  ib = 1.0f / sb;
    }

    __syncthreads();
    #pragma unroll
    for (int kt = 0; kt < 8; kt++) {
        Fa[kt*512 + ra*4 + la] =
            make_uint2(f16pack(s[2*kt  ][0]*ia, s[2*kt  ][1]*ia),
                       f16pack(s[2*kt+1][0]*ia, s[2*kt+1][1]*ia));
        Fa[kt*512 + rb*4 + la] =
            make_uint2(f16pack(s[2*kt  ][2]*ib, s[2*kt  ][3]*ib),
                       f16pack(s[2*kt+1][2]*ib, s[2*kt+1][3]*ib));
    }
    __syncwarp();

    /* ================= O = A V ======================================== */
    float o[16][4];
    #pragma unroll
    for (int n = 0; n < 16; n++) {
        o[n][0] = 0.f; o[n][1] = 0.f; o[n][2] = 0.f; o[n][3] = 0.f;
    }

    #pragma unroll 1
    for (int kt = 0; kt < 8; kt++) {
        uint2 u2a = Fa[kt*512 + (r0 + lg    )*4 + la];
        uint2 u2b = Fa[kt*512 + (r0 + lg + 8)*4 + la];
        const uint32_t a0 = u2a.x, a2 = u2a.y;
        const uint32_t a1 = u2b.x, a3 = u2b.y;

        const int w0v = (kt*8 + la) * 136;
        #pragma unroll
        for (int n = 0; n < 16; n++) {
            uint32_t b0 = Vp[w0v + n*8 + lg];
            uint32_t b1 = Vp[w0v + 4*136 + n*8 + lg];
            mma_f16(o[n], a0, a1, a2, a3, b0, b1);
        }
    }

    /* ---- O direct to global as fp16 (u32 = 2 cols) ---- */
    #pragma unroll
    for (int n = 0; n < 16; n++) {
        *(uint32_t*)&g_of[base + (size_t)ra*128 + n*8 + 2*la] = f16pack(o[n][0], o[n][1]);
        *(uint32_t*)&g_of[base + (size_t)rb*128 + n*8 + 2*la] = f16pack(o[n][2], o[n][3]);
    }
}

/* ------------------------------------------------------------------ */
/* Phase 3: output projection, 2-MMA fp16 (W 2-term split, o fp16).    */
/* B staged as channel-pair packed fp16x2 via byte_perm (mirrors AV).  */
/* ------------------------------------------------------------------ */
#define OPP 264                            /* u32 pitch, 264%32=8 -> cf */
#define P3_SMEM (32 * OPP * 4)             /* 33792 B                   */

__global__ void __launch_bounds__(256, 2) proj_o_kernel(
    float* __restrict__ out,
    const float* __restrict__ wo, const float* __restrict__ bo)
{
    extern __shared__ uint32_t op[];       /* [32][264] fp16x2 ch-pairs */

    const int tid  = threadIdx.x;
    const int lane = tid & 31;
    const int wrp  = tid >> 5;
    const int lg   = lane >> 2;
    const int la   = lane & 3;
    const int s0   = blockIdx.x * 256;

    const int c0 = (wrp & 3) * 16;
    const int hf = wrp >> 2;

    uint32_t ah[16], al[16];
    #pragma unroll
    for (int kt = 0; kt < 4; kt++) {
        int kk = kt*16 + 2*la;
        float2 w0 = *(const float2*)&wo[(c0 + lg    )*64 + kk    ];
        float2 w1 = *(const float2*)&wo[(c0 + lg + 8)*64 + kk    ];
        float2 w2 = *(const float2*)&wo[(c0 + lg    )*64 + kk + 8];
        float2 w3 = *(const float2*)&wo[(c0 + lg + 8)*64 + kk + 8];
        f16_split2(w0.x, w0.y, ah[kt*4+0], al[kt*4+0]);
        f16_split2(w1.x, w1.y, ah[kt*4+1], al[kt*4+1]);
        f16_split2(w2.x, w2.y, ah[kt*4+2], al[kt*4+2]);
        f16_split2(w3.x, w3.y, ah[kt*4+3], al[kt*4+3]);
    }
    const float b1 = bo[c0 + lg];
    const float b2 = bo[c0 + lg + 8];

    /* ---- stage o: channel-pair packing via byte_perm (ALL 256 cols) ---- */
    for (int i = tid; i < 1024; i += 256) {
        int kp = i >> 5, u = i & 31;          /* kp 0..31, cols u*8..u*8+7 */
        uint4 e = *(const uint4*)&g_of[(size_t)(2*kp  )*S_TOT + s0 + u*8];
        uint4 o = *(const uint4*)&g_of[(size_t)(2*kp+1)*S_TOT + s0 + u*8];
        uint4 w0, w1;
        w0.x = __byte_perm(e.x, o.x, 0x5410);  w0.y = __byte_perm(e.x, o.x, 0x7632);
        w0.z = __byte_perm(e.y, o.y, 0x5410);  w0.w = __byte_perm(e.y, o.y, 0x7632);
        w1.x = __byte_perm(e.z, o.z, 0x5410);  w1.y = __byte_perm(e.z, o.z, 0x7632);
        w1.z = __byte_perm(e.w, o.w, 0x5410);  w1.w = __byte_perm(e.w, o.w, 0x7632);
        *(uint4*)&op[kp*OPP + u*8    ] = w0;
        *(uint4*)&op[kp*OPP + u*8 + 4] = w1;
    }
    __syncthreads();

    #pragma unroll 1
    for (int qq = 0; qq < 2; qq++) {
        float c[8][4];
        #pragma unroll
        for (int n = 0; n < 8; n++) {
            c[n][0] = b1; c[n][1] = b1; c[n][2] = b2; c[n][3] = b2;
        }

        #pragma unroll 1
        for (int kt = 0; kt < 4; kt++) {
            const int w0i = (kt*8 + la)*OPP + hf*128 + qq*64 + lg;
            #pragma unroll
            for (int n = 0; n < 8; n++) {
                uint32_t B0 = op[w0i + n*8];
                uint32_t B1 = op[w0i + 4*OPP + n*8];
                mma_f16(c[n], ah[kt*4+0], ah[kt*4+1], ah[kt*4+2], ah[kt*4+3], B0, B1);
                mma_f16(c[n], al[kt*4+0], al[kt*4+1], al[kt*4+2], al[kt*4+3], B0, B1);
            }
        }

        #pragma unroll
        for (int n = 0; n < 8; n++) {
            size_t col = (size_t)(s0 + hf*128 + qq*64 + n*8 + 2*la);
            *(float2*)&out[(size_t)(c0 + lg    )*S_TOT + col] = make_float2(c[n][0], c[n][1]);
            *(float2*)&out[(size_t)(c0 + lg + 8)*S_TOT + col] = make_float2(c[n][2], c[n][3]);
        }
    }
}

/* ------------------------------------------------------------------ */
extern "C" void kernel_launch(void* const* d_in, const int* in_sizes, int n_in,
                              void* d_out, int out_size)
{
    const float* x  = (const float*)d_in[0];
    const float* wq = (const float*)d_in[1];
    const float* bq = (const float*)d_in[2];
    const float* wk = (const float*)d_in[3];
    const float* bk = (const float*)d_in[4];
    const float* wv = (const float*)d_in[5];
    const float* bv = (const float*)d_in[6];
    const float* wo = (const float*)d_in[7];
    const float* bo = (const float*)d_in[8];

    cudaFuncSetAttribute(qkv_kernel,    cudaFuncAttributeMaxDynamicSharedMemorySize, P1_SMEM);
    cudaFuncSetAttribute(attn_kernel,   cudaFuncAttributeMaxDynamicSharedMemorySize, AT_SMEM);
    cudaFuncSetAttribute(proj_o_kernel, cudaFuncAttributeMaxDynamicSharedMemorySize, P3_SMEM);

    qkv_kernel<<<S_TOT/256, 384, P1_SMEM>>>(x, wq, bq, wk, bk, wv, bv);
    attn_kernel<<<NSLAB, 256, AT_SMEM>>>();
    proj_o_kernel<<<S_TOT/256, 256, P3_SMEM>>>((float*)d_out, wo, bo);
}